// round 2
// baseline (speedup 1.0000x reference)
#include <cuda_runtime.h>
#include <math.h>

// Problem constants
#define B_    4
#define S_    2048
#define D_    768
#define H_    12
#define DK_   64
#define F_    3072
#define M_    (B_*S_)        // 8192 rows
#define NQKV_ (3*D_)         // 2304

// ---------------- scratch (static device globals; no allocation) ----------------
__device__ float g_wqkv[D_*NQKV_];          // packed QKV weights [D, 3*H*DK]
__device__ float g_bqkv[NQKV_];             // packed QKV bias
__device__ float g_qkv [M_*NQKV_];          // [B*S, 2304]  (q | k | v, each h-major)
__device__ float g_attn[M_*D_];             // concat heads [B*S, H*DK]
__device__ float g_mha [M_*D_];
__device__ float g_x1  [M_*D_];
__device__ float g_ffn1[M_*F_];
__device__ float g_ffn2[M_*D_];

// ---------------- pack QKV weights: [H,D,DK]x3 -> [D, 3*H*DK] ----------------
__global__ void pack_qkv(const float* __restrict__ Wq, const float* __restrict__ Wk,
                         const float* __restrict__ Wv, const float* __restrict__ bq,
                         const float* __restrict__ bk, const float* __restrict__ bv)
{
    int idx = blockIdx.x * blockDim.x + threadIdx.x;
    if (idx < D_ * NQKV_) {
        int d  = idx / NQKV_;
        int j  = idx % NQKV_;
        int wh = j / D_;          // 0=q,1=k,2=v
        int jj = j % D_;          // h*DK + kk
        int h  = jj / DK_;
        int kk = jj % DK_;
        const float* W = (wh == 0) ? Wq : (wh == 1) ? Wk : Wv;
        g_wqkv[idx] = W[(h * D_ + d) * DK_ + kk];
    }
    if (idx < NQKV_) {
        int wh = idx / D_, jj = idx % D_;
        const float* bsrc = (wh == 0) ? bq : (wh == 1) ? bk : bv;
        g_bqkv[idx] = bsrc[jj];
    }
}

// ---------------- SGEMM: C[M,N] = A[M,K] @ B[K,N] + bias, optional ReLU ----------------
// 128x128 block tile, BK=8, 256 threads, 8x8 per-thread register tile.
template<int RELU>
__global__ __launch_bounds__(256) void sgemm_bias(
    const float* __restrict__ A, const float* __restrict__ Bm,
    const float* __restrict__ bias, float* __restrict__ C,
    int M, int N, int K)
{
    __shared__ float As[8][128];
    __shared__ float Bs[8][128];

    const int t  = threadIdx.x;
    const int tx = t & 15;
    const int ty = t >> 4;
    const int rowC = blockIdx.y * 128;
    const int colC = blockIdx.x * 128;

    const int laR = t >> 1;          // 0..127
    const int laC = (t & 1) * 4;     // 0 or 4
    const int lbR = t >> 5;          // 0..7
    const int lbC = (t & 31) * 4;    // 0..124

    const float* Ap = A  + (size_t)(rowC + laR) * K + laC;
    const float* Bp = Bm + (size_t)lbR * N + colC + lbC;

    float acc[8][8];
#pragma unroll
    for (int i = 0; i < 8; i++)
#pragma unroll
        for (int j = 0; j < 8; j++) acc[i][j] = 0.f;

    for (int kt = 0; kt < K; kt += 8) {
        float4 a4 = *(const float4*)Ap; Ap += 8;
        float4 b4 = *(const float4*)Bp; Bp += (size_t)8 * N;
        As[laC + 0][laR] = a4.x;
        As[laC + 1][laR] = a4.y;
        As[laC + 2][laR] = a4.z;
        As[laC + 3][laR] = a4.w;
        *(float4*)&Bs[lbR][lbC] = b4;
        __syncthreads();

#pragma unroll
        for (int kk = 0; kk < 8; kk++) {
            float a[8], b[8];
            *(float4*)&a[0] = *(const float4*)&As[kk][ty * 8];
            *(float4*)&a[4] = *(const float4*)&As[kk][ty * 8 + 4];
            *(float4*)&b[0] = *(const float4*)&Bs[kk][tx * 8];
            *(float4*)&b[4] = *(const float4*)&Bs[kk][tx * 8 + 4];
#pragma unroll
            for (int i = 0; i < 8; i++)
#pragma unroll
                for (int j = 0; j < 8; j++)
                    acc[i][j] = fmaf(a[i], b[j], acc[i][j]);
        }
        __syncthreads();
    }

#pragma unroll
    for (int i = 0; i < 8; i++) {
        float* cp = C + (size_t)(rowC + ty * 8 + i) * N + colC + tx * 8;
        const float* bp = bias + colC + tx * 8;
        float4 o0, o1;
        o0.x = acc[i][0] + bp[0]; o0.y = acc[i][1] + bp[1];
        o0.z = acc[i][2] + bp[2]; o0.w = acc[i][3] + bp[3];
        o1.x = acc[i][4] + bp[4]; o1.y = acc[i][5] + bp[5];
        o1.z = acc[i][6] + bp[6]; o1.w = acc[i][7] + bp[7];
        if (RELU) {
            o0.x = fmaxf(o0.x, 0.f); o0.y = fmaxf(o0.y, 0.f);
            o0.z = fmaxf(o0.z, 0.f); o0.w = fmaxf(o0.w, 0.f);
            o1.x = fmaxf(o1.x, 0.f); o1.y = fmaxf(o1.y, 0.f);
            o1.z = fmaxf(o1.z, 0.f); o1.w = fmaxf(o1.w, 0.f);
        }
        *(float4*)cp       = o0;
        *(float4*)(cp + 4) = o1;
    }
}

// ---------------- fused flash attention (fp32, online softmax) ----------------
// grid (S/64, H, B); 256 threads; each CTA: 64 q-rows x full S keys.
// Thread (ty,tx): rows ty*4..+3, dk cols tx*4..+3 -> 4x4 output acc in regs.
#define KLD 68   // padded K row stride (2-way conflict instead of 16-way)

__global__ __launch_bounds__(256) void attn_kernel(
    const float* __restrict__ qkv, float* __restrict__ out)
{
    extern __shared__ float sm[];
    float* Qs = sm;                  // 64*64
    float* Ks = Qs + 64 * 64;        // 64*KLD
    float* Vs = Ks + 64 * KLD;       // 64*64
    float* Ps = Vs + 64 * 64;        // 64*64

    const int t  = threadIdx.x;
    const int tx = t & 15;
    const int ty = t >> 4;
    const int qb = blockIdx.x, h = blockIdx.y, b = blockIdx.z;

    const float* base = qkv + (size_t)b * S_ * NQKV_ + h * DK_;

    // load Q tile, pre-scaled by 1/sqrt(DK)
#pragma unroll
    for (int p = 0; p < 4; p++) {
        int idx = p * 256 + t;
        int r = idx >> 4, c = (idx & 15) * 4;
        float4 v = *(const float4*)(base + (size_t)(qb * 64 + r) * NQKV_ + c);
        v.x *= 0.125f; v.y *= 0.125f; v.z *= 0.125f; v.w *= 0.125f;
        *(float4*)&Qs[r * 64 + c] = v;
    }

    float m[4], l[4], acc[4][4];
#pragma unroll
    for (int i = 0; i < 4; i++) {
        m[i] = -3.0e38f; l[i] = 0.f;
#pragma unroll
        for (int j = 0; j < 4; j++) acc[i][j] = 0.f;
    }

    for (int kb = 0; kb < S_ / 64; kb++) {
        // load K, V tiles
#pragma unroll
        for (int p = 0; p < 4; p++) {
            int idx = p * 256 + t;
            int r = idx >> 4, c = (idx & 15) * 4;
            const float* rp = base + (size_t)(kb * 64 + r) * NQKV_ + c;
            *(float4*)&Ks[r * KLD + c] = *(const float4*)(rp + D_);
            *(float4*)&Vs[r * 64  + c] = *(const float4*)(rp + 2 * D_);
        }
        __syncthreads();

        // scores s = Q @ K^T (Q pre-scaled)
        float s[4][4];
#pragma unroll
        for (int i = 0; i < 4; i++)
#pragma unroll
            for (int j = 0; j < 4; j++) s[i][j] = 0.f;

#pragma unroll
        for (int d = 0; d < 64; d += 4) {
            float4 qv[4], kv[4];
#pragma unroll
            for (int i = 0; i < 4; i++) qv[i] = *(const float4*)&Qs[(ty * 4 + i) * 64 + d];
#pragma unroll
            for (int j = 0; j < 4; j++) kv[j] = *(const float4*)&Ks[(tx * 4 + j) * KLD + d];
#pragma unroll
            for (int i = 0; i < 4; i++)
#pragma unroll
                for (int j = 0; j < 4; j++) {
                    s[i][j] = fmaf(qv[i].x, kv[j].x, s[i][j]);
                    s[i][j] = fmaf(qv[i].y, kv[j].y, s[i][j]);
                    s[i][j] = fmaf(qv[i].z, kv[j].z, s[i][j]);
                    s[i][j] = fmaf(qv[i].w, kv[j].w, s[i][j]);
                }
        }

        // online softmax update (per-row stats shared across the 16 tx lanes via shuffles)
#pragma unroll
        for (int i = 0; i < 4; i++) {
            float mx = fmaxf(fmaxf(s[i][0], s[i][1]), fmaxf(s[i][2], s[i][3]));
#pragma unroll
            for (int mk = 8; mk; mk >>= 1)
                mx = fmaxf(mx, __shfl_xor_sync(0xffffffffu, mx, mk));
            float mnew = fmaxf(m[i], mx);
            float fac  = __expf(m[i] - mnew);
            m[i] = mnew;
            float p0 = __expf(s[i][0] - mnew);
            float p1 = __expf(s[i][1] - mnew);
            float p2 = __expf(s[i][2] - mnew);
            float p3 = __expf(s[i][3] - mnew);
            float ls = p0 + p1 + p2 + p3;
#pragma unroll
            for (int mk = 8; mk; mk >>= 1)
                ls += __shfl_xor_sync(0xffffffffu, ls, mk);
            l[i] = l[i] * fac + ls;
            acc[i][0] *= fac; acc[i][1] *= fac; acc[i][2] *= fac; acc[i][3] *= fac;
            float4 pw = make_float4(p0, p1, p2, p3);
            *(float4*)&Ps[(ty * 4 + i) * 64 + tx * 4] = pw;
        }
        __syncthreads();

        // acc += P @ V
#pragma unroll
        for (int tt = 0; tt < 64; tt += 4) {
            float4 pv[4];
#pragma unroll
            for (int i = 0; i < 4; i++) pv[i] = *(const float4*)&Ps[(ty * 4 + i) * 64 + tt];
            float4 v0 = *(const float4*)&Vs[(tt + 0) * 64 + tx * 4];
            float4 v1 = *(const float4*)&Vs[(tt + 1) * 64 + tx * 4];
            float4 v2 = *(const float4*)&Vs[(tt + 2) * 64 + tx * 4];
            float4 v3 = *(const float4*)&Vs[(tt + 3) * 64 + tx * 4];
#pragma unroll
            for (int i = 0; i < 4; i++) {
                acc[i][0] = fmaf(pv[i].x, v0.x, acc[i][0]);
                acc[i][0] = fmaf(pv[i].y, v1.x, acc[i][0]);
                acc[i][0] = fmaf(pv[i].z, v2.x, acc[i][0]);
                acc[i][0] = fmaf(pv[i].w, v3.x, acc[i][0]);
                acc[i][1] = fmaf(pv[i].x, v0.y, acc[i][1]);
                acc[i][1] = fmaf(pv[i].y, v1.y, acc[i][1]);
                acc[i][1] = fmaf(pv[i].z, v2.y, acc[i][1]);
                acc[i][1] = fmaf(pv[i].w, v3.y, acc[i][1]);
                acc[i][2] = fmaf(pv[i].x, v0.z, acc[i][2]);
                acc[i][2] = fmaf(pv[i].y, v1.z, acc[i][2]);
                acc[i][2] = fmaf(pv[i].z, v2.z, acc[i][2]);
                acc[i][2] = fmaf(pv[i].w, v3.z, acc[i][2]);
                acc[i][3] = fmaf(pv[i].x, v0.w, acc[i][3]);
                acc[i][3] = fmaf(pv[i].y, v1.w, acc[i][3]);
                acc[i][3] = fmaf(pv[i].z, v2.w, acc[i][3]);
                acc[i][3] = fmaf(pv[i].w, v3.w, acc[i][3]);
            }
        }
        __syncthreads();
    }

    // write concat-head output [B*S, H*DK]
#pragma unroll
    for (int i = 0; i < 4; i++) {
        float inv = 1.0f / l[i];
        int r = qb * 64 + ty * 4 + i;
        float4 o = make_float4(acc[i][0] * inv, acc[i][1] * inv,
                               acc[i][2] * inv, acc[i][3] * inv);
        *(float4*)(out + (size_t)(b * S_ + r) * D_ + h * DK_ + tx * 4) = o;
    }
}

// ---------------- fused residual-add + LayerNorm ----------------
// one CTA (256 threads) per row of 768
__global__ __launch_bounds__(256) void add_ln_kernel(
    const float* __restrict__ A, const float* __restrict__ Bv,
    const float* __restrict__ gamma, const float* __restrict__ beta,
    float* __restrict__ out)
{
    const int row = blockIdx.x;
    const int t   = threadIdx.x;
    __shared__ float wr[8];
    __shared__ float sMean, sRstd;

    const float* pa = A  + (size_t)row * D_;
    const float* pb = Bv + (size_t)row * D_;

    float v0 = pa[t]       + pb[t];
    float v1 = pa[t + 256] + pb[t + 256];
    float v2 = pa[t + 512] + pb[t + 512];

    float s = v0 + v1 + v2;
#pragma unroll
    for (int mk = 16; mk; mk >>= 1) s += __shfl_xor_sync(0xffffffffu, s, mk);
    if ((t & 31) == 0) wr[t >> 5] = s;
    __syncthreads();
    if (t == 0) {
        float tot = 0;
        for (int i = 0; i < 8; i++) tot += wr[i];
        sMean = tot * (1.0f / D_);
    }
    __syncthreads();
    float mean = sMean;
    float d0 = v0 - mean, d1 = v1 - mean, d2 = v2 - mean;
    float q = d0 * d0 + d1 * d1 + d2 * d2;
#pragma unroll
    for (int mk = 16; mk; mk >>= 1) q += __shfl_xor_sync(0xffffffffu, q, mk);
    if ((t & 31) == 0) wr[t >> 5] = q;
    __syncthreads();
    if (t == 0) {
        float tot = 0;
        for (int i = 0; i < 8; i++) tot += wr[i];
        sRstd = rsqrtf(tot * (1.0f / D_) + 1e-5f);
    }
    __syncthreads();
    float rstd = sRstd;

    float* po = out + (size_t)row * D_;
    po[t]       = d0 * rstd * gamma[t]       + beta[t];
    po[t + 256] = d1 * rstd * gamma[t + 256] + beta[t + 256];
    po[t + 512] = d2 * rstd * gamma[t + 512] + beta[t + 512];
}

// ---------------- launch ----------------
extern "C" void kernel_launch(void* const* d_in, const int* in_sizes, int n_in,
                              void* d_out, int out_size)
{
    const float* src = (const float*)d_in[0];
    const float* Wq  = (const float*)d_in[1];
    const float* bq  = (const float*)d_in[2];
    const float* Wk  = (const float*)d_in[3];
    const float* bk  = (const float*)d_in[4];
    const float* Wv  = (const float*)d_in[5];
    const float* bv  = (const float*)d_in[6];
    const float* Wo  = (const float*)d_in[7];
    const float* bo  = (const float*)d_in[8];
    const float* g1  = (const float*)d_in[9];
    const float* be1 = (const float*)d_in[10];
    const float* W1  = (const float*)d_in[11];
    const float* bf1 = (const float*)d_in[12];
    const float* W2  = (const float*)d_in[13];
    const float* bf2 = (const float*)d_in[14];
    const float* g2  = (const float*)d_in[15];
    const float* be2 = (const float*)d_in[16];
    float* out = (float*)d_out;

    float *wqkv, *bqkv, *qkv, *attn, *mha, *x1, *ffn1, *ffn2;
    cudaGetSymbolAddress((void**)&wqkv, g_wqkv);
    cudaGetSymbolAddress((void**)&bqkv, g_bqkv);
    cudaGetSymbolAddress((void**)&qkv,  g_qkv);
    cudaGetSymbolAddress((void**)&attn, g_attn);
    cudaGetSymbolAddress((void**)&mha,  g_mha);
    cudaGetSymbolAddress((void**)&x1,   g_x1);
    cudaGetSymbolAddress((void**)&ffn1, g_ffn1);
    cudaGetSymbolAddress((void**)&ffn2, g_ffn2);

    const int attn_smem = (64 * 64 * 3 + 64 * KLD) * (int)sizeof(float);  // 66560 B
    cudaFuncSetAttribute(attn_kernel, cudaFuncAttributeMaxDynamicSharedMemorySize, attn_smem);

    // 1) pack QKV weights+bias
    pack_qkv<<<(D_ * NQKV_ + 255) / 256, 256>>>(Wq, Wk, Wv, bq, bk, bv);

    // 2) QKV projection: [8192,768] @ [768,2304]
    sgemm_bias<0><<<dim3(NQKV_ / 128, M_ / 128), 256>>>(src, wqkv, bqkv, qkv, M_, NQKV_, D_);

    // 3) fused attention
    attn_kernel<<<dim3(S_ / 64, H_, B_), 256, attn_smem>>>(qkv, attn);

    // 4) output projection
    sgemm_bias<0><<<dim3(D_ / 128, M_ / 128), 256>>>(attn, Wo, bo, mha, M_, D_, D_);

    // 5) x1 = LN(src + mha)
    add_ln_kernel<<<M_, 256>>>(src, mha, g1, be1, x1);

    // 6) FFN1 (+ReLU): [8192,768] @ [768,3072]
    sgemm_bias<1><<<dim3(F_ / 128, M_ / 128), 256>>>(x1, W1, bf1, ffn1, M_, F_, D_);

    // 7) FFN2: [8192,3072] @ [3072,768]
    sgemm_bias<0><<<dim3(D_ / 128, M_ / 128), 256>>>(ffn1, W2, bf2, ffn2, M_, D_, F_);

    // 8) out = LN(x1 + ffn2)
    add_ln_kernel<<<M_, 256>>>(x1, ffn2, g2, be2, out);
}

// round 3
// speedup vs baseline: 1.3147x; 1.3147x over previous
#include <cuda_runtime.h>
#include <math.h>
#include <stdint.h>

// Problem constants
#define B_    4
#define S_    2048
#define D_    768
#define H_    12
#define DK_   64
#define F_    3072
#define M_    (B_*S_)        // 8192 rows
#define NQKV_ (3*D_)         // 2304

// ---------------- scratch (static device globals; no allocation) ----------------
__device__ float g_wqkv[D_*NQKV_];          // packed QKV weights [D, 3*H*DK]
__device__ float g_bqkv[NQKV_];             // packed QKV bias
__device__ float g_qkv [M_*NQKV_];          // [B*S, 2304]  (q | k | v, each h-major)
__device__ float g_attn[M_*D_];             // concat heads [B*S, H*DK]
__device__ float g_mha [M_*D_];
__device__ float g_x1  [M_*D_];
__device__ float g_ffn1[M_*F_];
__device__ float g_ffn2[M_*D_];

// ---------------- pack QKV weights: [H,D,DK]x3 -> [D, 3*H*DK] ----------------
__global__ void pack_qkv(const float* __restrict__ Wq, const float* __restrict__ Wk,
                         const float* __restrict__ Wv, const float* __restrict__ bq,
                         const float* __restrict__ bk, const float* __restrict__ bv)
{
    int idx = blockIdx.x * blockDim.x + threadIdx.x;
    if (idx < D_ * NQKV_) {
        int d  = idx / NQKV_;
        int j  = idx % NQKV_;
        int wh = j / D_;          // 0=q,1=k,2=v
        int jj = j % D_;          // h*DK + kk
        int h  = jj / DK_;
        int kk = jj % DK_;
        const float* W = (wh == 0) ? Wq : (wh == 1) ? Wk : Wv;
        g_wqkv[idx] = W[(h * D_ + d) * DK_ + kk];
    }
    if (idx < NQKV_) {
        int wh = idx / D_, jj = idx % D_;
        const float* bsrc = (wh == 0) ? bq : (wh == 1) ? bk : bv;
        g_bqkv[idx] = bsrc[jj];
    }
}

// ---------------- TF32 tensor-core GEMM ----------------
// C[M,N] = A[M,K] @ B[K,N] + bias, optional ReLU.
// CTA tile 128x128, BK=32, 256 threads (8 warps), warp tile 64x32,
// mma.sync.aligned.m16n8k8.row.col.f32.tf32.tf32.f32, double-buffered smem.
// A: LDG.128 -> register -> STS.32 transposed to col-major smem [k][m] (stride 132).
// B: cp.async 16B, row-major smem [k][n] (stride 132).

#define SLD 132                    // padded smem leading dim (floats)
#define SBUF (32 * SLD)            // one buffer of one operand

__device__ __forceinline__ uint32_t f2tf32(float x) {
    uint32_t r;
    asm volatile("cvt.rna.tf32.f32 %0, %1;" : "=r"(r) : "f"(x));
    return r;
}

__device__ __forceinline__ void mma_tf32(float* d, const uint32_t* a, const uint32_t* b) {
    asm volatile(
        "mma.sync.aligned.m16n8k8.row.col.f32.tf32.tf32.f32 "
        "{%0,%1,%2,%3}, {%4,%5,%6,%7}, {%8,%9}, {%0,%1,%2,%3};"
        : "+f"(d[0]), "+f"(d[1]), "+f"(d[2]), "+f"(d[3])
        : "r"(a[0]), "r"(a[1]), "r"(a[2]), "r"(a[3]), "r"(b[0]), "r"(b[1]));
}

__device__ __forceinline__ void cp_async16(void* smem_dst, const void* gmem_src) {
    uint32_t sa = (uint32_t)__cvta_generic_to_shared(smem_dst);
    asm volatile("cp.async.cg.shared.global [%0], [%1], 16;" :: "r"(sa), "l"(gmem_src));
}

template<int RELU>
__global__ __launch_bounds__(256, 2) void gemm_tf32(
    const float* __restrict__ A, const float* __restrict__ Bm,
    const float* __restrict__ bias, float* __restrict__ C,
    int M, int N, int K)
{
    extern __shared__ float sm[];
    float* As = sm;               // [2][32][SLD] col-major (k, m)
    float* Bs = sm + 2 * SBUF;    // [2][32][SLD] row-major (k, n)

    const int t    = threadIdx.x;
    const int wid  = t >> 5;
    const int lane = t & 31;
    const int g    = lane >> 2;   // group 0..7
    const int q    = lane & 3;    // 0..3
    const int wm   = wid & 1;     // warp row (64 rows)
    const int wn   = wid >> 1;    // warp col (32 cols)
    const int rowC = blockIdx.y * 128;
    const int colC = blockIdx.x * 128;

    // A loader mapping: thread t handles row m_loc, k-halves kh..kh+15
    const int m_loc = t & 127;
    const int kh    = (t >> 7) * 16;
    // B loader mapping: thread t handles k-row kB, 16 cols n4..n4+15
    const int kB    = t >> 3;
    const int n4    = (t & 7) * 16;

    const float* Aptr = A  + (size_t)(rowC + m_loc) * K + kh;
    const float* Bptr = Bm + (size_t)kB * N + colC + n4;

    float acc[4][4][4];
#pragma unroll
    for (int i = 0; i < 4; i++)
#pragma unroll
        for (int j = 0; j < 4; j++)
#pragma unroll
            for (int r = 0; r < 4; r++) acc[i][j][r] = 0.f;

    const int ntiles = K / 32;

    // ---- prologue: tile 0 into buffer 0 ----
    {
        float4 ar[4];
#pragma unroll
        for (int j = 0; j < 4; j++)
            ar[j] = *(const float4*)(Aptr + 4 * j);
#pragma unroll
        for (int j = 0; j < 4; j++) {
            As[(kh + 4 * j + 0) * SLD + m_loc] = ar[j].x;
            As[(kh + 4 * j + 1) * SLD + m_loc] = ar[j].y;
            As[(kh + 4 * j + 2) * SLD + m_loc] = ar[j].z;
            As[(kh + 4 * j + 3) * SLD + m_loc] = ar[j].w;
        }
#pragma unroll
        for (int j = 0; j < 4; j++)
            cp_async16(&Bs[kB * SLD + n4 + 4 * j], Bptr + 4 * j);
        asm volatile("cp.async.commit_group;");
        asm volatile("cp.async.wait_group 0;");
        __syncthreads();
    }

    int buf = 0;
    for (int kt = 0; kt < ntiles; kt++) {
        const bool more = (kt + 1) < ntiles;
        float4 ar[4];
        if (more) {
            const float* ap = Aptr + (size_t)(kt + 1) * 32;
#pragma unroll
            for (int j = 0; j < 4; j++)
                ar[j] = *(const float4*)(ap + 4 * j);
            const float* bp = Bptr + (size_t)(kt + 1) * 32 * N;
            float* bd = Bs + (buf ^ 1) * SBUF + kB * SLD + n4;
#pragma unroll
            for (int j = 0; j < 4; j++)
                cp_async16(bd + 4 * j, bp + 4 * j);
            asm volatile("cp.async.commit_group;");
        }

        // ---- compute on current buffer ----
        const float* Ab = As + buf * SBUF;
        const float* Bb = Bs + buf * SBUF;
#pragma unroll
        for (int kk = 0; kk < 4; kk++) {
            const int k0 = kk * 8;
            uint32_t af[4][4], bf[4][2];
#pragma unroll
            for (int mt = 0; mt < 4; mt++) {
                const int r0 = wm * 64 + mt * 16 + g;
                af[mt][0] = f2tf32(Ab[(k0 + q    ) * SLD + r0    ]);
                af[mt][1] = f2tf32(Ab[(k0 + q    ) * SLD + r0 + 8]);
                af[mt][2] = f2tf32(Ab[(k0 + q + 4) * SLD + r0    ]);
                af[mt][3] = f2tf32(Ab[(k0 + q + 4) * SLD + r0 + 8]);
            }
#pragma unroll
            for (int nt = 0; nt < 4; nt++) {
                const int c0 = wn * 32 + nt * 8 + g;
                bf[nt][0] = f2tf32(Bb[(k0 + q    ) * SLD + c0]);
                bf[nt][1] = f2tf32(Bb[(k0 + q + 4) * SLD + c0]);
            }
#pragma unroll
            for (int mt = 0; mt < 4; mt++)
#pragma unroll
                for (int nt = 0; nt < 4; nt++)
                    mma_tf32(acc[mt][nt], af[mt], bf[nt]);
        }

        if (more) {
            float* Ad = As + (buf ^ 1) * SBUF;
#pragma unroll
            for (int j = 0; j < 4; j++) {
                Ad[(kh + 4 * j + 0) * SLD + m_loc] = ar[j].x;
                Ad[(kh + 4 * j + 1) * SLD + m_loc] = ar[j].y;
                Ad[(kh + 4 * j + 2) * SLD + m_loc] = ar[j].z;
                Ad[(kh + 4 * j + 3) * SLD + m_loc] = ar[j].w;
            }
            asm volatile("cp.async.wait_group 0;");
        }
        __syncthreads();
        buf ^= 1;
    }

    // ---- epilogue: bias (+ReLU), STG.64 ----
#pragma unroll
    for (int mt = 0; mt < 4; mt++) {
        const int r0 = rowC + wm * 64 + mt * 16 + g;
#pragma unroll
        for (int nt = 0; nt < 4; nt++) {
            const int c = colC + wn * 32 + nt * 8 + 2 * q;
            const float b0v = bias[c], b1v = bias[c + 1];
            float2 o0 = make_float2(acc[mt][nt][0] + b0v, acc[mt][nt][1] + b1v);
            float2 o1 = make_float2(acc[mt][nt][2] + b0v, acc[mt][nt][3] + b1v);
            if (RELU) {
                o0.x = fmaxf(o0.x, 0.f); o0.y = fmaxf(o0.y, 0.f);
                o1.x = fmaxf(o1.x, 0.f); o1.y = fmaxf(o1.y, 0.f);
            }
            *(float2*)(C + (size_t)r0 * N + c)       = o0;
            *(float2*)(C + (size_t)(r0 + 8) * N + c) = o1;
        }
    }
}

// ---------------- fused flash attention (fp32, online softmax) ----------------
#define KLD 68   // padded K row stride

__global__ __launch_bounds__(256) void attn_kernel(
    const float* __restrict__ qkv, float* __restrict__ out)
{
    extern __shared__ float smf[];
    float* Qs = smf;                 // 64*64
    float* Ks = Qs + 64 * 64;        // 64*KLD
    float* Vs = Ks + 64 * KLD;       // 64*64
    float* Ps = Vs + 64 * 64;        // 64*64

    const int t  = threadIdx.x;
    const int tx = t & 15;
    const int ty = t >> 4;
    const int qb = blockIdx.x, h = blockIdx.y, b = blockIdx.z;

    const float* base = qkv + (size_t)b * S_ * NQKV_ + h * DK_;

#pragma unroll
    for (int p = 0; p < 4; p++) {
        int idx = p * 256 + t;
        int r = idx >> 4, c = (idx & 15) * 4;
        float4 v = *(const float4*)(base + (size_t)(qb * 64 + r) * NQKV_ + c);
        v.x *= 0.125f; v.y *= 0.125f; v.z *= 0.125f; v.w *= 0.125f;
        *(float4*)&Qs[r * 64 + c] = v;
    }

    float m[4], l[4], acc[4][4];
#pragma unroll
    for (int i = 0; i < 4; i++) {
        m[i] = -3.0e38f; l[i] = 0.f;
#pragma unroll
        for (int j = 0; j < 4; j++) acc[i][j] = 0.f;
    }

    for (int kb = 0; kb < S_ / 64; kb++) {
#pragma unroll
        for (int p = 0; p < 4; p++) {
            int idx = p * 256 + t;
            int r = idx >> 4, c = (idx & 15) * 4;
            const float* rp = base + (size_t)(kb * 64 + r) * NQKV_ + c;
            *(float4*)&Ks[r * KLD + c] = *(const float4*)(rp + D_);
            *(float4*)&Vs[r * 64  + c] = *(const float4*)(rp + 2 * D_);
        }
        __syncthreads();

        float s[4][4];
#pragma unroll
        for (int i = 0; i < 4; i++)
#pragma unroll
            for (int j = 0; j < 4; j++) s[i][j] = 0.f;

#pragma unroll
        for (int d = 0; d < 64; d += 4) {
            float4 qv[4], kv[4];
#pragma unroll
            for (int i = 0; i < 4; i++) qv[i] = *(const float4*)&Qs[(ty * 4 + i) * 64 + d];
#pragma unroll
            for (int j = 0; j < 4; j++) kv[j] = *(const float4*)&Ks[(tx * 4 + j) * KLD + d];
#pragma unroll
            for (int i = 0; i < 4; i++)
#pragma unroll
                for (int j = 0; j < 4; j++) {
                    s[i][j] = fmaf(qv[i].x, kv[j].x, s[i][j]);
                    s[i][j] = fmaf(qv[i].y, kv[j].y, s[i][j]);
                    s[i][j] = fmaf(qv[i].z, kv[j].z, s[i][j]);
                    s[i][j] = fmaf(qv[i].w, kv[j].w, s[i][j]);
                }
        }

#pragma unroll
        for (int i = 0; i < 4; i++) {
            float mx = fmaxf(fmaxf(s[i][0], s[i][1]), fmaxf(s[i][2], s[i][3]));
#pragma unroll
            for (int mk = 8; mk; mk >>= 1)
                mx = fmaxf(mx, __shfl_xor_sync(0xffffffffu, mx, mk));
            float mnew = fmaxf(m[i], mx);
            float fac  = __expf(m[i] - mnew);
            m[i] = mnew;
            float p0 = __expf(s[i][0] - mnew);
            float p1 = __expf(s[i][1] - mnew);
            float p2 = __expf(s[i][2] - mnew);
            float p3 = __expf(s[i][3] - mnew);
            float ls = p0 + p1 + p2 + p3;
#pragma unroll
            for (int mk = 8; mk; mk >>= 1)
                ls += __shfl_xor_sync(0xffffffffu, ls, mk);
            l[i] = l[i] * fac + ls;
            acc[i][0] *= fac; acc[i][1] *= fac; acc[i][2] *= fac; acc[i][3] *= fac;
            float4 pw = make_float4(p0, p1, p2, p3);
            *(float4*)&Ps[(ty * 4 + i) * 64 + tx * 4] = pw;
        }
        __syncthreads();

#pragma unroll
        for (int tt = 0; tt < 64; tt += 4) {
            float4 pv[4];
#pragma unroll
            for (int i = 0; i < 4; i++) pv[i] = *(const float4*)&Ps[(ty * 4 + i) * 64 + tt];
            float4 v0 = *(const float4*)&Vs[(tt + 0) * 64 + tx * 4];
            float4 v1 = *(const float4*)&Vs[(tt + 1) * 64 + tx * 4];
            float4 v2 = *(const float4*)&Vs[(tt + 2) * 64 + tx * 4];
            float4 v3 = *(const float4*)&Vs[(tt + 3) * 64 + tx * 4];
#pragma unroll
            for (int i = 0; i < 4; i++) {
                acc[i][0] = fmaf(pv[i].x, v0.x, acc[i][0]);
                acc[i][0] = fmaf(pv[i].y, v1.x, acc[i][0]);
                acc[i][0] = fmaf(pv[i].z, v2.x, acc[i][0]);
                acc[i][0] = fmaf(pv[i].w, v3.x, acc[i][0]);
                acc[i][1] = fmaf(pv[i].x, v0.y, acc[i][1]);
                acc[i][1] = fmaf(pv[i].y, v1.y, acc[i][1]);
                acc[i][1] = fmaf(pv[i].z, v2.y, acc[i][1]);
                acc[i][1] = fmaf(pv[i].w, v3.y, acc[i][1]);
                acc[i][2] = fmaf(pv[i].x, v0.z, acc[i][2]);
                acc[i][2] = fmaf(pv[i].y, v1.z, acc[i][2]);
                acc[i][2] = fmaf(pv[i].z, v2.z, acc[i][2]);
                acc[i][2] = fmaf(pv[i].w, v3.z, acc[i][2]);
                acc[i][3] = fmaf(pv[i].x, v0.w, acc[i][3]);
                acc[i][3] = fmaf(pv[i].y, v1.w, acc[i][3]);
                acc[i][3] = fmaf(pv[i].z, v2.w, acc[i][3]);
                acc[i][3] = fmaf(pv[i].w, v3.w, acc[i][3]);
            }
        }
        __syncthreads();
    }

#pragma unroll
    for (int i = 0; i < 4; i++) {
        float inv = 1.0f / l[i];
        int r = qb * 64 + ty * 4 + i;
        float4 o = make_float4(acc[i][0] * inv, acc[i][1] * inv,
                               acc[i][2] * inv, acc[i][3] * inv);
        *(float4*)(out + (size_t)(b * S_ + r) * D_ + h * DK_ + tx * 4) = o;
    }
}

// ---------------- fused residual-add + LayerNorm ----------------
__global__ __launch_bounds__(256) void add_ln_kernel(
    const float* __restrict__ A, const float* __restrict__ Bv,
    const float* __restrict__ gamma, const float* __restrict__ beta,
    float* __restrict__ out)
{
    const int row = blockIdx.x;
    const int t   = threadIdx.x;
    __shared__ float wr[8];
    __shared__ float sMean, sRstd;

    const float* pa = A  + (size_t)row * D_;
    const float* pb = Bv + (size_t)row * D_;

    float v0 = pa[t]       + pb[t];
    float v1 = pa[t + 256] + pb[t + 256];
    float v2 = pa[t + 512] + pb[t + 512];

    float s = v0 + v1 + v2;
#pragma unroll
    for (int mk = 16; mk; mk >>= 1) s += __shfl_xor_sync(0xffffffffu, s, mk);
    if ((t & 31) == 0) wr[t >> 5] = s;
    __syncthreads();
    if (t == 0) {
        float tot = 0;
        for (int i = 0; i < 8; i++) tot += wr[i];
        sMean = tot * (1.0f / D_);
    }
    __syncthreads();
    float mean = sMean;
    float d0 = v0 - mean, d1 = v1 - mean, d2 = v2 - mean;
    float qv = d0 * d0 + d1 * d1 + d2 * d2;
#pragma unroll
    for (int mk = 16; mk; mk >>= 1) qv += __shfl_xor_sync(0xffffffffu, qv, mk);
    if ((t & 31) == 0) wr[t >> 5] = qv;
    __syncthreads();
    if (t == 0) {
        float tot = 0;
        for (int i = 0; i < 8; i++) tot += wr[i];
        sRstd = rsqrtf(tot * (1.0f / D_) + 1e-5f);
    }
    __syncthreads();
    float rstd = sRstd;

    float* po = out + (size_t)row * D_;
    po[t]       = d0 * rstd * gamma[t]       + beta[t];
    po[t + 256] = d1 * rstd * gamma[t + 256] + beta[t + 256];
    po[t + 512] = d2 * rstd * gamma[t + 512] + beta[t + 512];
}

// ---------------- launch ----------------
extern "C" void kernel_launch(void* const* d_in, const int* in_sizes, int n_in,
                              void* d_out, int out_size)
{
    const float* src = (const float*)d_in[0];
    const float* Wq  = (const float*)d_in[1];
    const float* bq  = (const float*)d_in[2];
    const float* Wk  = (const float*)d_in[3];
    const float* bk  = (const float*)d_in[4];
    const float* Wv  = (const float*)d_in[5];
    const float* bv  = (const float*)d_in[6];
    const float* Wo  = (const float*)d_in[7];
    const float* bo  = (const float*)d_in[8];
    const float* g1  = (const float*)d_in[9];
    const float* be1 = (const float*)d_in[10];
    const float* W1  = (const float*)d_in[11];
    const float* bf1 = (const float*)d_in[12];
    const float* W2  = (const float*)d_in[13];
    const float* bf2 = (const float*)d_in[14];
    const float* g2  = (const float*)d_in[15];
    const float* be2 = (const float*)d_in[16];
    float* out = (float*)d_out;

    float *wqkv, *bqkv, *qkv, *attn, *mha, *x1, *ffn1, *ffn2;
    cudaGetSymbolAddress((void**)&wqkv, g_wqkv);
    cudaGetSymbolAddress((void**)&bqkv, g_bqkv);
    cudaGetSymbolAddress((void**)&qkv,  g_qkv);
    cudaGetSymbolAddress((void**)&attn, g_attn);
    cudaGetSymbolAddress((void**)&mha,  g_mha);
    cudaGetSymbolAddress((void**)&x1,   g_x1);
    cudaGetSymbolAddress((void**)&ffn1, g_ffn1);
    cudaGetSymbolAddress((void**)&ffn2, g_ffn2);

    const int gemm_smem = 4 * SBUF * (int)sizeof(float);   // 67584 B
    cudaFuncSetAttribute(gemm_tf32<0>, cudaFuncAttributeMaxDynamicSharedMemorySize, gemm_smem);
    cudaFuncSetAttribute(gemm_tf32<1>, cudaFuncAttributeMaxDynamicSharedMemorySize, gemm_smem);

    const int attn_smem = (64 * 64 * 3 + 64 * KLD) * (int)sizeof(float);  // 66560 B
    cudaFuncSetAttribute(attn_kernel, cudaFuncAttributeMaxDynamicSharedMemorySize, attn_smem);

    // 1) pack QKV weights+bias
    pack_qkv<<<(D_ * NQKV_ + 255) / 256, 256>>>(Wq, Wk, Wv, bq, bk, bv);

    // 2) QKV projection: [8192,768] @ [768,2304]
    gemm_tf32<0><<<dim3(NQKV_ / 128, M_ / 128), 256, gemm_smem>>>(src, wqkv, bqkv, qkv, M_, NQKV_, D_);

    // 3) fused attention
    attn_kernel<<<dim3(S_ / 64, H_, B_), 256, attn_smem>>>(qkv, attn);

    // 4) output projection
    gemm_tf32<0><<<dim3(D_ / 128, M_ / 128), 256, gemm_smem>>>(attn, Wo, bo, mha, M_, D_, D_);

    // 5) x1 = LN(src + mha)
    add_ln_kernel<<<M_, 256>>>(src, mha, g1, be1, x1);

    // 6) FFN1 (+ReLU): [8192,768] @ [768,3072]
    gemm_tf32<1><<<dim3(F_ / 128, M_ / 128), 256, gemm_smem>>>(x1, W1, bf1, ffn1, M_, F_, D_);

    // 7) FFN2: [8192,3072] @ [3072,768]
    gemm_tf32<0><<<dim3(D_ / 128, M_ / 128), 256, gemm_smem>>>(ffn1, W2, bf2, ffn2, M_, D_, F_);

    // 8) out = LN(x1 + ffn2)
    add_ln_kernel<<<M_, 256>>>(x1, ffn2, g2, be2, out);
}

// round 4
// speedup vs baseline: 2.2437x; 1.7066x over previous
#include <cuda_runtime.h>
#include <math.h>
#include <stdint.h>

// Problem constants
#define B_    4
#define S_    2048
#define D_    768
#define H_    12
#define DK_   64
#define F_    3072
#define M_    (B_*S_)        // 8192 rows
#define NQKV_ (3*D_)         // 2304

// ---------------- scratch (static device globals; no allocation) ----------------
__device__ float g_wqkv[D_*NQKV_];          // packed QKV weights [D, 3*H*DK]
__device__ float g_bqkv[NQKV_];             // packed QKV bias
__device__ float g_qkv [M_*NQKV_];          // [B*S, 2304]  (q | k | v, each h-major)
__device__ float g_attn[M_*D_];             // concat heads [B*S, H*DK]
__device__ float g_mha [M_*D_];
__device__ float g_x1  [M_*D_];
__device__ float g_ffn1[M_*F_];
__device__ float g_ffn2[M_*D_];

// ---------------- helpers ----------------
__device__ __forceinline__ uint32_t f2tf32(float x) {
    uint32_t r;
    asm volatile("cvt.rna.tf32.f32 %0, %1;" : "=r"(r) : "f"(x));
    return r;
}

__device__ __forceinline__ void mma_tf32(float* d, const uint32_t* a, const uint32_t* b) {
    asm volatile(
        "mma.sync.aligned.m16n8k8.row.col.f32.tf32.tf32.f32 "
        "{%0,%1,%2,%3}, {%4,%5,%6,%7}, {%8,%9}, {%0,%1,%2,%3};"
        : "+f"(d[0]), "+f"(d[1]), "+f"(d[2]), "+f"(d[3])
        : "r"(a[0]), "r"(a[1]), "r"(a[2]), "r"(a[3]), "r"(b[0]), "r"(b[1]));
}

// ---------------- pack QKV weights: [H,D,DK]x3 -> [D, 3*H*DK] ----------------
__global__ void pack_qkv(const float* __restrict__ Wq, const float* __restrict__ Wk,
                         const float* __restrict__ Wv, const float* __restrict__ bq,
                         const float* __restrict__ bk, const float* __restrict__ bv)
{
    int idx = blockIdx.x * blockDim.x + threadIdx.x;
    if (idx < D_ * NQKV_) {
        int d  = idx / NQKV_;
        int j  = idx % NQKV_;
        int wh = j / D_;          // 0=q,1=k,2=v
        int jj = j % D_;          // h*DK + kk
        int h  = jj / DK_;
        int kk = jj % DK_;
        const float* W = (wh == 0) ? Wq : (wh == 1) ? Wk : Wv;
        g_wqkv[idx] = W[(h * D_ + d) * DK_ + kk];
    }
    if (idx < NQKV_) {
        int wh = idx / D_, jj = idx % D_;
        const float* bsrc = (wh == 0) ? bq : (wh == 1) ? bk : bv;
        g_bqkv[idx] = bsrc[jj];
    }
}

// ---------------- TF32 tensor-core GEMM (tf32 stored in smem) ----------------
// CTA tile 128x128, BK=32, 256 threads, warp tile 64x32, double-buffered.
#define SLD 132                    // padded smem leading dim (words)
#define SBUF (32 * SLD)            // one buffer of one operand

template<int RELU>
__global__ __launch_bounds__(256, 2) void gemm_tf32(
    const float* __restrict__ A, const float* __restrict__ Bm,
    const float* __restrict__ bias, float* __restrict__ C,
    int M, int N, int K)
{
    extern __shared__ uint32_t sm[];
    uint32_t* As = sm;               // [2][32][SLD] col-major (k, m), tf32
    uint32_t* Bs = sm + 2 * SBUF;    // [2][32][SLD] row-major (k, n), tf32

    const int t    = threadIdx.x;
    const int wid  = t >> 5;
    const int lane = t & 31;
    const int g    = lane >> 2;   // group 0..7
    const int q    = lane & 3;    // 0..3
    const int wm   = wid & 1;     // warp row (64 rows)
    const int wn   = wid >> 1;    // warp col (32 cols)
    const int rowC = blockIdx.y * 128;
    const int colC = blockIdx.x * 128;

    // A loader: row m_loc, k-halves kh..kh+15
    const int m_loc = t & 127;
    const int kh    = (t >> 7) * 16;
    // B loader: k-row kB, 16 cols n4..n4+15
    const int kB    = t >> 3;
    const int n4    = (t & 7) * 16;

    const float* Aptr = A  + (size_t)(rowC + m_loc) * K + kh;
    const float* Bptr = Bm + (size_t)kB * N + colC + n4;

    float acc[4][4][4];
#pragma unroll
    for (int i = 0; i < 4; i++)
#pragma unroll
        for (int j = 0; j < 4; j++)
#pragma unroll
            for (int r = 0; r < 4; r++) acc[i][j][r] = 0.f;

    const int ntiles = K / 32;

    // ---- prologue: tile 0 into buffer 0 ----
    {
#pragma unroll
        for (int j = 0; j < 4; j++) {
            float4 a4 = *(const float4*)(Aptr + 4 * j);
            As[(kh + 4 * j + 0) * SLD + m_loc] = f2tf32(a4.x);
            As[(kh + 4 * j + 1) * SLD + m_loc] = f2tf32(a4.y);
            As[(kh + 4 * j + 2) * SLD + m_loc] = f2tf32(a4.z);
            As[(kh + 4 * j + 3) * SLD + m_loc] = f2tf32(a4.w);
        }
#pragma unroll
        for (int j = 0; j < 4; j++) {
            float4 b4 = *(const float4*)(Bptr + 4 * j);
            uint4 u;
            u.x = f2tf32(b4.x); u.y = f2tf32(b4.y);
            u.z = f2tf32(b4.z); u.w = f2tf32(b4.w);
            *(uint4*)&Bs[kB * SLD + n4 + 4 * j] = u;
        }
        __syncthreads();
    }

    int buf = 0;
    for (int kt = 0; kt < ntiles; kt++) {
        const bool more = (kt + 1) < ntiles;
        float4 ar[4], br[4];
        if (more) {
            const float* ap = Aptr + (size_t)(kt + 1) * 32;
            const float* bp = Bptr + (size_t)(kt + 1) * 32 * N;
#pragma unroll
            for (int j = 0; j < 4; j++) ar[j] = *(const float4*)(ap + 4 * j);
#pragma unroll
            for (int j = 0; j < 4; j++) br[j] = *(const float4*)(bp + 4 * j);
        }

        // ---- compute on current buffer ----
        const uint32_t* Ab = As + buf * SBUF;
        const uint32_t* Bb = Bs + buf * SBUF;
#pragma unroll
        for (int kk = 0; kk < 4; kk++) {
            const int k0 = kk * 8;
            uint32_t af[4][4], bf[4][2];
#pragma unroll
            for (int mt = 0; mt < 4; mt++) {
                const int r0 = wm * 64 + mt * 16 + g;
                af[mt][0] = Ab[(k0 + q    ) * SLD + r0    ];
                af[mt][1] = Ab[(k0 + q    ) * SLD + r0 + 8];
                af[mt][2] = Ab[(k0 + q + 4) * SLD + r0    ];
                af[mt][3] = Ab[(k0 + q + 4) * SLD + r0 + 8];
            }
#pragma unroll
            for (int nt = 0; nt < 4; nt++) {
                const int c0 = wn * 32 + nt * 8 + g;
                bf[nt][0] = Bb[(k0 + q    ) * SLD + c0];
                bf[nt][1] = Bb[(k0 + q + 4) * SLD + c0];
            }
#pragma unroll
            for (int mt = 0; mt < 4; mt++)
#pragma unroll
                for (int nt = 0; nt < 4; nt++)
                    mma_tf32(acc[mt][nt], af[mt], bf[nt]);
        }

        if (more) {
            uint32_t* Ad = As + (buf ^ 1) * SBUF;
            uint32_t* Bd = Bs + (buf ^ 1) * SBUF;
#pragma unroll
            for (int j = 0; j < 4; j++) {
                Ad[(kh + 4 * j + 0) * SLD + m_loc] = f2tf32(ar[j].x);
                Ad[(kh + 4 * j + 1) * SLD + m_loc] = f2tf32(ar[j].y);
                Ad[(kh + 4 * j + 2) * SLD + m_loc] = f2tf32(ar[j].z);
                Ad[(kh + 4 * j + 3) * SLD + m_loc] = f2tf32(ar[j].w);
            }
#pragma unroll
            for (int j = 0; j < 4; j++) {
                uint4 u;
                u.x = f2tf32(br[j].x); u.y = f2tf32(br[j].y);
                u.z = f2tf32(br[j].z); u.w = f2tf32(br[j].w);
                *(uint4*)&Bd[kB * SLD + n4 + 4 * j] = u;
            }
        }
        __syncthreads();
        buf ^= 1;
    }

    // ---- epilogue: bias (+ReLU), STG.64 ----
#pragma unroll
    for (int mt = 0; mt < 4; mt++) {
        const int r0 = rowC + wm * 64 + mt * 16 + g;
#pragma unroll
        for (int nt = 0; nt < 4; nt++) {
            const int c = colC + wn * 32 + nt * 8 + 2 * q;
            const float b0v = bias[c], b1v = bias[c + 1];
            float2 o0 = make_float2(acc[mt][nt][0] + b0v, acc[mt][nt][1] + b1v);
            float2 o1 = make_float2(acc[mt][nt][2] + b0v, acc[mt][nt][3] + b1v);
            if (RELU) {
                o0.x = fmaxf(o0.x, 0.f); o0.y = fmaxf(o0.y, 0.f);
                o1.x = fmaxf(o1.x, 0.f); o1.y = fmaxf(o1.y, 0.f);
            }
            *(float2*)(C + (size_t)r0 * N + c)       = o0;
            *(float2*)(C + (size_t)(r0 + 8) * N + c) = o1;
        }
    }
}

// ---------------- TF32 mma flash attention ----------------
// CTA: 128 q-rows, 8 warps (16 rows each), 64-key tiles, online softmax.
// smem: QPs [128][LDQ] (Q staging, reused as P), Ks [64][LDK], Vs [64][LDV],
// all tf32 words; strides chosen for conflict-free fragment LDS.
#define AT_BQ 128
#define AT_BK 64
#define LDQ 68
#define LDK 68
#define LDV 72
#define ATT_SMEM ((AT_BQ*LDQ + AT_BK*LDK + AT_BK*LDV) * 4)

__global__ __launch_bounds__(256, 2) void attn_mma_kernel(
    const float* __restrict__ qkv, float* __restrict__ out)
{
    extern __shared__ uint32_t smw[];
    uint32_t* QPs = smw;                    // [128][LDQ] Q staging -> P buffer
    uint32_t* Ks  = smw + AT_BQ * LDQ;      // [64][LDK]
    uint32_t* Vs  = Ks + AT_BK * LDK;       // [64][LDV]

    const int t    = threadIdx.x;
    const int w    = t >> 5;
    const int lane = t & 31;
    const int g    = lane >> 2;
    const int q    = lane & 3;
    const int qb = blockIdx.x, h = blockIdx.y, b = blockIdx.z;

    const float* base = qkv + (size_t)b * S_ * NQKV_ + h * DK_;

    // stage Q tile (scaled by 1/8, tf32)
    {
        const int r  = t >> 1;
        const int c0 = (t & 1) * 32;
        const float* qp = base + (size_t)(qb * AT_BQ + r) * NQKV_ + c0;
#pragma unroll
        for (int j = 0; j < 8; j++) {
            float4 v = *(const float4*)(qp + 4 * j);
            uint4 u;
            u.x = f2tf32(v.x * 0.125f); u.y = f2tf32(v.y * 0.125f);
            u.z = f2tf32(v.z * 0.125f); u.w = f2tf32(v.w * 0.125f);
            *(uint4*)&QPs[r * LDQ + c0 + 4 * j] = u;
        }
    }
    __syncthreads();

    // Q fragments into registers (rows w*16 .. w*16+15)
    uint32_t qa[8][4];
    {
        const uint32_t* Qw = QPs + (w * 16) * LDQ;
#pragma unroll
        for (int ks = 0; ks < 8; ks++) {
            qa[ks][0] = Qw[(g    ) * LDQ + ks * 8 + q    ];
            qa[ks][1] = Qw[(g + 8) * LDQ + ks * 8 + q    ];
            qa[ks][2] = Qw[(g    ) * LDQ + ks * 8 + q + 4];
            qa[ks][3] = Qw[(g + 8) * LDQ + ks * 8 + q + 4];
        }
    }
    __syncthreads();   // Q staging now reusable as P

    float m0 = -3.0e38f, m1 = -3.0e38f, l0 = 0.f, l1 = 0.f;
    float o[8][4];
#pragma unroll
    for (int nt = 0; nt < 8; nt++)
#pragma unroll
        for (int r = 0; r < 4; r++) o[nt][r] = 0.f;

    uint32_t* Pw = QPs + (w * 16) * LDQ;   // warp-private P rows

    const int ldr_r  = t >> 2;
    const int ldr_c0 = (t & 3) * 16;

    for (int kb = 0; kb < S_ / AT_BK; kb++) {
        __syncthreads();   // all warps done reading previous K/V
        // load K, V tiles (tf32)
        {
            const float* kp = base + (size_t)(kb * AT_BK + ldr_r) * NQKV_ + D_ + ldr_c0;
            const float* vp = kp + D_;
#pragma unroll
            for (int j = 0; j < 4; j++) {
                float4 kv = *(const float4*)(kp + 4 * j);
                uint4 uk;
                uk.x = f2tf32(kv.x); uk.y = f2tf32(kv.y);
                uk.z = f2tf32(kv.z); uk.w = f2tf32(kv.w);
                *(uint4*)&Ks[ldr_r * LDK + ldr_c0 + 4 * j] = uk;
                float4 vv = *(const float4*)(vp + 4 * j);
                uint4 uv;
                uv.x = f2tf32(vv.x); uv.y = f2tf32(vv.y);
                uv.z = f2tf32(vv.z); uv.w = f2tf32(vv.w);
                *(uint4*)&Vs[ldr_r * LDV + ldr_c0 + 4 * j] = uv;
            }
        }
        __syncthreads();

        // S = Q @ K^T
        float s[8][4];
#pragma unroll
        for (int nt = 0; nt < 8; nt++) {
#pragma unroll
            for (int r = 0; r < 4; r++) s[nt][r] = 0.f;
            const uint32_t* Kr = Ks + (nt * 8 + g) * LDK;
#pragma unroll
            for (int ks = 0; ks < 8; ks++) {
                uint32_t bb[2];
                bb[0] = Kr[ks * 8 + q    ];
                bb[1] = Kr[ks * 8 + q + 4];
                mma_tf32(s[nt], qa[ks], bb);
            }
        }

        // online softmax (rows g and g+8; row stats across lanes g*4..g*4+3)
        float mx0 = -3.0e38f, mx1 = -3.0e38f;
#pragma unroll
        for (int nt = 0; nt < 8; nt++) {
            mx0 = fmaxf(mx0, fmaxf(s[nt][0], s[nt][1]));
            mx1 = fmaxf(mx1, fmaxf(s[nt][2], s[nt][3]));
        }
        mx0 = fmaxf(mx0, __shfl_xor_sync(0xffffffffu, mx0, 1));
        mx0 = fmaxf(mx0, __shfl_xor_sync(0xffffffffu, mx0, 2));
        mx1 = fmaxf(mx1, __shfl_xor_sync(0xffffffffu, mx1, 1));
        mx1 = fmaxf(mx1, __shfl_xor_sync(0xffffffffu, mx1, 2));

        float mn0 = fmaxf(m0, mx0), mn1 = fmaxf(m1, mx1);
        float f0 = __expf(m0 - mn0), f1 = __expf(m1 - mn1);
        m0 = mn0; m1 = mn1;

        float ls0 = 0.f, ls1 = 0.f;
#pragma unroll
        for (int nt = 0; nt < 8; nt++) {
            float p00 = __expf(s[nt][0] - mn0);
            float p01 = __expf(s[nt][1] - mn0);
            float p10 = __expf(s[nt][2] - mn1);
            float p11 = __expf(s[nt][3] - mn1);
            ls0 += p00 + p01;
            ls1 += p10 + p11;
            uint2 u0; u0.x = f2tf32(p00); u0.y = f2tf32(p01);
            uint2 u1; u1.x = f2tf32(p10); u1.y = f2tf32(p11);
            *(uint2*)&Pw[(g    ) * LDQ + nt * 8 + 2 * q] = u0;
            *(uint2*)&Pw[(g + 8) * LDQ + nt * 8 + 2 * q] = u1;
            o[nt][0] *= f0; o[nt][1] *= f0;
            o[nt][2] *= f1; o[nt][3] *= f1;
        }
        ls0 += __shfl_xor_sync(0xffffffffu, ls0, 1);
        ls0 += __shfl_xor_sync(0xffffffffu, ls0, 2);
        ls1 += __shfl_xor_sync(0xffffffffu, ls1, 1);
        ls1 += __shfl_xor_sync(0xffffffffu, ls1, 2);
        l0 = l0 * f0 + ls0;
        l1 = l1 * f1 + ls1;
        __syncwarp();   // P rows are warp-private; only intra-warp visibility needed

        // O += P @ V
#pragma unroll
        for (int ks = 0; ks < 8; ks++) {
            uint32_t pa[4];
            pa[0] = Pw[(g    ) * LDQ + ks * 8 + q    ];
            pa[1] = Pw[(g + 8) * LDQ + ks * 8 + q    ];
            pa[2] = Pw[(g    ) * LDQ + ks * 8 + q + 4];
            pa[3] = Pw[(g + 8) * LDQ + ks * 8 + q + 4];
#pragma unroll
            for (int nt = 0; nt < 8; nt++) {
                uint32_t bb[2];
                bb[0] = Vs[(ks * 8 + q    ) * LDV + nt * 8 + g];
                bb[1] = Vs[(ks * 8 + q + 4) * LDV + nt * 8 + g];
                mma_tf32(o[nt], pa, bb);
            }
        }
    }

    // epilogue: normalize and write concat-head output
    const float i0 = 1.0f / l0, i1 = 1.0f / l1;
    float* op = out + (size_t)(b * S_ + qb * AT_BQ + w * 16) * D_ + h * DK_;
#pragma unroll
    for (int nt = 0; nt < 8; nt++) {
        float2 r0 = make_float2(o[nt][0] * i0, o[nt][1] * i0);
        float2 r1 = make_float2(o[nt][2] * i1, o[nt][3] * i1);
        *(float2*)(op + (size_t)(g    ) * D_ + nt * 8 + 2 * q) = r0;
        *(float2*)(op + (size_t)(g + 8) * D_ + nt * 8 + 2 * q) = r1;
    }
}

// ---------------- fused residual-add + LayerNorm ----------------
__global__ __launch_bounds__(256) void add_ln_kernel(
    const float* __restrict__ A, const float* __restrict__ Bv,
    const float* __restrict__ gamma, const float* __restrict__ beta,
    float* __restrict__ out)
{
    const int row = blockIdx.x;
    const int t   = threadIdx.x;
    __shared__ float wr[8];
    __shared__ float sMean, sRstd;

    const float* pa = A  + (size_t)row * D_;
    const float* pb = Bv + (size_t)row * D_;

    float v0 = pa[t]       + pb[t];
    float v1 = pa[t + 256] + pb[t + 256];
    float v2 = pa[t + 512] + pb[t + 512];

    float s = v0 + v1 + v2;
#pragma unroll
    for (int mk = 16; mk; mk >>= 1) s += __shfl_xor_sync(0xffffffffu, s, mk);
    if ((t & 31) == 0) wr[t >> 5] = s;
    __syncthreads();
    if (t == 0) {
        float tot = 0;
        for (int i = 0; i < 8; i++) tot += wr[i];
        sMean = tot * (1.0f / D_);
    }
    __syncthreads();
    float mean = sMean;
    float d0 = v0 - mean, d1 = v1 - mean, d2 = v2 - mean;
    float qv = d0 * d0 + d1 * d1 + d2 * d2;
#pragma unroll
    for (int mk = 16; mk; mk >>= 1) qv += __shfl_xor_sync(0xffffffffu, qv, mk);
    if ((t & 31) == 0) wr[t >> 5] = qv;
    __syncthreads();
    if (t == 0) {
        float tot = 0;
        for (int i = 0; i < 8; i++) tot += wr[i];
        sRstd = rsqrtf(tot * (1.0f / D_) + 1e-5f);
    }
    __syncthreads();
    float rstd = sRstd;

    float* po = out + (size_t)row * D_;
    po[t]       = d0 * rstd * gamma[t]       + beta[t];
    po[t + 256] = d1 * rstd * gamma[t + 256] + beta[t + 256];
    po[t + 512] = d2 * rstd * gamma[t + 512] + beta[t + 512];
}

// ---------------- launch ----------------
extern "C" void kernel_launch(void* const* d_in, const int* in_sizes, int n_in,
                              void* d_out, int out_size)
{
    const float* src = (const float*)d_in[0];
    const float* Wq  = (const float*)d_in[1];
    const float* bq  = (const float*)d_in[2];
    const float* Wk  = (const float*)d_in[3];
    const float* bk  = (const float*)d_in[4];
    const float* Wv  = (const float*)d_in[5];
    const float* bv  = (const float*)d_in[6];
    const float* Wo  = (const float*)d_in[7];
    const float* bo  = (const float*)d_in[8];
    const float* g1  = (const float*)d_in[9];
    const float* be1 = (const float*)d_in[10];
    const float* W1  = (const float*)d_in[11];
    const float* bf1 = (const float*)d_in[12];
    const float* W2  = (const float*)d_in[13];
    const float* bf2 = (const float*)d_in[14];
    const float* g2  = (const float*)d_in[15];
    const float* be2 = (const float*)d_in[16];
    float* out = (float*)d_out;

    float *wqkv, *bqkv, *qkv, *attn, *mha, *x1, *ffn1, *ffn2;
    cudaGetSymbolAddress((void**)&wqkv, g_wqkv);
    cudaGetSymbolAddress((void**)&bqkv, g_bqkv);
    cudaGetSymbolAddress((void**)&qkv,  g_qkv);
    cudaGetSymbolAddress((void**)&attn, g_attn);
    cudaGetSymbolAddress((void**)&mha,  g_mha);
    cudaGetSymbolAddress((void**)&x1,   g_x1);
    cudaGetSymbolAddress((void**)&ffn1, g_ffn1);
    cudaGetSymbolAddress((void**)&ffn2, g_ffn2);

    const int gemm_smem = 4 * SBUF * (int)sizeof(uint32_t);   // 67584 B
    cudaFuncSetAttribute(gemm_tf32<0>, cudaFuncAttributeMaxDynamicSharedMemorySize, gemm_smem);
    cudaFuncSetAttribute(gemm_tf32<1>, cudaFuncAttributeMaxDynamicSharedMemorySize, gemm_smem);
    cudaFuncSetAttribute(attn_mma_kernel, cudaFuncAttributeMaxDynamicSharedMemorySize, ATT_SMEM);

    // 1) pack QKV weights+bias
    pack_qkv<<<(D_ * NQKV_ + 255) / 256, 256>>>(Wq, Wk, Wv, bq, bk, bv);

    // 2) QKV projection: [8192,768] @ [768,2304]
    gemm_tf32<0><<<dim3(NQKV_ / 128, M_ / 128), 256, gemm_smem>>>(src, wqkv, bqkv, qkv, M_, NQKV_, D_);

    // 3) fused attention (tf32 mma)
    attn_mma_kernel<<<dim3(S_ / AT_BQ, H_, B_), 256, ATT_SMEM>>>(qkv, attn);

    // 4) output projection
    gemm_tf32<0><<<dim3(D_ / 128, M_ / 128), 256, gemm_smem>>>(attn, Wo, bo, mha, M_, D_, D_);

    // 5) x1 = LN(src + mha)
    add_ln_kernel<<<M_, 256>>>(src, mha, g1, be1, x1);

    // 6) FFN1 (+ReLU): [8192,768] @ [768,3072]
    gemm_tf32<1><<<dim3(F_ / 128, M_ / 128), 256, gemm_smem>>>(x1, W1, bf1, ffn1, M_, F_, D_);

    // 7) FFN2: [8192,3072] @ [3072,768]
    gemm_tf32<0><<<dim3(D_ / 128, M_ / 128), 256, gemm_smem>>>(ffn1, W2, bf2, ffn2, M_, D_, F_);

    // 8) out = LN(x1 + ffn2)
    add_ln_kernel<<<M_, 256>>>(x1, ffn2, g2, be2, out);
}

// round 5
// speedup vs baseline: 3.6426x; 1.6235x over previous
#include <cuda_runtime.h>
#include <math.h>
#include <stdint.h>

// Problem constants
#define B_    4
#define S_    2048
#define D_    768
#define H_    12
#define DK_   64
#define F_    3072
#define M_    (B_*S_)        // 8192 rows
#define NQKV_ (3*D_)         // 2304

// ---------------- scratch (static device globals; no allocation) ----------------
__device__ float g_wqkvT[NQKV_*D_];         // packed+transposed QKV weights [3*H*DK][D] tf32
__device__ float g_bqkv[NQKV_];             // packed QKV bias
__device__ float g_woT [D_*D_];             // Wo^T  [D][D]   tf32
__device__ float g_w1T [F_*D_];             // W1^T  [F][D]   tf32
__device__ float g_w2T [D_*F_];             // W2^T  [D][F]   tf32
__device__ float g_srct[M_*D_];             // tf32-rounded source
__device__ float g_x1t [M_*D_];             // tf32-rounded x1
__device__ float g_qkv [M_*NQKV_];          // [B*S, 2304]  (q | k | v), tf32-rounded
__device__ float g_attn[M_*D_];             // concat heads, tf32-rounded
__device__ float g_mha [M_*D_];
__device__ float g_x1  [M_*D_];
__device__ float g_ffn1[M_*F_];             // tf32-rounded (feeds FFN2 only)
__device__ float g_ffn2[M_*D_];

// ---------------- helpers ----------------
__device__ __forceinline__ uint32_t f2tf32(float x) {
    uint32_t r;
    asm volatile("cvt.rna.tf32.f32 %0, %1;" : "=r"(r) : "f"(x));
    return r;
}

__device__ __forceinline__ void mma_tf32(float* d, const uint32_t* a, const uint32_t* b) {
    asm volatile(
        "mma.sync.aligned.m16n8k8.row.col.f32.tf32.tf32.f32 "
        "{%0,%1,%2,%3}, {%4,%5,%6,%7}, {%8,%9}, {%0,%1,%2,%3};"
        : "+f"(d[0]), "+f"(d[1]), "+f"(d[2]), "+f"(d[3])
        : "r"(a[0]), "r"(a[1]), "r"(a[2]), "r"(a[3]), "r"(b[0]), "r"(b[1]));
}

__device__ __forceinline__ void ldsm4(uint32_t* r, uint32_t addr) {
    asm volatile("ldmatrix.sync.aligned.m8n8.x4.shared.b16 {%0,%1,%2,%3}, [%4];"
                 : "=r"(r[0]), "=r"(r[1]), "=r"(r[2]), "=r"(r[3]) : "r"(addr));
}

__device__ __forceinline__ void cp_async16(uint32_t smem_dst, const void* gmem_src) {
    asm volatile("cp.async.cg.shared.global [%0], [%1], 16;" :: "r"(smem_dst), "l"(gmem_src));
}

// ---------------- weight prep kernels ----------------
// tf32-rounding elementwise copy
__global__ void cvt_tf32_copy(const float* __restrict__ in, float* __restrict__ out, int n4)
{
    int i = (blockIdx.x * blockDim.x + threadIdx.x) * 4;
    if (i < n4 * 4) {
        float4 v = *(const float4*)(in + i);
        uint4 u;
        u.x = f2tf32(v.x); u.y = f2tf32(v.y); u.z = f2tf32(v.z); u.w = f2tf32(v.w);
        *(uint4*)(out + i) = u;
    }
}

// tiled transpose with tf32 rounding: in[R][C] -> out[C][R]
__global__ void transpose_cvt(const float* __restrict__ in, float* __restrict__ out,
                              int R, int C)
{
    __shared__ float tile[32][33];
    const int c0 = blockIdx.x * 32, r0 = blockIdx.y * 32;
    const int tx = threadIdx.x, ty = threadIdx.y;
#pragma unroll
    for (int i = 0; i < 32; i += 8)
        tile[ty + i][tx] = in[(size_t)(r0 + ty + i) * C + c0 + tx];
    __syncthreads();
#pragma unroll
    for (int i = 0; i < 32; i += 8)
        out[(size_t)(c0 + ty + i) * R + r0 + tx] = __uint_as_float(f2tf32(tile[tx][ty + i]));
}

// QKV weights: [H,D,DK]x3 -> transposed packed [3*H*DK][D] (tf32)
__global__ void pack_qkv_wT(const float* __restrict__ Wq, const float* __restrict__ Wk,
                            const float* __restrict__ Wv, float* __restrict__ out)
{
    __shared__ float tile[32][33];
    const int z = blockIdx.z;          // 0..35
    const int wh = z / H_, h = z % H_;
    const float* W = ((wh == 0) ? Wq : (wh == 1) ? Wk : Wv) + (size_t)h * D_ * DK_;
    const int d0 = blockIdx.y * 32, k0 = blockIdx.x * 32;
    const int tx = threadIdx.x, ty = threadIdx.y;
#pragma unroll
    for (int i = 0; i < 32; i += 8)
        tile[ty + i][tx] = W[(size_t)(d0 + ty + i) * DK_ + k0 + tx];
    __syncthreads();
    const int orow = wh * D_ + h * DK_ + k0;
#pragma unroll
    for (int i = 0; i < 32; i += 8)
        out[(size_t)(orow + ty + i) * D_ + d0 + tx] = __uint_as_float(f2tf32(tile[tx][ty + i]));
}

__global__ void pack_qkv_bias(const float* __restrict__ bq, const float* __restrict__ bk,
                              const float* __restrict__ bv)
{
    int idx = blockIdx.x * blockDim.x + threadIdx.x;
    if (idx < NQKV_) {
        int wh = idx / D_, jj = idx % D_;
        const float* bsrc = (wh == 0) ? bq : (wh == 1) ? bk : bv;
        g_bqkv[idx] = bsrc[jj];
    }
}

// ---------------- TF32 tensor-core GEMM: ldmatrix + cp.async pipeline ----------------
// C[M,N] = A[M,K] @ Bt[N,K]^T + bias. A,Bt tf32-rounded fp32 in gmem.
// CTA tile 128x256, BK=32, 256 threads (8 warps, 2x4), warp tile 64x64, 3 stages.
#define BMg 128
#define BNg 256
#define BKg 32
#define STAGES 3
#define A_CHUNKS (BMg*8)                   // 16B chunks per stage
#define B_CHUNKS (BNg*8)
#define STAGE_CHUNKS (A_CHUNKS + B_CHUNKS) // 3072 -> 48KB/stage
#define GEMM_SMEM (STAGES * STAGE_CHUNKS * 16)

#define CP_COMMIT() asm volatile("cp.async.commit_group;")
#define CP_WAIT1()  asm volatile("cp.async.wait_group 1;")

template<int RELU, int OUTCVT>
__global__ __launch_bounds__(256, 1) void gemm_tc(
    const float* __restrict__ A, const float* __restrict__ Bt,
    const float* __restrict__ bias, float* __restrict__ C,
    int M, int N, int K)
{
    extern __shared__ uint4 smem4[];
    const uint32_t smem_base = (uint32_t)__cvta_generic_to_shared(smem4);

    const int t    = threadIdx.x;
    const int lane = t & 31;
    const int wid  = t >> 5;
    const int wm   = wid & 1;     // 0..1 (64-row slab)
    const int wn   = wid >> 1;    // 0..3 (64-col slab)
    const int rowC = blockIdx.y * BMg;
    const int colC = blockIdx.x * BNg;

    float acc[4][8][4];
#pragma unroll
    for (int i = 0; i < 4; i++)
#pragma unroll
        for (int j = 0; j < 8; j++)
#pragma unroll
            for (int r = 0; r < 4; r++) acc[i][j][r] = 0.f;

    const int ntiles = K / BKg;

    // loader: A 4 chunks/thread, B 8 chunks/thread
    auto load_tile = [&](int stage, int kt) {
        const uint32_t sa = smem_base + stage * (STAGE_CHUNKS * 16);
#pragma unroll
        for (int i = 0; i < 4; i++) {
            int lin = i * 256 + t;
            int m = lin >> 3, c4 = lin & 7;
            uint32_t dst = sa + (uint32_t)(m * 8 + (c4 ^ (m & 7))) * 16;
            cp_async16(dst, A + (size_t)(rowC + m) * K + kt * BKg + c4 * 4);
        }
#pragma unroll
        for (int i = 0; i < 8; i++) {
            int lin = i * 256 + t;
            int n = lin >> 3, c4 = lin & 7;
            uint32_t dst = sa + (uint32_t)(A_CHUNKS + n * 8 + (c4 ^ (n & 7))) * 16;
            cp_async16(dst, Bt + (size_t)(colC + n) * K + kt * BKg + c4 * 4);
        }
        CP_COMMIT();
    };

    // prologue: first STAGES-1 tiles
    load_tile(0, 0);
    load_tile(1, 1);

    // per-thread fragment address invariants
    const int lrow = lane & 15;
    const int hi   = lane >> 4;
    const int xr   = lane & 7;
    uint32_t aRowOff[4], bRowOff[4];
#pragma unroll
    for (int mt = 0; mt < 4; mt++)
        aRowOff[mt] = (uint32_t)((wm * 64 + mt * 16 + lrow) * 8) * 16;
#pragma unroll
    for (int nt2 = 0; nt2 < 4; nt2++)
        bRowOff[nt2] = (uint32_t)(A_CHUNKS + (wn * 64 + nt2 * 16 + lrow) * 8) * 16;

    for (int kt = 0; kt < ntiles; kt++) {
        CP_WAIT1();
        __syncthreads();

        const int nxt = kt + STAGES - 1;
        if (nxt < ntiles) load_tile(nxt % STAGES, nxt);
        else              CP_COMMIT();

        const uint32_t sa = smem_base + (kt % STAGES) * (STAGE_CHUNKS * 16);
#pragma unroll
        for (int kk = 0; kk < 4; kk++) {
            const uint32_t cx = (uint32_t)(((2 * kk + hi) ^ xr) * 16);
            uint32_t a[4][4], bfr[4][4];
#pragma unroll
            for (int mt = 0; mt < 4; mt++)
                ldsm4(a[mt], sa + aRowOff[mt] + cx);
#pragma unroll
            for (int nt2 = 0; nt2 < 4; nt2++)
                ldsm4(bfr[nt2], sa + bRowOff[nt2] + cx);
#pragma unroll
            for (int mt = 0; mt < 4; mt++)
#pragma unroll
                for (int nt = 0; nt < 8; nt++) {
                    uint32_t bb[2];
                    bb[0] = bfr[nt >> 1][(nt & 1)];
                    bb[1] = bfr[nt >> 1][2 + (nt & 1)];
                    mma_tf32(acc[mt][nt], a[mt], bb);
                }
        }
    }

    // epilogue
    const int g2 = lane >> 2, q2 = lane & 3;
#pragma unroll
    for (int mt = 0; mt < 4; mt++) {
        const int r0 = rowC + wm * 64 + mt * 16 + g2;
        float* cp0 = C + (size_t)r0 * N;
        float* cp1 = C + (size_t)(r0 + 8) * N;
#pragma unroll
        for (int nt = 0; nt < 8; nt++) {
            const int c = colC + wn * 64 + nt * 8 + 2 * q2;
            const float b0v = bias[c], b1v = bias[c + 1];
            float2 o0 = make_float2(acc[mt][nt][0] + b0v, acc[mt][nt][1] + b1v);
            float2 o1 = make_float2(acc[mt][nt][2] + b0v, acc[mt][nt][3] + b1v);
            if (RELU) {
                o0.x = fmaxf(o0.x, 0.f); o0.y = fmaxf(o0.y, 0.f);
                o1.x = fmaxf(o1.x, 0.f); o1.y = fmaxf(o1.y, 0.f);
            }
            if (OUTCVT) {
                o0.x = __uint_as_float(f2tf32(o0.x)); o0.y = __uint_as_float(f2tf32(o0.y));
                o1.x = __uint_as_float(f2tf32(o1.x)); o1.y = __uint_as_float(f2tf32(o1.y));
            }
            *(float2*)(cp0 + c) = o0;
            *(float2*)(cp1 + c) = o1;
        }
    }
}

// ---------------- TF32 mma flash attention ----------------
// CTA: 128 q-rows, 8 warps (16 rows each), 64-key tiles, online softmax.
// qkv is already tf32-rounded -> loads are bit copies.
#define AT_BQ 128
#define AT_BK 64
#define LDQ 68
#define LDK 68
#define LDV 72
#define ATT_SMEM ((AT_BQ*LDQ + AT_BK*LDK + AT_BK*LDV) * 4)

__global__ __launch_bounds__(256, 2) void attn_mma_kernel(
    const float* __restrict__ qkv, float* __restrict__ out)
{
    extern __shared__ uint32_t smw[];
    uint32_t* QPs = smw;                    // [128][LDQ] Q staging -> P buffer
    uint32_t* Ks  = smw + AT_BQ * LDQ;      // [64][LDK]
    uint32_t* Vs  = Ks + AT_BK * LDK;       // [64][LDV]

    const int t    = threadIdx.x;
    const int w    = t >> 5;
    const int lane = t & 31;
    const int g    = lane >> 2;
    const int q    = lane & 3;
    const int qb = blockIdx.x, h = blockIdx.y, b = blockIdx.z;

    const float* base = qkv + (size_t)b * S_ * NQKV_ + h * DK_;

    // stage Q tile (scaled by 1/8; values already tf32 -> exponent-only scale keeps tf32)
    {
        const int r  = t >> 1;
        const int c0 = (t & 1) * 32;
        const float* qp = base + (size_t)(qb * AT_BQ + r) * NQKV_ + c0;
#pragma unroll
        for (int j = 0; j < 8; j++) {
            float4 v = *(const float4*)(qp + 4 * j);
            uint4 u;
            u.x = __float_as_uint(v.x * 0.125f); u.y = __float_as_uint(v.y * 0.125f);
            u.z = __float_as_uint(v.z * 0.125f); u.w = __float_as_uint(v.w * 0.125f);
            *(uint4*)&QPs[r * LDQ + c0 + 4 * j] = u;
        }
    }
    __syncthreads();

    // Q fragments into registers (rows w*16 .. w*16+15)
    uint32_t qa[8][4];
    {
        const uint32_t* Qw = QPs + (w * 16) * LDQ;
#pragma unroll
        for (int ks = 0; ks < 8; ks++) {
            qa[ks][0] = Qw[(g    ) * LDQ + ks * 8 + q    ];
            qa[ks][1] = Qw[(g + 8) * LDQ + ks * 8 + q    ];
            qa[ks][2] = Qw[(g    ) * LDQ + ks * 8 + q + 4];
            qa[ks][3] = Qw[(g + 8) * LDQ + ks * 8 + q + 4];
        }
    }
    __syncthreads();   // Q staging now reusable as P

    float m0 = -3.0e38f, m1 = -3.0e38f, l0 = 0.f, l1 = 0.f;
    float o[8][4];
#pragma unroll
    for (int nt = 0; nt < 8; nt++)
#pragma unroll
        for (int r = 0; r < 4; r++) o[nt][r] = 0.f;

    uint32_t* Pw = QPs + (w * 16) * LDQ;   // warp-private P rows

    const int ldr_r  = t >> 2;
    const int ldr_c0 = (t & 3) * 16;

    for (int kb = 0; kb < S_ / AT_BK; kb++) {
        __syncthreads();   // all warps done reading previous K/V
        {
            const float* kp = base + (size_t)(kb * AT_BK + ldr_r) * NQKV_ + D_ + ldr_c0;
            const float* vp = kp + D_;
#pragma unroll
            for (int j = 0; j < 4; j++) {
                *(uint4*)&Ks[ldr_r * LDK + ldr_c0 + 4 * j] = *(const uint4*)(kp + 4 * j);
                *(uint4*)&Vs[ldr_r * LDV + ldr_c0 + 4 * j] = *(const uint4*)(vp + 4 * j);
            }
        }
        __syncthreads();

        // S = Q @ K^T
        float s[8][4];
#pragma unroll
        for (int nt = 0; nt < 8; nt++) {
#pragma unroll
            for (int r = 0; r < 4; r++) s[nt][r] = 0.f;
            const uint32_t* Kr = Ks + (nt * 8 + g) * LDK;
#pragma unroll
            for (int ks = 0; ks < 8; ks++) {
                uint32_t bb[2];
                bb[0] = Kr[ks * 8 + q    ];
                bb[1] = Kr[ks * 8 + q + 4];
                mma_tf32(s[nt], qa[ks], bb);
            }
        }

        // online softmax
        float mx0 = -3.0e38f, mx1 = -3.0e38f;
#pragma unroll
        for (int nt = 0; nt < 8; nt++) {
            mx0 = fmaxf(mx0, fmaxf(s[nt][0], s[nt][1]));
            mx1 = fmaxf(mx1, fmaxf(s[nt][2], s[nt][3]));
        }
        mx0 = fmaxf(mx0, __shfl_xor_sync(0xffffffffu, mx0, 1));
        mx0 = fmaxf(mx0, __shfl_xor_sync(0xffffffffu, mx0, 2));
        mx1 = fmaxf(mx1, __shfl_xor_sync(0xffffffffu, mx1, 1));
        mx1 = fmaxf(mx1, __shfl_xor_sync(0xffffffffu, mx1, 2));

        float mn0 = fmaxf(m0, mx0), mn1 = fmaxf(m1, mx1);
        float f0 = __expf(m0 - mn0), f1 = __expf(m1 - mn1);
        m0 = mn0; m1 = mn1;

        float ls0 = 0.f, ls1 = 0.f;
#pragma unroll
        for (int nt = 0; nt < 8; nt++) {
            float p00 = __expf(s[nt][0] - mn0);
            float p01 = __expf(s[nt][1] - mn0);
            float p10 = __expf(s[nt][2] - mn1);
            float p11 = __expf(s[nt][3] - mn1);
            ls0 += p00 + p01;
            ls1 += p10 + p11;
            uint2 u0; u0.x = f2tf32(p00); u0.y = f2tf32(p01);
            uint2 u1; u1.x = f2tf32(p10); u1.y = f2tf32(p11);
            *(uint2*)&Pw[(g    ) * LDQ + nt * 8 + 2 * q] = u0;
            *(uint2*)&Pw[(g + 8) * LDQ + nt * 8 + 2 * q] = u1;
            o[nt][0] *= f0; o[nt][1] *= f0;
            o[nt][2] *= f1; o[nt][3] *= f1;
        }
        ls0 += __shfl_xor_sync(0xffffffffu, ls0, 1);
        ls0 += __shfl_xor_sync(0xffffffffu, ls0, 2);
        ls1 += __shfl_xor_sync(0xffffffffu, ls1, 1);
        ls1 += __shfl_xor_sync(0xffffffffu, ls1, 2);
        l0 = l0 * f0 + ls0;
        l1 = l1 * f1 + ls1;
        __syncwarp();

        // O += P @ V
#pragma unroll
        for (int ks = 0; ks < 8; ks++) {
            uint32_t pa[4];
            pa[0] = Pw[(g    ) * LDQ + ks * 8 + q    ];
            pa[1] = Pw[(g + 8) * LDQ + ks * 8 + q    ];
            pa[2] = Pw[(g    ) * LDQ + ks * 8 + q + 4];
            pa[3] = Pw[(g + 8) * LDQ + ks * 8 + q + 4];
#pragma unroll
            for (int nt = 0; nt < 8; nt++) {
                uint32_t bb[2];
                bb[0] = Vs[(ks * 8 + q    ) * LDV + nt * 8 + g];
                bb[1] = Vs[(ks * 8 + q + 4) * LDV + nt * 8 + g];
                mma_tf32(o[nt], pa, bb);
            }
        }
    }

    // epilogue: normalize, tf32-round (feeds out-proj GEMM), write
    const float i0 = 1.0f / l0, i1 = 1.0f / l1;
    float* op = out + (size_t)(b * S_ + qb * AT_BQ + w * 16) * D_ + h * DK_;
#pragma unroll
    for (int nt = 0; nt < 8; nt++) {
        float2 r0, r1;
        r0.x = __uint_as_float(f2tf32(o[nt][0] * i0));
        r0.y = __uint_as_float(f2tf32(o[nt][1] * i0));
        r1.x = __uint_as_float(f2tf32(o[nt][2] * i1));
        r1.y = __uint_as_float(f2tf32(o[nt][3] * i1));
        *(float2*)(op + (size_t)(g    ) * D_ + nt * 8 + 2 * q) = r0;
        *(float2*)(op + (size_t)(g + 8) * D_ + nt * 8 + 2 * q) = r1;
    }
}

// ---------------- fused residual-add + LayerNorm (optionally dual fp32+tf32 out) ----------------
template<int DUAL>
__global__ __launch_bounds__(256) void add_ln_kernel(
    const float* __restrict__ A, const float* __restrict__ Bv,
    const float* __restrict__ gamma, const float* __restrict__ beta,
    float* __restrict__ out, float* __restrict__ outt)
{
    const int row = blockIdx.x;
    const int t   = threadIdx.x;
    __shared__ float wr[8];
    __shared__ float sMean, sRstd;

    const float* pa = A  + (size_t)row * D_;
    const float* pb = Bv + (size_t)row * D_;

    float v0 = pa[t]       + pb[t];
    float v1 = pa[t + 256] + pb[t + 256];
    float v2 = pa[t + 512] + pb[t + 512];

    float s = v0 + v1 + v2;
#pragma unroll
    for (int mk = 16; mk; mk >>= 1) s += __shfl_xor_sync(0xffffffffu, s, mk);
    if ((t & 31) == 0) wr[t >> 5] = s;
    __syncthreads();
    if (t == 0) {
        float tot = 0;
        for (int i = 0; i < 8; i++) tot += wr[i];
        sMean = tot * (1.0f / D_);
    }
    __syncthreads();
    float mean = sMean;
    float d0 = v0 - mean, d1 = v1 - mean, d2 = v2 - mean;
    float qv = d0 * d0 + d1 * d1 + d2 * d2;
#pragma unroll
    for (int mk = 16; mk; mk >>= 1) qv += __shfl_xor_sync(0xffffffffu, qv, mk);
    if ((t & 31) == 0) wr[t >> 5] = qv;
    __syncthreads();
    if (t == 0) {
        float tot = 0;
        for (int i = 0; i < 8; i++) tot += wr[i];
        sRstd = rsqrtf(tot * (1.0f / D_) + 1e-5f);
    }
    __syncthreads();
    float rstd = sRstd;

    float r0 = d0 * rstd * gamma[t]       + beta[t];
    float r1 = d1 * rstd * gamma[t + 256] + beta[t + 256];
    float r2 = d2 * rstd * gamma[t + 512] + beta[t + 512];

    float* po = out + (size_t)row * D_;
    po[t] = r0; po[t + 256] = r1; po[t + 512] = r2;
    if (DUAL) {
        float* pt = outt + (size_t)row * D_;
        pt[t]       = __uint_as_float(f2tf32(r0));
        pt[t + 256] = __uint_as_float(f2tf32(r1));
        pt[t + 512] = __uint_as_float(f2tf32(r2));
    }
}

// ---------------- launch ----------------
extern "C" void kernel_launch(void* const* d_in, const int* in_sizes, int n_in,
                              void* d_out, int out_size)
{
    const float* src = (const float*)d_in[0];
    const float* Wq  = (const float*)d_in[1];
    const float* bq  = (const float*)d_in[2];
    const float* Wk  = (const float*)d_in[3];
    const float* bk  = (const float*)d_in[4];
    const float* Wv  = (const float*)d_in[5];
    const float* bv  = (const float*)d_in[6];
    const float* Wo  = (const float*)d_in[7];
    const float* bo  = (const float*)d_in[8];
    const float* g1  = (const float*)d_in[9];
    const float* be1 = (const float*)d_in[10];
    const float* W1  = (const float*)d_in[11];
    const float* bf1 = (const float*)d_in[12];
    const float* W2  = (const float*)d_in[13];
    const float* bf2 = (const float*)d_in[14];
    const float* g2  = (const float*)d_in[15];
    const float* be2 = (const float*)d_in[16];
    float* out = (float*)d_out;

    float *wqkvT, *bqkv, *woT, *w1T, *w2T, *srct, *x1t;
    float *qkv, *attn, *mha, *x1, *ffn1, *ffn2;
    cudaGetSymbolAddress((void**)&wqkvT, g_wqkvT);
    cudaGetSymbolAddress((void**)&bqkv,  g_bqkv);
    cudaGetSymbolAddress((void**)&woT,   g_woT);
    cudaGetSymbolAddress((void**)&w1T,   g_w1T);
    cudaGetSymbolAddress((void**)&w2T,   g_w2T);
    cudaGetSymbolAddress((void**)&srct,  g_srct);
    cudaGetSymbolAddress((void**)&x1t,   g_x1t);
    cudaGetSymbolAddress((void**)&qkv,   g_qkv);
    cudaGetSymbolAddress((void**)&attn,  g_attn);
    cudaGetSymbolAddress((void**)&mha,   g_mha);
    cudaGetSymbolAddress((void**)&x1,    g_x1);
    cudaGetSymbolAddress((void**)&ffn1,  g_ffn1);
    cudaGetSymbolAddress((void**)&ffn2,  g_ffn2);

    cudaFuncSetAttribute(gemm_tc<0,0>, cudaFuncAttributeMaxDynamicSharedMemorySize, GEMM_SMEM);
    cudaFuncSetAttribute(gemm_tc<0,1>, cudaFuncAttributeMaxDynamicSharedMemorySize, GEMM_SMEM);
    cudaFuncSetAttribute(gemm_tc<1,1>, cudaFuncAttributeMaxDynamicSharedMemorySize, GEMM_SMEM);
    cudaFuncSetAttribute(attn_mma_kernel, cudaFuncAttributeMaxDynamicSharedMemorySize, ATT_SMEM);

    dim3 tb(32, 8);

    // 0) operand prep (tf32 rounding + weight transposes)
    cvt_tf32_copy<<<(M_ * D_ / 4 + 255) / 256, 256>>>(src, srct, M_ * D_ / 4);
    pack_qkv_wT<<<dim3(DK_ / 32, D_ / 32, 3 * H_), tb>>>(Wq, Wk, Wv, wqkvT);
    pack_qkv_bias<<<(NQKV_ + 255) / 256, 256>>>(bq, bk, bv);
    transpose_cvt<<<dim3(D_ / 32, D_ / 32), tb>>>(Wo, woT, D_, D_);
    transpose_cvt<<<dim3(F_ / 32, D_ / 32), tb>>>(W1, w1T, D_, F_);
    transpose_cvt<<<dim3(D_ / 32, F_ / 32), tb>>>(W2, w2T, F_, D_);

    // 1) QKV projection: [8192,768] @ [768,2304] -> tf32-rounded qkv
    gemm_tc<0,1><<<dim3(NQKV_ / BNg, M_ / BMg), 256, GEMM_SMEM>>>(srct, wqkvT, bqkv, qkv, M_, NQKV_, D_);

    // 2) fused attention (tf32 mma) -> tf32-rounded attn
    attn_mma_kernel<<<dim3(S_ / AT_BQ, H_, B_), 256, ATT_SMEM>>>(qkv, attn);

    // 3) output projection
    gemm_tc<0,0><<<dim3(D_ / BNg, M_ / BMg), 256, GEMM_SMEM>>>(attn, woT, bo, mha, M_, D_, D_);

    // 4) x1 = LN(src + mha), dual fp32 + tf32
    add_ln_kernel<1><<<M_, 256>>>(src, mha, g1, be1, x1, x1t);

    // 5) FFN1 (+ReLU): [8192,768] @ [768,3072] -> tf32-rounded ffn1
    gemm_tc<1,1><<<dim3(F_ / BNg, M_ / BMg), 256, GEMM_SMEM>>>(x1t, w1T, bf1, ffn1, M_, F_, D_);

    // 6) FFN2: [8192,3072] @ [3072,768]
    gemm_tc<0,0><<<dim3(D_ / BNg, M_ / BMg), 256, GEMM_SMEM>>>(ffn1, w2T, bf2, ffn2, M_, D_, F_);

    // 7) out = LN(x1 + ffn2)
    add_ln_kernel<0><<<M_, 256>>>(x1, ffn2, g2, be2, out, nullptr);
}

// round 7
// speedup vs baseline: 7.3421x; 2.0156x over previous
#include <cuda_runtime.h>
#include <cuda_fp16.h>
#include <math.h>
#include <stdint.h>

// Problem constants
#define B_    4
#define S_    2048
#define D_    768
#define H_    12
#define DK_   64
#define F_    3072
#define M_    (B_*S_)        // 8192 rows
#define NQKV_ (3*D_)         // 2304

// ---------------- scratch (static device globals; no allocation) ----------------
__device__ __half g_wqkvT[NQKV_*D_];   // packed+transposed QKV weights [3*H*DK][D]
__device__ float  g_bqkv[NQKV_];       // packed QKV bias (fp32)
__device__ __half g_woT [D_*D_];       // Wo^T  [D][D]
__device__ __half g_w1T [F_*D_];       // W1^T  [F][D]
__device__ __half g_w2T [D_*F_];       // W2^T  [D][F]
__device__ __half g_srch[M_*D_];       // fp16 source
__device__ __half g_x1h [M_*D_];       // fp16 x1
__device__ __half g_qkvh[M_*NQKV_];    // fp16 qkv (q|k|v)
__device__ __half g_attnh[M_*D_];      // fp16 concat-head attention out
__device__ __half g_ffn1h[M_*F_];      // fp16 relu(ffn1)
__device__ float  g_mha [M_*D_];
__device__ float  g_x1  [M_*D_];
__device__ float  g_ffn2[M_*D_];

// ---------------- helpers ----------------
__device__ __forceinline__ void mma_f16(float* d, const uint32_t* a, const uint32_t* b) {
    asm volatile(
        "mma.sync.aligned.m16n8k16.row.col.f32.f16.f16.f32 "
        "{%0,%1,%2,%3}, {%4,%5,%6,%7}, {%8,%9}, {%0,%1,%2,%3};"
        : "+f"(d[0]), "+f"(d[1]), "+f"(d[2]), "+f"(d[3])
        : "r"(a[0]), "r"(a[1]), "r"(a[2]), "r"(a[3]), "r"(b[0]), "r"(b[1]));
}

__device__ __forceinline__ void ldsm4(uint32_t* r, uint32_t addr) {
    asm volatile("ldmatrix.sync.aligned.m8n8.x4.shared.b16 {%0,%1,%2,%3}, [%4];"
                 : "=r"(r[0]), "=r"(r[1]), "=r"(r[2]), "=r"(r[3]) : "r"(addr));
}

__device__ __forceinline__ void ldsm4t(uint32_t* r, uint32_t addr) {
    asm volatile("ldmatrix.sync.aligned.m8n8.x4.trans.shared.b16 {%0,%1,%2,%3}, [%4];"
                 : "=r"(r[0]), "=r"(r[1]), "=r"(r[2]), "=r"(r[3]) : "r"(addr));
}

__device__ __forceinline__ void cp_async16(uint32_t smem_dst, const void* gmem_src) {
    asm volatile("cp.async.cg.shared.global [%0], [%1], 16;" :: "r"(smem_dst), "l"(gmem_src));
}
#define CP_COMMIT() asm volatile("cp.async.commit_group;")
#define CP_WAIT0()  asm volatile("cp.async.wait_group 0;")
#define CP_WAIT1()  asm volatile("cp.async.wait_group 1;")

__device__ __forceinline__ uint32_t h2u(__half2 h) { return *reinterpret_cast<uint32_t*>(&h); }

// ---------------- prep kernels ----------------
__global__ void cvt_f2h(const float* __restrict__ in, __half* __restrict__ out, int n4)
{
    int i = blockIdx.x * blockDim.x + threadIdx.x;
    if (i < n4) {
        float4 v = *(const float4*)(in + (size_t)i * 4);
        uint2 o;
        o.x = h2u(__floats2half2_rn(v.x, v.y));
        o.y = h2u(__floats2half2_rn(v.z, v.w));
        *(uint2*)(out + (size_t)i * 4) = o;
    }
}

// tiled transpose fp32 -> fp16: in[R][C] -> out[C][R]
__global__ void transpose_h(const float* __restrict__ in, __half* __restrict__ out,
                            int R, int C)
{
    __shared__ float tile[32][33];
    const int c0 = blockIdx.x * 32, r0 = blockIdx.y * 32;
    const int tx = threadIdx.x, ty = threadIdx.y;
#pragma unroll
    for (int i = 0; i < 32; i += 8)
        tile[ty + i][tx] = in[(size_t)(r0 + ty + i) * C + c0 + tx];
    __syncthreads();
#pragma unroll
    for (int i = 0; i < 32; i += 8)
        out[(size_t)(c0 + ty + i) * R + r0 + tx] = __float2half_rn(tile[tx][ty + i]);
}

// QKV weights: [H,D,DK]x3 -> transposed packed [3*H*DK][D] (fp16)
__global__ void pack_qkv_wT(const float* __restrict__ Wq, const float* __restrict__ Wk,
                            const float* __restrict__ Wv, __half* __restrict__ out)
{
    __shared__ float tile[32][33];
    const int z = blockIdx.z;          // 0..35
    const int wh = z / H_, h = z % H_;
    const float* W = ((wh == 0) ? Wq : (wh == 1) ? Wk : Wv) + (size_t)h * D_ * DK_;
    const int d0 = blockIdx.y * 32, k0 = blockIdx.x * 32;
    const int tx = threadIdx.x, ty = threadIdx.y;
#pragma unroll
    for (int i = 0; i < 32; i += 8)
        tile[ty + i][tx] = W[(size_t)(d0 + ty + i) * DK_ + k0 + tx];
    __syncthreads();
    const int orow = wh * D_ + h * DK_ + k0;
#pragma unroll
    for (int i = 0; i < 32; i += 8)
        out[(size_t)(orow + ty + i) * D_ + d0 + tx] = __float2half_rn(tile[tx][ty + i]);
}

__global__ void pack_qkv_bias(const float* __restrict__ bq, const float* __restrict__ bk,
                              const float* __restrict__ bv)
{
    int idx = blockIdx.x * blockDim.x + threadIdx.x;
    if (idx < NQKV_) {
        int wh = idx / D_, jj = idx % D_;
        const float* bsrc = (wh == 0) ? bq : (wh == 1) ? bk : bv;
        g_bqkv[idx] = bsrc[jj];
    }
}

// ---------------- FP16 tensor-core GEMM: ldmatrix + cp.async, 3 stages ----------------
// C[M,N] = A[M,K] @ Bt[N,K]^T + bias. CTA 128x256, BK=64 halves, 8 warps (2x4),
// warp tile 64x64, mma.m16n8k16.
#define BMg 128
#define BNg 256
#define BKg 64
#define STAGES 3
#define A_CHUNKS (BMg*8)                   // 16B chunks per stage
#define B_CHUNKS (BNg*8)
#define STAGE_CHUNKS (A_CHUNKS + B_CHUNKS) // 3072 -> 48KB/stage
#define GEMM_SMEM (STAGES * STAGE_CHUNKS * 16)

template<int RELU, int OUTH>
__global__ __launch_bounds__(256, 1) void gemm_f16(
    const __half* __restrict__ A, const __half* __restrict__ Bt,
    const float* __restrict__ bias, void* __restrict__ Cv,
    int M, int N, int K)
{
    extern __shared__ uint4 smem4[];
    const uint32_t smem_base = (uint32_t)__cvta_generic_to_shared(smem4);

    const int t    = threadIdx.x;
    const int lane = t & 31;
    const int wid  = t >> 5;
    const int wm   = wid & 1;     // 0..1 (64-row slab)
    const int wn   = wid >> 1;    // 0..3 (64-col slab)
    const int rowC = blockIdx.y * BMg;
    const int colC = blockIdx.x * BNg;

    float acc[4][8][4];
#pragma unroll
    for (int i = 0; i < 4; i++)
#pragma unroll
        for (int j = 0; j < 8; j++)
#pragma unroll
            for (int r = 0; r < 4; r++) acc[i][j][r] = 0.f;

    const int ntiles = K / BKg;

    auto load_tile = [&](int stage, int kt) {
        const uint32_t sa = smem_base + stage * (STAGE_CHUNKS * 16);
#pragma unroll
        for (int i = 0; i < 4; i++) {
            int lin = i * 256 + t;
            int m = lin >> 3, c = lin & 7;
            uint32_t dst = sa + (uint32_t)(m * 8 + (c ^ (m & 7))) * 16;
            cp_async16(dst, A + (size_t)(rowC + m) * K + kt * BKg + c * 8);
        }
#pragma unroll
        for (int i = 0; i < 8; i++) {
            int lin = i * 256 + t;
            int n = lin >> 3, c = lin & 7;
            uint32_t dst = sa + (uint32_t)(A_CHUNKS + n * 8 + (c ^ (n & 7))) * 16;
            cp_async16(dst, Bt + (size_t)(colC + n) * K + kt * BKg + c * 8);
        }
        CP_COMMIT();
    };

    load_tile(0, 0);
    load_tile(1, 1);

    const int lr = lane & 15;
    const int hi = lane >> 4;
    const int x7 = lane & 7;
    uint32_t aRowOff[4], bRowOff[4];
#pragma unroll
    for (int mt = 0; mt < 4; mt++)
        aRowOff[mt] = (uint32_t)(wm * 64 + mt * 16 + lr) * 128;
#pragma unroll
    for (int nt2 = 0; nt2 < 4; nt2++)
        bRowOff[nt2] = (uint32_t)(A_CHUNKS * 16) + (uint32_t)(wn * 64 + nt2 * 16 + lr) * 128;

    for (int kt = 0; kt < ntiles; kt++) {
        CP_WAIT1();
        __syncthreads();

        const int nxt = kt + STAGES - 1;
        if (nxt < ntiles) load_tile(nxt % STAGES, nxt);
        else              CP_COMMIT();

        const uint32_t sa = smem_base + (kt % STAGES) * (STAGE_CHUNKS * 16);
#pragma unroll
        for (int kk = 0; kk < 4; kk++) {
            const uint32_t cx = (uint32_t)(((2 * kk + hi) ^ x7) * 16);
            uint32_t a[4][4], bfr[4][4];
#pragma unroll
            for (int mt = 0; mt < 4; mt++)
                ldsm4(a[mt], sa + aRowOff[mt] + cx);
#pragma unroll
            for (int nt2 = 0; nt2 < 4; nt2++)
                ldsm4(bfr[nt2], sa + bRowOff[nt2] + cx);
#pragma unroll
            for (int mt = 0; mt < 4; mt++)
#pragma unroll
                for (int nt = 0; nt < 8; nt++) {
                    uint32_t bb[2];
                    bb[0] = bfr[nt >> 1][(nt & 1)];
                    bb[1] = bfr[nt >> 1][2 + (nt & 1)];
                    mma_f16(acc[mt][nt], a[mt], bb);
                }
        }
    }

    // epilogue
    const int g2 = lane >> 2, q2 = lane & 3;
#pragma unroll
    for (int mt = 0; mt < 4; mt++) {
        const int r0 = rowC + wm * 64 + mt * 16 + g2;
#pragma unroll
        for (int nt = 0; nt < 8; nt++) {
            const int c = colC + wn * 64 + nt * 8 + 2 * q2;
            const float b0v = bias[c], b1v = bias[c + 1];
            float o00 = acc[mt][nt][0] + b0v, o01 = acc[mt][nt][1] + b1v;
            float o10 = acc[mt][nt][2] + b0v, o11 = acc[mt][nt][3] + b1v;
            if (RELU) {
                o00 = fmaxf(o00, 0.f); o01 = fmaxf(o01, 0.f);
                o10 = fmaxf(o10, 0.f); o11 = fmaxf(o11, 0.f);
            }
            if (OUTH) {
                __half* Ch = (__half*)Cv;
                *(uint32_t*)(Ch + (size_t)r0 * N + c)       = h2u(__floats2half2_rn(o00, o01));
                *(uint32_t*)(Ch + (size_t)(r0 + 8) * N + c) = h2u(__floats2half2_rn(o10, o11));
            } else {
                float* Cf = (float*)Cv;
                *(float2*)(Cf + (size_t)r0 * N + c)       = make_float2(o00, o01);
                *(float2*)(Cf + (size_t)(r0 + 8) * N + c) = make_float2(o10, o11);
            }
        }
    }
}

// ---------------- FP16 mma flash attention (register-P, cp.async double buffer) ----------------
// CTA: 128 q-rows, 8 warps (16 rows each), 64-key tiles.
// smem: Q [128][64]h swizzled (16KB) + 2 stages of (K 64x64 + V 64x64) (16KB each).
#define AT_BQ 128
#define AT_BK 64
#define ATQ_BYTES (AT_BQ * 64 * 2)          // 16384
#define ATKV_STAGE (AT_BK * 64 * 2 * 2)     // 16384 (K+V)
#define ATT_SMEM (ATQ_BYTES + 2 * ATKV_STAGE)

__global__ __launch_bounds__(256) void attn_f16_kernel(
    const __half* __restrict__ qkv, __half* __restrict__ out)
{
    extern __shared__ uint4 smemA[];
    const uint32_t sb = (uint32_t)__cvta_generic_to_shared(smemA);

    const int t    = threadIdx.x;
    const int w    = t >> 5;
    const int lane = t & 31;
    const int g    = lane >> 2;
    const int q    = lane & 3;
    const int lr   = lane & 15;
    const int hi   = lane >> 4;
    const int x7   = lane & 7;
    const int qb = blockIdx.x, h = blockIdx.y, b = blockIdx.z;

    const __half* qg = qkv + (size_t)(b * S_ + qb * AT_BQ) * NQKV_ + h * DK_;

    // stage Q tile via cp.async (swizzled)
#pragma unroll
    for (int i = 0; i < 4; i++) {
        int lin = i * 256 + t;
        int row = lin >> 3, c = lin & 7;
        uint32_t dst = sb + (uint32_t)(row * 8 + (c ^ (row & 7))) * 16;
        cp_async16(dst, qg + (size_t)row * NQKV_ + c * 8);
    }
    CP_COMMIT();
    CP_WAIT0();
    __syncthreads();

    // Q fragments -> registers, scaled by 1/sqrt(DK)=0.125 (exact in fp16)
    uint32_t qa[4][4];
    {
        const uint32_t qRowOff = (uint32_t)(w * 16 + lr) * 128;
        const __half2 sc = __float2half2_rn(0.125f);
#pragma unroll
        for (int kb2 = 0; kb2 < 4; kb2++) {
            ldsm4(qa[kb2], sb + qRowOff + (uint32_t)(((2 * kb2 + hi) ^ x7) * 16));
#pragma unroll
            for (int i = 0; i < 4; i++) {
                __half2 v = *reinterpret_cast<__half2*>(&qa[kb2][i]);
                v = __hmul2(v, sc);
                qa[kb2][i] = h2u(v);
            }
        }
    }

    float m0 = -3.0e38f, m1 = -3.0e38f, l0 = 0.f, l1 = 0.f;
    float o[8][4];
#pragma unroll
    for (int nt = 0; nt < 8; nt++)
#pragma unroll
        for (int r = 0; r < 4; r++) o[nt][r] = 0.f;

    const __half* kg = qkv + (size_t)b * S_ * NQKV_ + D_ + h * DK_;

    auto loadKV = [&](int stage, int kb) {
        const uint32_t sbase = sb + ATQ_BYTES + stage * ATKV_STAGE;
        const __half* kr = kg + (size_t)(kb * AT_BK) * NQKV_;
#pragma unroll
        for (int i = 0; i < 2; i++) {
            int lin = i * 256 + t;
            int row = lin >> 3, c = lin & 7;
            uint32_t sw = (uint32_t)(row * 8 + (c ^ (row & 7))) * 16;
            const __half* kp = kr + (size_t)row * NQKV_ + c * 8;
            cp_async16(sbase + sw, kp);
            cp_async16(sbase + (AT_BK * 64 * 2) + sw, kp + D_);
        }
        CP_COMMIT();
    };

    const int NTILES = S_ / AT_BK;   // 32
    int buf = 0;
    loadKV(0, 0);

    for (int kb = 0; kb < NTILES; kb++) {
        const bool more = (kb + 1) < NTILES;
        if (more) loadKV(buf ^ 1, kb + 1);
        if (more) { CP_WAIT1(); } else { CP_WAIT0(); }
        __syncthreads();

        const uint32_t kbase = sb + ATQ_BYTES + buf * ATKV_STAGE;
        const uint32_t vbase = kbase + AT_BK * 64 * 2;

        // S = Q @ K^T
        float s[8][4];
#pragma unroll
        for (int nt = 0; nt < 8; nt++)
#pragma unroll
            for (int r = 0; r < 4; r++) s[nt][r] = 0.f;

#pragma unroll
        for (int nb = 0; nb < 4; nb++) {
            uint32_t kf[4][4];
            const uint32_t kro = (uint32_t)(nb * 16 + lr) * 128;
#pragma unroll
            for (int kb2 = 0; kb2 < 4; kb2++)
                ldsm4(kf[kb2], kbase + kro + (uint32_t)(((2 * kb2 + hi) ^ x7) * 16));
#pragma unroll
            for (int kb2 = 0; kb2 < 4; kb2++) {
                uint32_t b0[2] = { kf[kb2][0], kf[kb2][2] };
                uint32_t b1[2] = { kf[kb2][1], kf[kb2][3] };
                mma_f16(s[2 * nb],     qa[kb2], b0);
                mma_f16(s[2 * nb + 1], qa[kb2], b1);
            }
        }

        // online softmax (rows g / g+8; stats across quad lanes)
        float mx0 = -3.0e38f, mx1 = -3.0e38f;
#pragma unroll
        for (int nt = 0; nt < 8; nt++) {
            mx0 = fmaxf(mx0, fmaxf(s[nt][0], s[nt][1]));
            mx1 = fmaxf(mx1, fmaxf(s[nt][2], s[nt][3]));
        }
        mx0 = fmaxf(mx0, __shfl_xor_sync(0xffffffffu, mx0, 1));
        mx0 = fmaxf(mx0, __shfl_xor_sync(0xffffffffu, mx0, 2));
        mx1 = fmaxf(mx1, __shfl_xor_sync(0xffffffffu, mx1, 1));
        mx1 = fmaxf(mx1, __shfl_xor_sync(0xffffffffu, mx1, 2));

        const float mn0 = fmaxf(m0, mx0), mn1 = fmaxf(m1, mx1);
        const float f0 = __expf(m0 - mn0), f1 = __expf(m1 - mn1);
        m0 = mn0; m1 = mn1;

        float ls0 = 0.f, ls1 = 0.f;
#pragma unroll
        for (int nt = 0; nt < 8; nt++) {
            s[nt][0] = __expf(s[nt][0] - mn0);
            s[nt][1] = __expf(s[nt][1] - mn0);
            s[nt][2] = __expf(s[nt][2] - mn1);
            s[nt][3] = __expf(s[nt][3] - mn1);
            ls0 += s[nt][0] + s[nt][1];
            ls1 += s[nt][2] + s[nt][3];
        }
        ls0 += __shfl_xor_sync(0xffffffffu, ls0, 1);
        ls0 += __shfl_xor_sync(0xffffffffu, ls0, 2);
        ls1 += __shfl_xor_sync(0xffffffffu, ls1, 1);
        ls1 += __shfl_xor_sync(0xffffffffu, ls1, 2);
        l0 = l0 * f0 + ls0;
        l1 = l1 * f1 + ls1;

        // P fragments directly in registers (S-frag layout == A-frag layout)
        uint32_t pa[4][4];
#pragma unroll
        for (int kb2 = 0; kb2 < 4; kb2++) {
            pa[kb2][0] = h2u(__floats2half2_rn(s[2 * kb2][0],     s[2 * kb2][1]));
            pa[kb2][1] = h2u(__floats2half2_rn(s[2 * kb2][2],     s[2 * kb2][3]));
            pa[kb2][2] = h2u(__floats2half2_rn(s[2 * kb2 + 1][0], s[2 * kb2 + 1][1]));
            pa[kb2][3] = h2u(__floats2half2_rn(s[2 * kb2 + 1][2], s[2 * kb2 + 1][3]));
        }

        // rescale O accumulators
#pragma unroll
        for (int nt = 0; nt < 8; nt++) {
            o[nt][0] *= f0; o[nt][1] *= f0;
            o[nt][2] *= f1; o[nt][3] *= f1;
        }

        // O += P @ V  (V via ldmatrix.trans)
#pragma unroll
        for (int nb2 = 0; nb2 < 4; nb2++) {
            const uint32_t cxv = (uint32_t)(((2 * nb2 + hi) ^ x7) * 16);
#pragma unroll
            for (int kb2 = 0; kb2 < 4; kb2++) {
                uint32_t vf[4];
                ldsm4t(vf, vbase + (uint32_t)(kb2 * 16 + lr) * 128 + cxv);
                uint32_t b0[2] = { vf[0], vf[1] };
                uint32_t b1[2] = { vf[2], vf[3] };
                mma_f16(o[2 * nb2],     pa[kb2], b0);
                mma_f16(o[2 * nb2 + 1], pa[kb2], b1);
            }
        }

        __syncthreads();
        buf ^= 1;
    }

    // epilogue: normalize, write fp16 concat-head output
    const float i0 = 1.0f / l0, i1 = 1.0f / l1;
    __half* op = out + (size_t)(b * S_ + qb * AT_BQ + w * 16) * D_ + h * DK_;
#pragma unroll
    for (int nt = 0; nt < 8; nt++) {
        const int c = nt * 8 + 2 * q;
        *(uint32_t*)(op + (size_t)g * D_ + c) =
            h2u(__floats2half2_rn(o[nt][0] * i0, o[nt][1] * i0));
        *(uint32_t*)(op + (size_t)(g + 8) * D_ + c) =
            h2u(__floats2half2_rn(o[nt][2] * i1, o[nt][3] * i1));
    }
}

// ---------------- fused residual-add + LayerNorm (optionally dual fp32+fp16 out) ----------------
template<int DUAL>
__global__ __launch_bounds__(256) void add_ln_kernel(
    const float* __restrict__ A, const float* __restrict__ Bv,
    const float* __restrict__ gamma, const float* __restrict__ beta,
    float* __restrict__ out, __half* __restrict__ outh)
{
    const int row = blockIdx.x;
    const int t   = threadIdx.x;
    __shared__ float wr[8];
    __shared__ float sMean, sRstd;

    const float* pa = A  + (size_t)row * D_;
    const float* pb = Bv + (size_t)row * D_;

    float v0 = pa[t]       + pb[t];
    float v1 = pa[t + 256] + pb[t + 256];
    float v2 = pa[t + 512] + pb[t + 512];

    float s = v0 + v1 + v2;
#pragma unroll
    for (int mk = 16; mk; mk >>= 1) s += __shfl_xor_sync(0xffffffffu, s, mk);
    if ((t & 31) == 0) wr[t >> 5] = s;
    __syncthreads();
    if (t == 0) {
        float tot = 0;
        for (int i = 0; i < 8; i++) tot += wr[i];
        sMean = tot * (1.0f / D_);
    }
    __syncthreads();
    float mean = sMean;
    float d0 = v0 - mean, d1 = v1 - mean, d2 = v2 - mean;
    float qv = d0 * d0 + d1 * d1 + d2 * d2;
#pragma unroll
    for (int mk = 16; mk; mk >>= 1) qv += __shfl_xor_sync(0xffffffffu, qv, mk);
    if ((t & 31) == 0) wr[t >> 5] = qv;
    __syncthreads();
    if (t == 0) {
        float tot = 0;
        for (int i = 0; i < 8; i++) tot += wr[i];
        sRstd = rsqrtf(tot * (1.0f / D_) + 1e-5f);
    }
    __syncthreads();
    float rstd = sRstd;

    float r0 = d0 * rstd * gamma[t]       + beta[t];
    float r1 = d1 * rstd * gamma[t + 256] + beta[t + 256];
    float r2 = d2 * rstd * gamma[t + 512] + beta[t + 512];

    float* po = out + (size_t)row * D_;
    po[t] = r0; po[t + 256] = r1; po[t + 512] = r2;
    if (DUAL) {
        __half* ph = outh + (size_t)row * D_;
        ph[t]       = __float2half_rn(r0);
        ph[t + 256] = __float2half_rn(r1);
        ph[t + 512] = __float2half_rn(r2);
    }
}

// ---------------- launch ----------------
extern "C" void kernel_launch(void* const* d_in, const int* in_sizes, int n_in,
                              void* d_out, int out_size)
{
    const float* src = (const float*)d_in[0];
    const float* Wq  = (const float*)d_in[1];
    const float* bq  = (const float*)d_in[2];
    const float* Wk  = (const float*)d_in[3];
    const float* bk  = (const float*)d_in[4];
    const float* Wv  = (const float*)d_in[5];
    const float* bv  = (const float*)d_in[6];
    const float* Wo  = (const float*)d_in[7];
    const float* bo  = (const float*)d_in[8];
    const float* g1  = (const float*)d_in[9];
    const float* be1 = (const float*)d_in[10];
    const float* W1  = (const float*)d_in[11];
    const float* bf1 = (const float*)d_in[12];
    const float* W2  = (const float*)d_in[13];
    const float* bf2 = (const float*)d_in[14];
    const float* g2  = (const float*)d_in[15];
    const float* be2 = (const float*)d_in[16];
    float* out = (float*)d_out;

    __half *wqkvT, *woT, *w1T, *w2T, *srch, *x1h, *qkvh, *attnh, *ffn1h;
    float *bqkv, *mha, *x1, *ffn2;
    cudaGetSymbolAddress((void**)&wqkvT, g_wqkvT);
    cudaGetSymbolAddress((void**)&bqkv,  g_bqkv);
    cudaGetSymbolAddress((void**)&woT,   g_woT);
    cudaGetSymbolAddress((void**)&w1T,   g_w1T);
    cudaGetSymbolAddress((void**)&w2T,   g_w2T);
    cudaGetSymbolAddress((void**)&srch,  g_srch);
    cudaGetSymbolAddress((void**)&x1h,   g_x1h);
    cudaGetSymbolAddress((void**)&qkvh,  g_qkvh);
    cudaGetSymbolAddress((void**)&attnh, g_attnh);
    cudaGetSymbolAddress((void**)&ffn1h, g_ffn1h);
    cudaGetSymbolAddress((void**)&mha,   g_mha);
    cudaGetSymbolAddress((void**)&x1,    g_x1);
    cudaGetSymbolAddress((void**)&ffn2,  g_ffn2);

    cudaFuncSetAttribute(gemm_f16<0,0>, cudaFuncAttributeMaxDynamicSharedMemorySize, GEMM_SMEM);
    cudaFuncSetAttribute(gemm_f16<0,1>, cudaFuncAttributeMaxDynamicSharedMemorySize, GEMM_SMEM);
    cudaFuncSetAttribute(gemm_f16<1,1>, cudaFuncAttributeMaxDynamicSharedMemorySize, GEMM_SMEM);
    cudaFuncSetAttribute(attn_f16_kernel, cudaFuncAttributeMaxDynamicSharedMemorySize, ATT_SMEM);

    dim3 tb(32, 8);

    // 0) operand prep
    cvt_f2h<<<(M_ * D_ / 4 + 255) / 256, 256>>>(src, srch, M_ * D_ / 4);
    pack_qkv_wT<<<dim3(DK_ / 32, D_ / 32, 3 * H_), tb>>>(Wq, Wk, Wv, wqkvT);
    pack_qkv_bias<<<(NQKV_ + 255) / 256, 256>>>(bq, bk, bv);
    transpose_h<<<dim3(D_ / 32, D_ / 32), tb>>>(Wo, woT, D_, D_);
    transpose_h<<<dim3(F_ / 32, D_ / 32), tb>>>(W1, w1T, D_, F_);
    transpose_h<<<dim3(D_ / 32, F_ / 32), tb>>>(W2, w2T, F_, D_);

    // 1) QKV projection -> fp16 qkv
    gemm_f16<0,1><<<dim3(NQKV_ / BNg, M_ / BMg), 256, GEMM_SMEM>>>(srch, wqkvT, bqkv, qkvh, M_, NQKV_, D_);

    // 2) fused attention -> fp16 attn
    attn_f16_kernel<<<dim3(S_ / AT_BQ, H_, B_), 256, ATT_SMEM>>>(qkvh, attnh);

    // 3) output projection -> fp32 mha
    gemm_f16<0,0><<<dim3(D_ / BNg, M_ / BMg), 256, GEMM_SMEM>>>(attnh, woT, bo, mha, M_, D_, D_);

    // 4) x1 = LN(src + mha), dual fp32 + fp16
    add_ln_kernel<1><<<M_, 256>>>(src, mha, g1, be1, x1, x1h);

    // 5) FFN1 (+ReLU) -> fp16 ffn1
    gemm_f16<1,1><<<dim3(F_ / BNg, M_ / BMg), 256, GEMM_SMEM>>>(x1h, w1T, bf1, ffn1h, M_, F_, D_);

    // 6) FFN2 -> fp32 ffn2
    gemm_f16<0,0><<<dim3(D_ / BNg, M_ / BMg), 256, GEMM_SMEM>>>(ffn1h, w2T, bf2, ffn2, M_, D_, F_);

    // 7) out = LN(x1 + ffn2)
    add_ln_kernel<0><<<M_, 256>>>(x1, ffn2, g2, be2, out, nullptr);
}

// round 9
// speedup vs baseline: 7.4075x; 1.0089x over previous
#include <cuda_runtime.h>
#include <cuda_fp16.h>
#include <math.h>
#include <stdint.h>

// Problem constants
#define B_    4
#define S_    2048
#define D_    768
#define H_    12
#define DK_   64
#define F_    3072
#define M_    (B_*S_)        // 8192 rows
#define NQKV_ (3*D_)         // 2304

// ---------------- scratch (static device globals; no allocation) ----------------
__device__ __half g_wqkvT[NQKV_*D_];   // packed+transposed QKV weights [3*H*DK][D]
__device__ float  g_bqkv[NQKV_];       // packed QKV bias (fp32)
__device__ __half g_woT [D_*D_];       // Wo^T  [D][D]
__device__ __half g_w1T [F_*D_];       // W1^T  [F][D]
__device__ __half g_w2T [D_*F_];       // W2^T  [D][F]
__device__ __half g_srch[M_*D_];       // fp16 source
__device__ __half g_x1h [M_*D_];       // fp16 x1
__device__ __half g_qkvh[M_*NQKV_];    // fp16 qkv (q|k|v)
__device__ __half g_attnh[M_*D_];      // fp16 concat-head attention out
__device__ __half g_ffn1h[M_*F_];      // fp16 relu(ffn1)
__device__ float  g_mha [M_*D_];
__device__ float  g_x1  [M_*D_];
__device__ float  g_ffn2[M_*D_];

// ---------------- helpers ----------------
__device__ __forceinline__ void mma_f16(float* d, const uint32_t* a, const uint32_t* b) {
    asm volatile(
        "mma.sync.aligned.m16n8k16.row.col.f32.f16.f16.f32 "
        "{%0,%1,%2,%3}, {%4,%5,%6,%7}, {%8,%9}, {%0,%1,%2,%3};"
        : "+f"(d[0]), "+f"(d[1]), "+f"(d[2]), "+f"(d[3])
        : "r"(a[0]), "r"(a[1]), "r"(a[2]), "r"(a[3]), "r"(b[0]), "r"(b[1]));
}

__device__ __forceinline__ void ldsm4(uint32_t* r, uint32_t addr) {
    asm volatile("ldmatrix.sync.aligned.m8n8.x4.shared.b16 {%0,%1,%2,%3}, [%4];"
                 : "=r"(r[0]), "=r"(r[1]), "=r"(r[2]), "=r"(r[3]) : "r"(addr));
}

__device__ __forceinline__ void ldsm4t(uint32_t* r, uint32_t addr) {
    asm volatile("ldmatrix.sync.aligned.m8n8.x4.trans.shared.b16 {%0,%1,%2,%3}, [%4];"
                 : "=r"(r[0]), "=r"(r[1]), "=r"(r[2]), "=r"(r[3]) : "r"(addr));
}

__device__ __forceinline__ void cp_async16(uint32_t smem_dst, const void* gmem_src) {
    asm volatile("cp.async.cg.shared.global [%0], [%1], 16;" :: "r"(smem_dst), "l"(gmem_src));
}
#define CP_COMMIT() asm volatile("cp.async.commit_group;")
#define CP_WAIT0()  asm volatile("cp.async.wait_group 0;")
#define CP_WAIT1()  asm volatile("cp.async.wait_group 1;")

__device__ __forceinline__ uint32_t h2u(__half2 h) { return *reinterpret_cast<uint32_t*>(&h); }

// ---------------- prep kernels ----------------
__global__ void cvt_f2h(const float* __restrict__ in, __half* __restrict__ out, int n4)
{
    int i = blockIdx.x * blockDim.x + threadIdx.x;
    if (i < n4) {
        float4 v = *(const float4*)(in + (size_t)i * 4);
        uint2 o;
        o.x = h2u(__floats2half2_rn(v.x, v.y));
        o.y = h2u(__floats2half2_rn(v.z, v.w));
        *(uint2*)(out + (size_t)i * 4) = o;
    }
}

// tiled transpose fp32 -> fp16: in[R][C] -> out[C][R]
__global__ void transpose_h(const float* __restrict__ in, __half* __restrict__ out,
                            int R, int C)
{
    __shared__ float tile[32][33];
    const int c0 = blockIdx.x * 32, r0 = blockIdx.y * 32;
    const int tx = threadIdx.x, ty = threadIdx.y;
#pragma unroll
    for (int i = 0; i < 32; i += 8)
        tile[ty + i][tx] = in[(size_t)(r0 + ty + i) * C + c0 + tx];
    __syncthreads();
#pragma unroll
    for (int i = 0; i < 32; i += 8)
        out[(size_t)(c0 + ty + i) * R + r0 + tx] = __float2half_rn(tile[tx][ty + i]);
}

// QKV weights: [H,D,DK]x3 -> transposed packed [3*H*DK][D] (fp16)
__global__ void pack_qkv_wT(const float* __restrict__ Wq, const float* __restrict__ Wk,
                            const float* __restrict__ Wv, __half* __restrict__ out)
{
    __shared__ float tile[32][33];
    const int z = blockIdx.z;          // 0..35
    const int wh = z / H_, h = z % H_;
    const float* W = ((wh == 0) ? Wq : (wh == 1) ? Wk : Wv) + (size_t)h * D_ * DK_;
    const int d0 = blockIdx.y * 32, k0 = blockIdx.x * 32;
    const int tx = threadIdx.x, ty = threadIdx.y;
#pragma unroll
    for (int i = 0; i < 32; i += 8)
        tile[ty + i][tx] = W[(size_t)(d0 + ty + i) * DK_ + k0 + tx];
    __syncthreads();
    const int orow = wh * D_ + h * DK_ + k0;
#pragma unroll
    for (int i = 0; i < 32; i += 8)
        out[(size_t)(orow + ty + i) * D_ + d0 + tx] = __float2half_rn(tile[tx][ty + i]);
}

__global__ void pack_qkv_bias(const float* __restrict__ bq, const float* __restrict__ bk,
                              const float* __restrict__ bv)
{
    int idx = blockIdx.x * blockDim.x + threadIdx.x;
    if (idx < NQKV_) {
        int wh = idx / D_, jj = idx % D_;
        const float* bsrc = (wh == 0) ? bq : (wh == 1) ? bk : bv;
        g_bqkv[idx] = bsrc[jj];
    }
}

// ---------------- FP16 tensor-core GEMM: ldmatrix + cp.async, 3 stages ----------------
// C[M,N] = A[M,K] @ Bt[N,K]^T + bias. CTA 128x256, BK=64 halves, 8 warps (2x4),
// warp tile 64x64, mma.m16n8k16, fragment double-buffering across kk steps.
#define BMg 128
#define BNg 256
#define BKg 64
#define STAGES 3
#define A_CHUNKS (BMg*8)                   // 16B chunks per stage
#define B_CHUNKS (BNg*8)
#define STAGE_CHUNKS (A_CHUNKS + B_CHUNKS) // 3072 -> 48KB/stage
#define GEMM_SMEM (STAGES * STAGE_CHUNKS * 16)

template<int RELU, int OUTH>
__global__ __launch_bounds__(256, 1) void gemm_f16(
    const __half* __restrict__ A, const __half* __restrict__ Bt,
    const float* __restrict__ bias, void* __restrict__ Cv,
    int M, int N, int K)
{
    extern __shared__ uint4 smem4[];
    const uint32_t smem_base = (uint32_t)__cvta_generic_to_shared(smem4);

    const int t    = threadIdx.x;
    const int lane = t & 31;
    const int wid  = t >> 5;
    const int wm   = wid & 1;     // 0..1 (64-row slab)
    const int wn   = wid >> 1;    // 0..3 (64-col slab)
    const int rowC = blockIdx.y * BMg;
    const int colC = blockIdx.x * BNg;

    float acc[4][8][4];
#pragma unroll
    for (int i = 0; i < 4; i++)
#pragma unroll
        for (int j = 0; j < 8; j++)
#pragma unroll
            for (int r = 0; r < 4; r++) acc[i][j][r] = 0.f;

    const int ntiles = K / BKg;

    auto load_tile = [&](int stage, int kt) {
        const uint32_t sa = smem_base + stage * (STAGE_CHUNKS * 16);
#pragma unroll
        for (int i = 0; i < 4; i++) {
            int lin = i * 256 + t;
            int m = lin >> 3, c = lin & 7;
            uint32_t dst = sa + (uint32_t)(m * 8 + (c ^ (m & 7))) * 16;
            cp_async16(dst, A + (size_t)(rowC + m) * K + kt * BKg + c * 8);
        }
#pragma unroll
        for (int i = 0; i < 8; i++) {
            int lin = i * 256 + t;
            int n = lin >> 3, c = lin & 7;
            uint32_t dst = sa + (uint32_t)(A_CHUNKS + n * 8 + (c ^ (n & 7))) * 16;
            cp_async16(dst, Bt + (size_t)(colC + n) * K + kt * BKg + c * 8);
        }
        CP_COMMIT();
    };

    load_tile(0, 0);
    load_tile(1, 1);

    const int lr = lane & 15;
    const int hi = lane >> 4;
    const int x7 = lane & 7;
    uint32_t aRowOff[4], bRowOff[4];
#pragma unroll
    for (int mt = 0; mt < 4; mt++)
        aRowOff[mt] = (uint32_t)(wm * 64 + mt * 16 + lr) * 128;
#pragma unroll
    for (int nt2 = 0; nt2 < 4; nt2++)
        bRowOff[nt2] = (uint32_t)(A_CHUNKS * 16) + (uint32_t)(wn * 64 + nt2 * 16 + lr) * 128;

    uint32_t afr[2][4][4], bfr[2][4][4];

    for (int kt = 0; kt < ntiles; kt++) {
        CP_WAIT1();
        __syncthreads();

        const int nxt = kt + STAGES - 1;
        if (nxt < ntiles) load_tile(nxt % STAGES, nxt);
        else              CP_COMMIT();

        const uint32_t sa = smem_base + (kt % STAGES) * (STAGE_CHUNKS * 16);

        // preload kk=0 fragments
        {
            const uint32_t cx = (uint32_t)((hi ^ x7) * 16);
#pragma unroll
            for (int mt = 0; mt < 4; mt++)
                ldsm4(afr[0][mt], sa + aRowOff[mt] + cx);
#pragma unroll
            for (int nt2 = 0; nt2 < 4; nt2++)
                ldsm4(bfr[0][nt2], sa + bRowOff[nt2] + cx);
        }

#pragma unroll
        for (int kk = 0; kk < 4; kk++) {
            const int cur = kk & 1;
            if (kk < 3) {
                const int nb = cur ^ 1;
                const uint32_t cx = (uint32_t)(((2 * (kk + 1) + hi) ^ x7) * 16);
#pragma unroll
                for (int mt = 0; mt < 4; mt++)
                    ldsm4(afr[nb][mt], sa + aRowOff[mt] + cx);
#pragma unroll
                for (int nt2 = 0; nt2 < 4; nt2++)
                    ldsm4(bfr[nb][nt2], sa + bRowOff[nt2] + cx);
            }
#pragma unroll
            for (int mt = 0; mt < 4; mt++)
#pragma unroll
                for (int nt = 0; nt < 8; nt++) {
                    uint32_t bb[2];
                    bb[0] = bfr[cur][nt >> 1][(nt & 1)];
                    bb[1] = bfr[cur][nt >> 1][2 + (nt & 1)];
                    mma_f16(acc[mt][nt], afr[cur][mt], bb);
                }
        }
    }

    // epilogue
    const int g2 = lane >> 2, q2 = lane & 3;
#pragma unroll
    for (int mt = 0; mt < 4; mt++) {
        const int r0 = rowC + wm * 64 + mt * 16 + g2;
#pragma unroll
        for (int nt = 0; nt < 8; nt++) {
            const int c = colC + wn * 64 + nt * 8 + 2 * q2;
            const float b0v = bias[c], b1v = bias[c + 1];
            float o00 = acc[mt][nt][0] + b0v, o01 = acc[mt][nt][1] + b1v;
            float o10 = acc[mt][nt][2] + b0v, o11 = acc[mt][nt][3] + b1v;
            if (RELU) {
                o00 = fmaxf(o00, 0.f); o01 = fmaxf(o01, 0.f);
                o10 = fmaxf(o10, 0.f); o11 = fmaxf(o11, 0.f);
            }
            if (OUTH) {
                __half* Ch = (__half*)Cv;
                *(uint32_t*)(Ch + (size_t)r0 * N + c)       = h2u(__floats2half2_rn(o00, o01));
                *(uint32_t*)(Ch + (size_t)(r0 + 8) * N + c) = h2u(__floats2half2_rn(o10, o11));
            } else {
                float* Cf = (float*)Cv;
                *(float2*)(Cf + (size_t)r0 * N + c)       = make_float2(o00, o01);
                *(float2*)(Cf + (size_t)(r0 + 8) * N + c) = make_float2(o10, o11);
            }
        }
    }
}

// ---------------- FP16 mma flash attention (register-P, cp.async double buffer) ----------------
#define AT_BQ 128
#define AT_BK 64
#define ATQ_BYTES (AT_BQ * 64 * 2)          // 16384
#define ATKV_STAGE (AT_BK * 64 * 2 * 2)     // 16384 (K+V)
#define ATT_SMEM (ATQ_BYTES + 2 * ATKV_STAGE)

__global__ __launch_bounds__(256) void attn_f16_kernel(
    const __half* __restrict__ qkv, __half* __restrict__ out)
{
    extern __shared__ uint4 smemA[];
    const uint32_t sb = (uint32_t)__cvta_generic_to_shared(smemA);

    const int t    = threadIdx.x;
    const int w    = t >> 5;
    const int lane = t & 31;
    const int g    = lane >> 2;
    const int q    = lane & 3;
    const int lr   = lane & 15;
    const int hi   = lane >> 4;
    const int x7   = lane & 7;
    const int qb = blockIdx.x, h = blockIdx.y, b = blockIdx.z;

    const __half* qg = qkv + (size_t)(b * S_ + qb * AT_BQ) * NQKV_ + h * DK_;

#pragma unroll
    for (int i = 0; i < 4; i++) {
        int lin = i * 256 + t;
        int row = lin >> 3, c = lin & 7;
        uint32_t dst = sb + (uint32_t)(row * 8 + (c ^ (row & 7))) * 16;
        cp_async16(dst, qg + (size_t)row * NQKV_ + c * 8);
    }
    CP_COMMIT();
    CP_WAIT0();
    __syncthreads();

    uint32_t qa[4][4];
    {
        const uint32_t qRowOff = (uint32_t)(w * 16 + lr) * 128;
        const __half2 sc = __float2half2_rn(0.125f);
#pragma unroll
        for (int kb2 = 0; kb2 < 4; kb2++) {
            ldsm4(qa[kb2], sb + qRowOff + (uint32_t)(((2 * kb2 + hi) ^ x7) * 16));
#pragma unroll
            for (int i = 0; i < 4; i++) {
                __half2 v = *reinterpret_cast<__half2*>(&qa[kb2][i]);
                v = __hmul2(v, sc);
                qa[kb2][i] = h2u(v);
            }
        }
    }

    float m0 = -3.0e38f, m1 = -3.0e38f, l0 = 0.f, l1 = 0.f;
    float o[8][4];
#pragma unroll
    for (int nt = 0; nt < 8; nt++)
#pragma unroll
        for (int r = 0; r < 4; r++) o[nt][r] = 0.f;

    const __half* kg = qkv + (size_t)b * S_ * NQKV_ + D_ + h * DK_;

    auto loadKV = [&](int stage, int kb) {
        const uint32_t sbase = sb + ATQ_BYTES + stage * ATKV_STAGE;
        const __half* kr = kg + (size_t)(kb * AT_BK) * NQKV_;
#pragma unroll
        for (int i = 0; i < 2; i++) {
            int lin = i * 256 + t;
            int row = lin >> 3, c = lin & 7;
            uint32_t sw = (uint32_t)(row * 8 + (c ^ (row & 7))) * 16;
            const __half* kp = kr + (size_t)row * NQKV_ + c * 8;
            cp_async16(sbase + sw, kp);
            cp_async16(sbase + (AT_BK * 64 * 2) + sw, kp + D_);
        }
        CP_COMMIT();
    };

    const int NTILES = S_ / AT_BK;   // 32
    int buf = 0;
    loadKV(0, 0);

    for (int kb = 0; kb < NTILES; kb++) {
        const bool more = (kb + 1) < NTILES;
        if (more) loadKV(buf ^ 1, kb + 1);
        if (more) { CP_WAIT1(); } else { CP_WAIT0(); }
        __syncthreads();

        const uint32_t kbase = sb + ATQ_BYTES + buf * ATKV_STAGE;
        const uint32_t vbase = kbase + AT_BK * 64 * 2;

        float s[8][4];
#pragma unroll
        for (int nt = 0; nt < 8; nt++)
#pragma unroll
            for (int r = 0; r < 4; r++) s[nt][r] = 0.f;

#pragma unroll
        for (int nb = 0; nb < 4; nb++) {
            uint32_t kf[4][4];
            const uint32_t kro = (uint32_t)(nb * 16 + lr) * 128;
#pragma unroll
            for (int kb2 = 0; kb2 < 4; kb2++)
                ldsm4(kf[kb2], kbase + kro + (uint32_t)(((2 * kb2 + hi) ^ x7) * 16));
#pragma unroll
            for (int kb2 = 0; kb2 < 4; kb2++) {
                uint32_t b0[2] = { kf[kb2][0], kf[kb2][2] };
                uint32_t b1[2] = { kf[kb2][1], kf[kb2][3] };
                mma_f16(s[2 * nb],     qa[kb2], b0);
                mma_f16(s[2 * nb + 1], qa[kb2], b1);
            }
        }

        float mx0 = -3.0e38f, mx1 = -3.0e38f;
#pragma unroll
        for (int nt = 0; nt < 8; nt++) {
            mx0 = fmaxf(mx0, fmaxf(s[nt][0], s[nt][1]));
            mx1 = fmaxf(mx1, fmaxf(s[nt][2], s[nt][3]));
        }
        mx0 = fmaxf(mx0, __shfl_xor_sync(0xffffffffu, mx0, 1));
        mx0 = fmaxf(mx0, __shfl_xor_sync(0xffffffffu, mx0, 2));
        mx1 = fmaxf(mx1, __shfl_xor_sync(0xffffffffu, mx1, 1));
        mx1 = fmaxf(mx1, __shfl_xor_sync(0xffffffffu, mx1, 2));

        const float mn0 = fmaxf(m0, mx0), mn1 = fmaxf(m1, mx1);
        const float f0 = __expf(m0 - mn0), f1 = __expf(m1 - mn1);
        m0 = mn0; m1 = mn1;

        float ls0 = 0.f, ls1 = 0.f;
#pragma unroll
        for (int nt = 0; nt < 8; nt++) {
            s[nt][0] = __expf(s[nt][0] - mn0);
            s[nt][1] = __expf(s[nt][1] - mn0);
            s[nt][2] = __expf(s[nt][2] - mn1);
            s[nt][3] = __expf(s[nt][3] - mn1);
            ls0 += s[nt][0] + s[nt][1];
            ls1 += s[nt][2] + s[nt][3];
        }
        ls0 += __shfl_xor_sync(0xffffffffu, ls0, 1);
        ls0 += __shfl_xor_sync(0xffffffffu, ls0, 2);
        ls1 += __shfl_xor_sync(0xffffffffu, ls1, 1);
        ls1 += __shfl_xor_sync(0xffffffffu, ls1, 2);
        l0 = l0 * f0 + ls0;
        l1 = l1 * f1 + ls1;

        uint32_t pa[4][4];
#pragma unroll
        for (int kb2 = 0; kb2 < 4; kb2++) {
            pa[kb2][0] = h2u(__floats2half2_rn(s[2 * kb2][0],     s[2 * kb2][1]));
            pa[kb2][1] = h2u(__floats2half2_rn(s[2 * kb2][2],     s[2 * kb2][3]));
            pa[kb2][2] = h2u(__floats2half2_rn(s[2 * kb2 + 1][0], s[2 * kb2 + 1][1]));
            pa[kb2][3] = h2u(__floats2half2_rn(s[2 * kb2 + 1][2], s[2 * kb2 + 1][3]));
        }

#pragma unroll
        for (int nt = 0; nt < 8; nt++) {
            o[nt][0] *= f0; o[nt][1] *= f0;
            o[nt][2] *= f1; o[nt][3] *= f1;
        }

#pragma unroll
        for (int nb2 = 0; nb2 < 4; nb2++) {
            const uint32_t cxv = (uint32_t)(((2 * nb2 + hi) ^ x7) * 16);
#pragma unroll
            for (int kb2 = 0; kb2 < 4; kb2++) {
                uint32_t vf[4];
                ldsm4t(vf, vbase + (uint32_t)(kb2 * 16 + lr) * 128 + cxv);
                uint32_t b0[2] = { vf[0], vf[1] };
                uint32_t b1[2] = { vf[2], vf[3] };
                mma_f16(o[2 * nb2],     pa[kb2], b0);
                mma_f16(o[2 * nb2 + 1], pa[kb2], b1);
            }
        }

        __syncthreads();
        buf ^= 1;
    }

    const float i0 = 1.0f / l0, i1 = 1.0f / l1;
    __half* op = out + (size_t)(b * S_ + qb * AT_BQ + w * 16) * D_ + h * DK_;
#pragma unroll
    for (int nt = 0; nt < 8; nt++) {
        const int c = nt * 8 + 2 * q;
        *(uint32_t*)(op + (size_t)g * D_ + c) =
            h2u(__floats2half2_rn(o[nt][0] * i0, o[nt][1] * i0));
        *(uint32_t*)(op + (size_t)(g + 8) * D_ + c) =
            h2u(__floats2half2_rn(o[nt][2] * i1, o[nt][3] * i1));
    }
}

// ---------------- fused residual-add + LayerNorm: warp-per-row, float4, shuffle-only ----------------
template<int DUAL>
__global__ __launch_bounds__(256) void add_ln_kernel(
    const float* __restrict__ A, const float* __restrict__ Bv,
    const float* __restrict__ gamma, const float* __restrict__ beta,
    float* __restrict__ out, __half* __restrict__ outh)
{
    const int w    = threadIdx.x >> 5;
    const int lane = threadIdx.x & 31;
    const int row  = blockIdx.x * 8 + w;

    const float* pa = A  + (size_t)row * D_;
    const float* pb = Bv + (size_t)row * D_;

    float4 v[6];
    float s = 0.f;
#pragma unroll
    for (int i = 0; i < 6; i++) {
        const int off = (i * 32 + lane) * 4;
        float4 a4 = *(const float4*)(pa + off);
        float4 b4 = *(const float4*)(pb + off);
        v[i].x = a4.x + b4.x; v[i].y = a4.y + b4.y;
        v[i].z = a4.z + b4.z; v[i].w = a4.w + b4.w;
        s += v[i].x + v[i].y + v[i].z + v[i].w;
    }
#pragma unroll
    for (int mk = 16; mk; mk >>= 1) s += __shfl_xor_sync(0xffffffffu, s, mk);
    const float mean = s * (1.0f / D_);

    float qv = 0.f;
#pragma unroll
    for (int i = 0; i < 6; i++) {
        v[i].x -= mean; v[i].y -= mean; v[i].z -= mean; v[i].w -= mean;
        qv += v[i].x * v[i].x + v[i].y * v[i].y + v[i].z * v[i].z + v[i].w * v[i].w;
    }
#pragma unroll
    for (int mk = 16; mk; mk >>= 1) qv += __shfl_xor_sync(0xffffffffu, qv, mk);
    const float rstd = rsqrtf(qv * (1.0f / D_) + 1e-5f);

    float* po = out + (size_t)row * D_;
    __half* ph = DUAL ? (outh + (size_t)row * D_) : nullptr;
#pragma unroll
    for (int i = 0; i < 6; i++) {
        const int off = (i * 32 + lane) * 4;
        float4 g4 = *(const float4*)(gamma + off);
        float4 e4 = *(const float4*)(beta + off);
        float4 r;
        r.x = v[i].x * rstd * g4.x + e4.x;
        r.y = v[i].y * rstd * g4.y + e4.y;
        r.z = v[i].z * rstd * g4.z + e4.z;
        r.w = v[i].w * rstd * g4.w + e4.w;
        *(float4*)(po + off) = r;
        if (DUAL) {
            uint2 hh;
            hh.x = h2u(__floats2half2_rn(r.x, r.y));
            hh.y = h2u(__floats2half2_rn(r.z, r.w));
            *(uint2*)(ph + off) = hh;
        }
    }
}

// ---------------- launch ----------------
extern "C" void kernel_launch(void* const* d_in, const int* in_sizes, int n_in,
                              void* d_out, int out_size)
{
    const float* src = (const float*)d_in[0];
    const float* Wq  = (const float*)d_in[1];
    const float* bq  = (const float*)d_in[2];
    const float* Wk  = (const float*)d_in[3];
    const float* bk  = (const float*)d_in[4];
    const float* Wv  = (const float*)d_in[5];
    const float* bv  = (const float*)d_in[6];
    const float* Wo  = (const float*)d_in[7];
    const float* bo  = (const float*)d_in[8];
    const float* g1  = (const float*)d_in[9];
    const float* be1 = (const float*)d_in[10];
    const float* W1  = (const float*)d_in[11];
    const float* bf1 = (const float*)d_in[12];
    const float* W2  = (const float*)d_in[13];
    const float* bf2 = (const float*)d_in[14];
    const float* g2  = (const float*)d_in[15];
    const float* be2 = (const float*)d_in[16];
    float* out = (float*)d_out;

    __half *wqkvT, *woT, *w1T, *w2T, *srch, *x1h, *qkvh, *attnh, *ffn1h;
    float *bqkv, *mha, *x1, *ffn2;
    cudaGetSymbolAddress((void**)&wqkvT, g_wqkvT);
    cudaGetSymbolAddress((void**)&bqkv,  g_bqkv);
    cudaGetSymbolAddress((void**)&woT,   g_woT);
    cudaGetSymbolAddress((void**)&w1T,   g_w1T);
    cudaGetSymbolAddress((void**)&w2T,   g_w2T);
    cudaGetSymbolAddress((void**)&srch,  g_srch);
    cudaGetSymbolAddress((void**)&x1h,   g_x1h);
    cudaGetSymbolAddress((void**)&qkvh,  g_qkvh);
    cudaGetSymbolAddress((void**)&attnh, g_attnh);
    cudaGetSymbolAddress((void**)&ffn1h, g_ffn1h);
    cudaGetSymbolAddress((void**)&mha,   g_mha);
    cudaGetSymbolAddress((void**)&x1,    g_x1);
    cudaGetSymbolAddress((void**)&ffn2,  g_ffn2);

    cudaFuncSetAttribute(gemm_f16<0,0>, cudaFuncAttributeMaxDynamicSharedMemorySize, GEMM_SMEM);
    cudaFuncSetAttribute(gemm_f16<0,1>, cudaFuncAttributeMaxDynamicSharedMemorySize, GEMM_SMEM);
    cudaFuncSetAttribute(gemm_f16<1,1>, cudaFuncAttributeMaxDynamicSharedMemorySize, GEMM_SMEM);
    cudaFuncSetAttribute(attn_f16_kernel, cudaFuncAttributeMaxDynamicSharedMemorySize, ATT_SMEM);

    dim3 tb(32, 8);

    // 0) operand prep
    cvt_f2h<<<(M_ * D_ / 4 + 255) / 256, 256>>>(src, srch, M_ * D_ / 4);
    pack_qkv_wT<<<dim3(DK_ / 32, D_ / 32, 3 * H_), tb>>>(Wq, Wk, Wv, wqkvT);
    pack_qkv_bias<<<(NQKV_ + 255) / 256, 256>>>(bq, bk, bv);
    transpose_h<<<dim3(D_ / 32, D_ / 32), tb>>>(Wo, woT, D_, D_);
    transpose_h<<<dim3(F_ / 32, D_ / 32), tb>>>(W1, w1T, D_, F_);
    transpose_h<<<dim3(D_ / 32, F_ / 32), tb>>>(W2, w2T, F_, D_);

    // 1) QKV projection -> fp16 qkv
    gemm_f16<0,1><<<dim3(NQKV_ / BNg, M_ / BMg), 256, GEMM_SMEM>>>(srch, wqkvT, bqkv, qkvh, M_, NQKV_, D_);

    // 2) fused attention -> fp16 attn
    attn_f16_kernel<<<dim3(S_ / AT_BQ, H_, B_), 256, ATT_SMEM>>>(qkvh, attnh);

    // 3) output projection -> fp32 mha
    gemm_f16<0,0><<<dim3(D_ / BNg, M_ / BMg), 256, GEMM_SMEM>>>(attnh, woT, bo, mha, M_, D_, D_);

    // 4) x1 = LN(src + mha), dual fp32 + fp16
    add_ln_kernel<1><<<M_ / 8, 256>>>(src, mha, g1, be1, x1, x1h);

    // 5) FFN1 (+ReLU) -> fp16 ffn1
    gemm_f16<1,1><<<dim3(F_ / BNg, M_ / BMg), 256, GEMM_SMEM>>>(x1h, w1T, bf1, ffn1h, M_, F_, D_);

    // 6) FFN2 -> fp32 ffn2
    gemm_f16<0,0><<<dim3(D_ / BNg, M_ / BMg), 256, GEMM_SMEM>>>(ffn1h, w2T, bf2, ffn2, M_, D_, F_);

    // 7) out = LN(x1 + ffn2)
    add_ln_kernel<0><<<M_ / 8, 256>>>(x1, ffn2, g2, be2, out, nullptr);
}

// round 11
// speedup vs baseline: 7.9728x; 1.0763x over previous
#include <cuda_runtime.h>
#include <cuda_fp16.h>
#include <math.h>
#include <stdint.h>

// Problem constants
#define B_    4
#define S_    2048
#define D_    768
#define H_    12
#define DK_   64
#define F_    3072
#define M_    (B_*S_)        // 8192 rows
#define NQKV_ (3*D_)         // 2304

// ---------------- scratch (static device globals; no allocation) ----------------
__device__ __half g_wqkvT[NQKV_*D_];   // packed+transposed QKV weights [3*H*DK][D]
__device__ float  g_bqkv[NQKV_];       // packed QKV bias (fp32)
__device__ __half g_woT [D_*D_];       // Wo^T  [D][D]
__device__ __half g_w1T [F_*D_];       // W1^T  [F][D]
__device__ __half g_w2T [D_*F_];       // W2^T  [D][F]
__device__ __half g_srch[M_*D_];       // fp16 source
__device__ __half g_x1h [M_*D_];       // fp16 x1
__device__ __half g_qkvh[M_*NQKV_];    // fp16 qkv (q|k|v)
__device__ __half g_attnh[M_*D_];      // fp16 concat-head attention out
__device__ __half g_ffn1h[M_*F_];      // fp16 relu(ffn1)
__device__ float  g_mha [M_*D_];
__device__ float  g_x1  [M_*D_];
__device__ float  g_ffn2[M_*D_];

// ---------------- helpers ----------------
__device__ __forceinline__ void mma_f16(float* d, const uint32_t* a, const uint32_t* b) {
    asm volatile(
        "mma.sync.aligned.m16n8k16.row.col.f32.f16.f16.f32 "
        "{%0,%1,%2,%3}, {%4,%5,%6,%7}, {%8,%9}, {%0,%1,%2,%3};"
        : "+f"(d[0]), "+f"(d[1]), "+f"(d[2]), "+f"(d[3])
        : "r"(a[0]), "r"(a[1]), "r"(a[2]), "r"(a[3]), "r"(b[0]), "r"(b[1]));
}

__device__ __forceinline__ void ldsm4(uint32_t* r, uint32_t addr) {
    asm volatile("ldmatrix.sync.aligned.m8n8.x4.shared.b16 {%0,%1,%2,%3}, [%4];"
                 : "=r"(r[0]), "=r"(r[1]), "=r"(r[2]), "=r"(r[3]) : "r"(addr));
}

__device__ __forceinline__ void ldsm4t(uint32_t* r, uint32_t addr) {
    asm volatile("ldmatrix.sync.aligned.m8n8.x4.trans.shared.b16 {%0,%1,%2,%3}, [%4];"
                 : "=r"(r[0]), "=r"(r[1]), "=r"(r[2]), "=r"(r[3]) : "r"(addr));
}

__device__ __forceinline__ void cp_async16(uint32_t smem_dst, const void* gmem_src) {
    asm volatile("cp.async.cg.shared.global [%0], [%1], 16;" :: "r"(smem_dst), "l"(gmem_src));
}
#define CP_COMMIT() asm volatile("cp.async.commit_group;")
#define CP_WAIT0()  asm volatile("cp.async.wait_group 0;")
#define CP_WAIT1()  asm volatile("cp.async.wait_group 1;")

__device__ __forceinline__ uint32_t h2u(__half2 h) { return *reinterpret_cast<uint32_t*>(&h); }

// ---------------- prep kernels ----------------
__global__ void cvt_f2h(const float* __restrict__ in, __half* __restrict__ out, int n4)
{
    int i = blockIdx.x * blockDim.x + threadIdx.x;
    if (i < n4) {
        float4 v = *(const float4*)(in + (size_t)i * 4);
        uint2 o;
        o.x = h2u(__floats2half2_rn(v.x, v.y));
        o.y = h2u(__floats2half2_rn(v.z, v.w));
        *(uint2*)(out + (size_t)i * 4) = o;
    }
}

// tiled transpose fp32 -> fp16: in[R][C] -> out[C][R]
__global__ void transpose_h(const float* __restrict__ in, __half* __restrict__ out,
                            int R, int C)
{
    __shared__ float tile[32][33];
    const int c0 = blockIdx.x * 32, r0 = blockIdx.y * 32;
    const int tx = threadIdx.x, ty = threadIdx.y;
#pragma unroll
    for (int i = 0; i < 32; i += 8)
        tile[ty + i][tx] = in[(size_t)(r0 + ty + i) * C + c0 + tx];
    __syncthreads();
#pragma unroll
    for (int i = 0; i < 32; i += 8)
        out[(size_t)(c0 + ty + i) * R + r0 + tx] = __float2half_rn(tile[tx][ty + i]);
}

// QKV weights: [H,D,DK]x3 -> transposed packed [3*H*DK][D] (fp16)
__global__ void pack_qkv_wT(const float* __restrict__ Wq, const float* __restrict__ Wk,
                            const float* __restrict__ Wv, __half* __restrict__ out)
{
    __shared__ float tile[32][33];
    const int z = blockIdx.z;          // 0..35
    const int wh = z / H_, h = z % H_;
    const float* W = ((wh == 0) ? Wq : (wh == 1) ? Wk : Wv) + (size_t)h * D_ * DK_;
    const int d0 = blockIdx.y * 32, k0 = blockIdx.x * 32;
    const int tx = threadIdx.x, ty = threadIdx.y;
#pragma unroll
    for (int i = 0; i < 32; i += 8)
        tile[ty + i][tx] = W[(size_t)(d0 + ty + i) * DK_ + k0 + tx];
    __syncthreads();
    const int orow = wh * D_ + h * DK_ + k0;
#pragma unroll
    for (int i = 0; i < 32; i += 8)
        out[(size_t)(orow + ty + i) * D_ + d0 + tx] = __float2half_rn(tile[tx][ty + i]);
}

__global__ void pack_qkv_bias(const float* __restrict__ bq, const float* __restrict__ bk,
                              const float* __restrict__ bv)
{
    int idx = blockIdx.x * blockDim.x + threadIdx.x;
    if (idx < NQKV_) {
        int wh = idx / D_, jj = idx % D_;
        const float* bsrc = (wh == 0) ? bq : (wh == 1) ? bk : bv;
        g_bqkv[idx] = bsrc[jj];
    }
}

// ---------------- FP16 tensor-core GEMM: ldmatrix + cp.async, 3 stages ----------------
// C[M,N] = A[M,K] @ Bt[N,K]^T + bias. CTA 128xBN, BK=64 halves, 8 warps (2 x 4),
// warp tile 64x(BN/4), mma.m16n8k16. BN=256 (1 CTA/SM) or BN=128 (2 CTAs/SM).
#define BMg 128
#define BKg 64
#define STAGES 3
#define A_CHUNKS (BMg*8)                   // 16B chunks per stage

constexpr int gemm_smem_bytes(int BN) { return STAGES * (A_CHUNKS + BN * 8) * 16; }

template<int RELU, int OUTH, int BN>
__global__ __launch_bounds__(256, (BN == 128) ? 2 : 1) void gemm_f16(
    const __half* __restrict__ A, const __half* __restrict__ Bt,
    const float* __restrict__ bias, void* __restrict__ Cv,
    int M, int N, int K)
{
    constexpr int B_CHUNKS = BN * 8;
    constexpr int STAGE_CHUNKS = A_CHUNKS + B_CHUNKS;
    constexpr int WN = BN / 4;       // warp tile N (64 or 32)
    constexpr int NT = WN / 8;       // n8 tiles per warp (8 or 4)
    constexpr int NB = WN / 16;      // 16-col ldsm groups (4 or 2)

    extern __shared__ uint4 smem4[];
    const uint32_t smem_base = (uint32_t)__cvta_generic_to_shared(smem4);

    const int t    = threadIdx.x;
    const int lane = t & 31;
    const int wid  = t >> 5;
    const int wm   = wid & 1;     // 0..1 (64-row slab)
    const int wn   = wid >> 1;    // 0..3 (WN-col slab)
    const int rowC = blockIdx.y * BMg;
    const int colC = blockIdx.x * BN;

    float acc[4][NT][4];
#pragma unroll
    for (int i = 0; i < 4; i++)
#pragma unroll
        for (int j = 0; j < NT; j++)
#pragma unroll
            for (int r = 0; r < 4; r++) acc[i][j][r] = 0.f;

    const int ntiles = K / BKg;

    auto load_tile = [&](int stage, int kt) {
        const uint32_t sa = smem_base + stage * (STAGE_CHUNKS * 16);
#pragma unroll
        for (int i = 0; i < 4; i++) {
            int lin = i * 256 + t;
            int m = lin >> 3, c = lin & 7;
            uint32_t dst = sa + (uint32_t)(m * 8 + (c ^ (m & 7))) * 16;
            cp_async16(dst, A + (size_t)(rowC + m) * K + kt * BKg + c * 8);
        }
#pragma unroll
        for (int i = 0; i < B_CHUNKS / 256; i++) {
            int lin = i * 256 + t;
            int n = lin >> 3, c = lin & 7;
            uint32_t dst = sa + (uint32_t)(A_CHUNKS + n * 8 + (c ^ (n & 7))) * 16;
            cp_async16(dst, Bt + (size_t)(colC + n) * K + kt * BKg + c * 8);
        }
        CP_COMMIT();
    };

    load_tile(0, 0);
    load_tile(1, 1);

    const int lr = lane & 15;
    const int hi = lane >> 4;
    const int x7 = lane & 7;
    uint32_t aRowOff[4], bRowOff[NB];
#pragma unroll
    for (int mt = 0; mt < 4; mt++)
        aRowOff[mt] = (uint32_t)(wm * 64 + mt * 16 + lr) * 128;
#pragma unroll
    for (int nb = 0; nb < NB; nb++)
        bRowOff[nb] = (uint32_t)(A_CHUNKS * 16) + (uint32_t)(wn * WN + nb * 16 + lr) * 128;

    for (int kt = 0; kt < ntiles; kt++) {
        CP_WAIT1();
        __syncthreads();

        const int nxt = kt + STAGES - 1;
        if (nxt < ntiles) load_tile(nxt % STAGES, nxt);
        else              CP_COMMIT();

        const uint32_t sa = smem_base + (kt % STAGES) * (STAGE_CHUNKS * 16);
#pragma unroll
        for (int kk = 0; kk < 4; kk++) {
            const uint32_t cx = (uint32_t)(((2 * kk + hi) ^ x7) * 16);
            uint32_t a[4][4], bfr[NB][4];
#pragma unroll
            for (int mt = 0; mt < 4; mt++)
                ldsm4(a[mt], sa + aRowOff[mt] + cx);
#pragma unroll
            for (int nb = 0; nb < NB; nb++)
                ldsm4(bfr[nb], sa + bRowOff[nb] + cx);
#pragma unroll
            for (int mt = 0; mt < 4; mt++)
#pragma unroll
                for (int nt = 0; nt < NT; nt++) {
                    uint32_t bb[2];
                    bb[0] = bfr[nt >> 1][(nt & 1)];
                    bb[1] = bfr[nt >> 1][2 + (nt & 1)];
                    mma_f16(acc[mt][nt], a[mt], bb);
                }
        }
    }

    // epilogue
    const int g2 = lane >> 2, q2 = lane & 3;
#pragma unroll
    for (int mt = 0; mt < 4; mt++) {
        const int r0 = rowC + wm * 64 + mt * 16 + g2;
#pragma unroll
        for (int nt = 0; nt < NT; nt++) {
            const int c = colC + wn * WN + nt * 8 + 2 * q2;
            const float b0v = bias[c], b1v = bias[c + 1];
            float o00 = acc[mt][nt][0] + b0v, o01 = acc[mt][nt][1] + b1v;
            float o10 = acc[mt][nt][2] + b0v, o11 = acc[mt][nt][3] + b1v;
            if (RELU) {
                o00 = fmaxf(o00, 0.f); o01 = fmaxf(o01, 0.f);
                o10 = fmaxf(o10, 0.f); o11 = fmaxf(o11, 0.f);
            }
            if (OUTH) {
                __half* Ch = (__half*)Cv;
                *(uint32_t*)(Ch + (size_t)r0 * N + c)       = h2u(__floats2half2_rn(o00, o01));
                *(uint32_t*)(Ch + (size_t)(r0 + 8) * N + c) = h2u(__floats2half2_rn(o10, o11));
            } else {
                float* Cf = (float*)Cv;
                *(float2*)(Cf + (size_t)r0 * N + c)       = make_float2(o00, o01);
                *(float2*)(Cf + (size_t)(r0 + 8) * N + c) = make_float2(o10, o11);
            }
        }
    }
}

// ---------------- FP16 mma flash attention (register-P, cp.async double buffer) ----------------
#define AT_BQ 128
#define AT_BK 64
#define ATQ_BYTES (AT_BQ * 64 * 2)          // 16384
#define ATKV_STAGE (AT_BK * 64 * 2 * 2)     // 16384 (K+V)
#define ATT_SMEM (ATQ_BYTES + 2 * ATKV_STAGE)

__global__ __launch_bounds__(256) void attn_f16_kernel(
    const __half* __restrict__ qkv, __half* __restrict__ out)
{
    extern __shared__ uint4 smemA[];
    const uint32_t sb = (uint32_t)__cvta_generic_to_shared(smemA);

    const int t    = threadIdx.x;
    const int w    = t >> 5;
    const int lane = t & 31;
    const int g    = lane >> 2;
    const int q    = lane & 3;
    const int lr   = lane & 15;
    const int hi   = lane >> 4;
    const int x7   = lane & 7;
    const int qb = blockIdx.x, h = blockIdx.y, b = blockIdx.z;

    const __half* qg = qkv + (size_t)(b * S_ + qb * AT_BQ) * NQKV_ + h * DK_;

#pragma unroll
    for (int i = 0; i < 4; i++) {
        int lin = i * 256 + t;
        int row = lin >> 3, c = lin & 7;
        uint32_t dst = sb + (uint32_t)(row * 8 + (c ^ (row & 7))) * 16;
        cp_async16(dst, qg + (size_t)row * NQKV_ + c * 8);
    }
    CP_COMMIT();
    CP_WAIT0();
    __syncthreads();

    uint32_t qa[4][4];
    {
        const uint32_t qRowOff = (uint32_t)(w * 16 + lr) * 128;
        const __half2 sc = __float2half2_rn(0.125f);
#pragma unroll
        for (int kb2 = 0; kb2 < 4; kb2++) {
            ldsm4(qa[kb2], sb + qRowOff + (uint32_t)(((2 * kb2 + hi) ^ x7) * 16));
#pragma unroll
            for (int i = 0; i < 4; i++) {
                __half2 v = *reinterpret_cast<__half2*>(&qa[kb2][i]);
                v = __hmul2(v, sc);
                qa[kb2][i] = h2u(v);
            }
        }
    }

    float m0 = -3.0e38f, m1 = -3.0e38f, l0 = 0.f, l1 = 0.f;
    float o[8][4];
#pragma unroll
    for (int nt = 0; nt < 8; nt++)
#pragma unroll
        for (int r = 0; r < 4; r++) o[nt][r] = 0.f;

    const __half* kg = qkv + (size_t)b * S_ * NQKV_ + D_ + h * DK_;

    auto loadKV = [&](int stage, int kb) {
        const uint32_t sbase = sb + ATQ_BYTES + stage * ATKV_STAGE;
        const __half* kr = kg + (size_t)(kb * AT_BK) * NQKV_;
#pragma unroll
        for (int i = 0; i < 2; i++) {
            int lin = i * 256 + t;
            int row = lin >> 3, c = lin & 7;
            uint32_t sw = (uint32_t)(row * 8 + (c ^ (row & 7))) * 16;
            const __half* kp = kr + (size_t)row * NQKV_ + c * 8;
            cp_async16(sbase + sw, kp);
            cp_async16(sbase + (AT_BK * 64 * 2) + sw, kp + D_);
        }
        CP_COMMIT();
    };

    const int NTILES = S_ / AT_BK;   // 32
    int buf = 0;
    loadKV(0, 0);

    for (int kb = 0; kb < NTILES; kb++) {
        const bool more = (kb + 1) < NTILES;
        if (more) loadKV(buf ^ 1, kb + 1);
        if (more) { CP_WAIT1(); } else { CP_WAIT0(); }
        __syncthreads();

        const uint32_t kbase = sb + ATQ_BYTES + buf * ATKV_STAGE;
        const uint32_t vbase = kbase + AT_BK * 64 * 2;

        float s[8][4];
#pragma unroll
        for (int nt = 0; nt < 8; nt++)
#pragma unroll
            for (int r = 0; r < 4; r++) s[nt][r] = 0.f;

#pragma unroll
        for (int nb = 0; nb < 4; nb++) {
            uint32_t kf[4][4];
            const uint32_t kro = (uint32_t)(nb * 16 + lr) * 128;
#pragma unroll
            for (int kb2 = 0; kb2 < 4; kb2++)
                ldsm4(kf[kb2], kbase + kro + (uint32_t)(((2 * kb2 + hi) ^ x7) * 16));
#pragma unroll
            for (int kb2 = 0; kb2 < 4; kb2++) {
                uint32_t b0[2] = { kf[kb2][0], kf[kb2][2] };
                uint32_t b1[2] = { kf[kb2][1], kf[kb2][3] };
                mma_f16(s[2 * nb],     qa[kb2], b0);
                mma_f16(s[2 * nb + 1], qa[kb2], b1);
            }
        }

        float mx0 = -3.0e38f, mx1 = -3.0e38f;
#pragma unroll
        for (int nt = 0; nt < 8; nt++) {
            mx0 = fmaxf(mx0, fmaxf(s[nt][0], s[nt][1]));
            mx1 = fmaxf(mx1, fmaxf(s[nt][2], s[nt][3]));
        }
        mx0 = fmaxf(mx0, __shfl_xor_sync(0xffffffffu, mx0, 1));
        mx0 = fmaxf(mx0, __shfl_xor_sync(0xffffffffu, mx0, 2));
        mx1 = fmaxf(mx1, __shfl_xor_sync(0xffffffffu, mx1, 1));
        mx1 = fmaxf(mx1, __shfl_xor_sync(0xffffffffu, mx1, 2));

        const float mn0 = fmaxf(m0, mx0), mn1 = fmaxf(m1, mx1);
        const float f0 = __expf(m0 - mn0), f1 = __expf(m1 - mn1);
        m0 = mn0; m1 = mn1;

        float ls0 = 0.f, ls1 = 0.f;
#pragma unroll
        for (int nt = 0; nt < 8; nt++) {
            s[nt][0] = __expf(s[nt][0] - mn0);
            s[nt][1] = __expf(s[nt][1] - mn0);
            s[nt][2] = __expf(s[nt][2] - mn1);
            s[nt][3] = __expf(s[nt][3] - mn1);
            ls0 += s[nt][0] + s[nt][1];
            ls1 += s[nt][2] + s[nt][3];
        }
        ls0 += __shfl_xor_sync(0xffffffffu, ls0, 1);
        ls0 += __shfl_xor_sync(0xffffffffu, ls0, 2);
        ls1 += __shfl_xor_sync(0xffffffffu, ls1, 1);
        ls1 += __shfl_xor_sync(0xffffffffu, ls1, 2);
        l0 = l0 * f0 + ls0;
        l1 = l1 * f1 + ls1;

        uint32_t pa[4][4];
#pragma unroll
        for (int kb2 = 0; kb2 < 4; kb2++) {
            pa[kb2][0] = h2u(__floats2half2_rn(s[2 * kb2][0],     s[2 * kb2][1]));
            pa[kb2][1] = h2u(__floats2half2_rn(s[2 * kb2][2],     s[2 * kb2][3]));
            pa[kb2][2] = h2u(__floats2half2_rn(s[2 * kb2 + 1][0], s[2 * kb2 + 1][1]));
            pa[kb2][3] = h2u(__floats2half2_rn(s[2 * kb2 + 1][2], s[2 * kb2 + 1][3]));
        }

#pragma unroll
        for (int nt = 0; nt < 8; nt++) {
            o[nt][0] *= f0; o[nt][1] *= f0;
            o[nt][2] *= f1; o[nt][3] *= f1;
        }

#pragma unroll
        for (int nb2 = 0; nb2 < 4; nb2++) {
            const uint32_t cxv = (uint32_t)(((2 * nb2 + hi) ^ x7) * 16);
#pragma unroll
            for (int kb2 = 0; kb2 < 4; kb2++) {
                uint32_t vf[4];
                ldsm4t(vf, vbase + (uint32_t)(kb2 * 16 + lr) * 128 + cxv);
                uint32_t b0[2] = { vf[0], vf[1] };
                uint32_t b1[2] = { vf[2], vf[3] };
                mma_f16(o[2 * nb2],     pa[kb2], b0);
                mma_f16(o[2 * nb2 + 1], pa[kb2], b1);
            }
        }

        __syncthreads();
        buf ^= 1;
    }

    const float i0 = 1.0f / l0, i1 = 1.0f / l1;
    __half* op = out + (size_t)(b * S_ + qb * AT_BQ + w * 16) * D_ + h * DK_;
#pragma unroll
    for (int nt = 0; nt < 8; nt++) {
        const int c = nt * 8 + 2 * q;
        *(uint32_t*)(op + (size_t)g * D_ + c) =
            h2u(__floats2half2_rn(o[nt][0] * i0, o[nt][1] * i0));
        *(uint32_t*)(op + (size_t)(g + 8) * D_ + c) =
            h2u(__floats2half2_rn(o[nt][2] * i1, o[nt][3] * i1));
    }
}

// ---------------- fused residual-add + LayerNorm: warp-per-row, float4, shuffle-only ----------------
template<int DUAL>
__global__ __launch_bounds__(256) void add_ln_kernel(
    const float* __restrict__ A, const float* __restrict__ Bv,
    const float* __restrict__ gamma, const float* __restrict__ beta,
    float* __restrict__ out, __half* __restrict__ outh)
{
    const int w    = threadIdx.x >> 5;
    const int lane = threadIdx.x & 31;
    const int row  = blockIdx.x * 8 + w;

    const float* pa = A  + (size_t)row * D_;
    const float* pb = Bv + (size_t)row * D_;

    float4 v[6];
    float s = 0.f;
#pragma unroll
    for (int i = 0; i < 6; i++) {
        const int off = (i * 32 + lane) * 4;
        float4 a4 = *(const float4*)(pa + off);
        float4 b4 = *(const float4*)(pb + off);
        v[i].x = a4.x + b4.x; v[i].y = a4.y + b4.y;
        v[i].z = a4.z + b4.z; v[i].w = a4.w + b4.w;
        s += v[i].x + v[i].y + v[i].z + v[i].w;
    }
#pragma unroll
    for (int mk = 16; mk; mk >>= 1) s += __shfl_xor_sync(0xffffffffu, s, mk);
    const float mean = s * (1.0f / D_);

    float qv = 0.f;
#pragma unroll
    for (int i = 0; i < 6; i++) {
        v[i].x -= mean; v[i].y -= mean; v[i].z -= mean; v[i].w -= mean;
        qv += v[i].x * v[i].x + v[i].y * v[i].y + v[i].z * v[i].z + v[i].w * v[i].w;
    }
#pragma unroll
    for (int mk = 16; mk; mk >>= 1) qv += __shfl_xor_sync(0xffffffffu, qv, mk);
    const float rstd = rsqrtf(qv * (1.0f / D_) + 1e-5f);

    float* po = out + (size_t)row * D_;
    __half* ph = DUAL ? (outh + (size_t)row * D_) : nullptr;
#pragma unroll
    for (int i = 0; i < 6; i++) {
        const int off = (i * 32 + lane) * 4;
        float4 g4 = *(const float4*)(gamma + off);
        float4 e4 = *(const float4*)(beta + off);
        float4 r;
        r.x = v[i].x * rstd * g4.x + e4.x;
        r.y = v[i].y * rstd * g4.y + e4.y;
        r.z = v[i].z * rstd * g4.z + e4.z;
        r.w = v[i].w * rstd * g4.w + e4.w;
        *(float4*)(po + off) = r;
        if (DUAL) {
            uint2 hh;
            hh.x = h2u(__floats2half2_rn(r.x, r.y));
            hh.y = h2u(__floats2half2_rn(r.z, r.w));
            *(uint2*)(ph + off) = hh;
        }
    }
}

// ---------------- launch ----------------
extern "C" void kernel_launch(void* const* d_in, const int* in_sizes, int n_in,
                              void* d_out, int out_size)
{
    const float* src = (const float*)d_in[0];
    const float* Wq  = (const float*)d_in[1];
    const float* bq  = (const float*)d_in[2];
    const float* Wk  = (const float*)d_in[3];
    const float* bk  = (const float*)d_in[4];
    const float* Wv  = (const float*)d_in[5];
    const float* bv  = (const float*)d_in[6];
    const float* Wo  = (const float*)d_in[7];
    const float* bo  = (const float*)d_in[8];
    const float* g1  = (const float*)d_in[9];
    const float* be1 = (const float*)d_in[10];
    const float* W1  = (const float*)d_in[11];
    const float* bf1 = (const float*)d_in[12];
    const float* W2  = (const float*)d_in[13];
    const float* bf2 = (const float*)d_in[14];
    const float* g2  = (const float*)d_in[15];
    const float* be2 = (const float*)d_in[16];
    float* out = (float*)d_out;

    __half *wqkvT, *woT, *w1T, *w2T, *srch, *x1h, *qkvh, *attnh, *ffn1h;
    float *bqkv, *mha, *x1, *ffn2;
    cudaGetSymbolAddress((void**)&wqkvT, g_wqkvT);
    cudaGetSymbolAddress((void**)&bqkv,  g_bqkv);
    cudaGetSymbolAddress((void**)&woT,   g_woT);
    cudaGetSymbolAddress((void**)&w1T,   g_w1T);
    cudaGetSymbolAddress((void**)&w2T,   g_w2T);
    cudaGetSymbolAddress((void**)&srch,  g_srch);
    cudaGetSymbolAddress((void**)&x1h,   g_x1h);
    cudaGetSymbolAddress((void**)&qkvh,  g_qkvh);
    cudaGetSymbolAddress((void**)&attnh, g_attnh);
    cudaGetSymbolAddress((void**)&ffn1h, g_ffn1h);
    cudaGetSymbolAddress((void**)&mha,   g_mha);
    cudaGetSymbolAddress((void**)&x1,    g_x1);
    cudaGetSymbolAddress((void**)&ffn2,  g_ffn2);

    const int smem256 = gemm_smem_bytes(256);   // 147456
    const int smem128 = gemm_smem_bytes(128);   // 98304
    cudaFuncSetAttribute(gemm_f16<0,1,256>, cudaFuncAttributeMaxDynamicSharedMemorySize, smem256);
    cudaFuncSetAttribute(gemm_f16<1,1,256>, cudaFuncAttributeMaxDynamicSharedMemorySize, smem256);
    cudaFuncSetAttribute(gemm_f16<0,0,128>, cudaFuncAttributeMaxDynamicSharedMemorySize, smem128);
    cudaFuncSetAttribute(attn_f16_kernel, cudaFuncAttributeMaxDynamicSharedMemorySize, ATT_SMEM);

    dim3 tb(32, 8);

    // 0) operand prep
    cvt_f2h<<<(M_ * D_ / 4 + 255) / 256, 256>>>(src, srch, M_ * D_ / 4);
    pack_qkv_wT<<<dim3(DK_ / 32, D_ / 32, 3 * H_), tb>>>(Wq, Wk, Wv, wqkvT);
    pack_qkv_bias<<<(NQKV_ + 255) / 256, 256>>>(bq, bk, bv);
    transpose_h<<<dim3(D_ / 32, D_ / 32), tb>>>(Wo, woT, D_, D_);
    transpose_h<<<dim3(F_ / 32, D_ / 32), tb>>>(W1, w1T, D_, F_);
    transpose_h<<<dim3(D_ / 32, F_ / 32), tb>>>(W2, w2T, F_, D_);

    // 1) QKV projection -> fp16 qkv   (grid 9x64 = 576)
    gemm_f16<0,1,256><<<dim3(NQKV_ / 256, M_ / BMg), 256, smem256>>>(srch, wqkvT, bqkv, qkvh, M_, NQKV_, D_);

    // 2) fused attention -> fp16 attn
    attn_f16_kernel<<<dim3(S_ / AT_BQ, H_, B_), 256, ATT_SMEM>>>(qkvh, attnh);

    // 3) output projection -> fp32 mha  (BN=128: grid 6x64 = 384, 2 CTAs/SM)
    gemm_f16<0,0,128><<<dim3(D_ / 128, M_ / BMg), 256, smem128>>>(attnh, woT, bo, mha, M_, D_, D_);

    // 4) x1 = LN(src + mha), dual fp32 + fp16
    add_ln_kernel<1><<<M_ / 8, 256>>>(src, mha, g1, be1, x1, x1h);

    // 5) FFN1 (+ReLU) -> fp16 ffn1  (grid 12x64 = 768)
    gemm_f16<1,1,256><<<dim3(F_ / 256, M_ / BMg), 256, smem256>>>(x1h, w1T, bf1, ffn1h, M_, F_, D_);

    // 6) FFN2 -> fp32 ffn2  (BN=128: grid 6x64 = 384, 2 CTAs/SM)
    gemm_f16<0,0,128><<<dim3(D_ / 128, M_ / BMg), 256, smem128>>>(ffn1h, w2T, bf2, ffn2, M_, D_, F_);

    // 7) out = LN(x1 + ffn2)
    add_ln_kernel<0><<<M_ / 8, 256>>>(x1, ffn2, g2, be2, out, nullptr);
}

// round 12
// speedup vs baseline: 8.1140x; 1.0177x over previous
#include <cuda_runtime.h>
#include <cuda_fp16.h>
#include <math.h>
#include <stdint.h>

// Problem constants
#define B_    4
#define S_    2048
#define D_    768
#define H_    12
#define DK_   64
#define F_    3072
#define M_    (B_*S_)        // 8192 rows
#define NQKV_ (3*D_)         // 2304

// ---------------- scratch (static device globals; no allocation) ----------------
__device__ __half g_wqkvT[NQKV_*D_];   // packed+transposed QKV weights [3*H*DK][D]
__device__ float  g_bqkv[NQKV_];       // packed QKV bias (fp32)
__device__ __half g_woT [D_*D_];       // Wo^T  [D][D]
__device__ __half g_w1T [F_*D_];       // W1^T  [F][D]
__device__ __half g_w2T [D_*F_];       // W2^T  [D][F]
__device__ __half g_srch[M_*D_];       // fp16 source
__device__ __half g_x1h [M_*D_];       // fp16 x1
__device__ __half g_qkvh[M_*NQKV_];    // fp16 qkv (q|k|v)
__device__ __half g_attnh[M_*D_];      // fp16 concat-head attention out
__device__ __half g_ffn1h[M_*F_];      // fp16 relu(ffn1)
__device__ __half g_mhah [M_*D_];      // fp16 out-proj result
__device__ __half g_ffn2h[M_*D_];      // fp16 ffn2 result
__device__ float  g_x1  [M_*D_];

// ---------------- helpers ----------------
__device__ __forceinline__ void mma_f16(float* d, const uint32_t* a, const uint32_t* b) {
    asm volatile(
        "mma.sync.aligned.m16n8k16.row.col.f32.f16.f16.f32 "
        "{%0,%1,%2,%3}, {%4,%5,%6,%7}, {%8,%9}, {%0,%1,%2,%3};"
        : "+f"(d[0]), "+f"(d[1]), "+f"(d[2]), "+f"(d[3])
        : "r"(a[0]), "r"(a[1]), "r"(a[2]), "r"(a[3]), "r"(b[0]), "r"(b[1]));
}

__device__ __forceinline__ void ldsm4(uint32_t* r, uint32_t addr) {
    asm volatile("ldmatrix.sync.aligned.m8n8.x4.shared.b16 {%0,%1,%2,%3}, [%4];"
                 : "=r"(r[0]), "=r"(r[1]), "=r"(r[2]), "=r"(r[3]) : "r"(addr));
}

__device__ __forceinline__ void ldsm4t(uint32_t* r, uint32_t addr) {
    asm volatile("ldmatrix.sync.aligned.m8n8.x4.trans.shared.b16 {%0,%1,%2,%3}, [%4];"
                 : "=r"(r[0]), "=r"(r[1]), "=r"(r[2]), "=r"(r[3]) : "r"(addr));
}

__device__ __forceinline__ void cp_async16(uint32_t smem_dst, const void* gmem_src) {
    asm volatile("cp.async.cg.shared.global [%0], [%1], 16;" :: "r"(smem_dst), "l"(gmem_src));
}
#define CP_COMMIT() asm volatile("cp.async.commit_group;")
#define CP_WAIT0()  asm volatile("cp.async.wait_group 0;")
#define CP_WAIT1()  asm volatile("cp.async.wait_group 1;")

__device__ __forceinline__ uint32_t h2u(__half2 h) { return *reinterpret_cast<uint32_t*>(&h); }

// ---------------- fused prep kernel: src cvt + bias pack + all weight transposes ----------------
// block-job dispatch; 256 threads/block.
#define PB_CVT   6144                       // M_*D_/4/256
#define PB_BIAS  9                          // ceil(2304/256)
#define PB_WO    576                        // (768/32)*(768/32)
#define PB_W1    2304                       // (3072/32)*(768/32)
#define PB_W2    2304                       // (768/32)*(3072/32)
#define PB_QKV   1728                       // 36 * (64/32)*(768/32)
#define PB_TOTAL (PB_CVT + PB_BIAS + PB_WO + PB_W1 + PB_W2 + PB_QKV)

__global__ __launch_bounds__(256) void prep_all(
    const float* __restrict__ src,
    const float* __restrict__ Wq, const float* __restrict__ Wk, const float* __restrict__ Wv,
    const float* __restrict__ bq, const float* __restrict__ bk, const float* __restrict__ bv,
    const float* __restrict__ Wo, const float* __restrict__ W1, const float* __restrict__ W2)
{
    int bid = blockIdx.x;
    const int t = threadIdx.x;

    if (bid < PB_CVT) {                     // src fp32 -> fp16
        int i = bid * 256 + t;              // float4 index
        float4 v = *(const float4*)(src + (size_t)i * 4);
        uint2 o;
        o.x = h2u(__floats2half2_rn(v.x, v.y));
        o.y = h2u(__floats2half2_rn(v.z, v.w));
        *(uint2*)(g_srch + (size_t)i * 4) = o;
        return;
    }
    bid -= PB_CVT;
    if (bid < PB_BIAS) {                    // qkv bias pack
        int idx = bid * 256 + t;
        if (idx < NQKV_) {
            int wh = idx / D_, jj = idx % D_;
            const float* bsrc = (wh == 0) ? bq : (wh == 1) ? bk : bv;
            g_bqkv[idx] = bsrc[jj];
        }
        return;
    }
    bid -= PB_BIAS;

    // ---- transpose jobs: 32x32 tile, (32,8) thread view ----
    __shared__ float tile[32][33];
    const int tx = t & 31, ty = t >> 5;

    const float* in; __half* out;
    int C, r0, c0, obase, outLD;
    if (bid < PB_WO) {                      // Wo [768,768] -> woT
        in = Wo; out = g_woT; C = D_; outLD = D_; obase = 0;
        c0 = (bid % 24) * 32; r0 = (bid / 24) * 32;
    } else if (bid < PB_WO + PB_W1) {       // W1 [768,3072] -> w1T
        bid -= PB_WO;
        in = W1; out = g_w1T; C = F_; outLD = D_; obase = 0;
        c0 = (bid % 96) * 32; r0 = (bid / 96) * 32;
    } else if (bid < PB_WO + PB_W1 + PB_W2) {  // W2 [3072,768] -> w2T
        bid -= PB_WO + PB_W1;
        in = W2; out = g_w2T; C = D_; outLD = F_; obase = 0;
        c0 = (bid % 24) * 32; r0 = (bid / 24) * 32;
    } else {                                // QKV weights [H,D,DK]x3 -> wqkvT
        bid -= PB_WO + PB_W1 + PB_W2;
        const int z = bid / 48;             // 0..35
        const int j = bid % 48;             // 2 x 24 tiles
        const int wh = z / H_, h = z % H_;
        in = ((wh == 0) ? Wq : (wh == 1) ? Wk : Wv) + (size_t)h * D_ * DK_;
        out = g_wqkvT; C = DK_; outLD = D_;
        obase = wh * D_ + h * DK_;
        c0 = (j % 2) * 32; r0 = (j / 2) * 32;
    }

#pragma unroll
    for (int i = 0; i < 32; i += 8)
        tile[ty + i][tx] = in[(size_t)(r0 + ty + i) * C + c0 + tx];
    __syncthreads();
#pragma unroll
    for (int i = 0; i < 32; i += 8)
        out[(size_t)(obase + c0 + ty + i) * outLD + r0 + tx] = __float2half_rn(tile[tx][ty + i]);
}

// ---------------- FP16 tensor-core GEMM: ldmatrix + cp.async, 3 stages ----------------
// C[M,N] = A[M,K] @ Bt[N,K]^T + bias. CTA 128xBN, BK=64 halves, 8 warps (2 x 4),
// warp tile 64x(BN/4), mma.m16n8k16. BN=256 (1 CTA/SM) or BN=128 (2 CTAs/SM).
#define BMg 128
#define BKg 64
#define STAGES 3
#define A_CHUNKS (BMg*8)                   // 16B chunks per stage

constexpr int gemm_smem_bytes(int BN) { return STAGES * (A_CHUNKS + BN * 8) * 16; }

template<int RELU, int OUTH, int BN>
__global__ __launch_bounds__(256, (BN == 128) ? 2 : 1) void gemm_f16(
    const __half* __restrict__ A, const __half* __restrict__ Bt,
    const float* __restrict__ bias, void* __restrict__ Cv,
    int M, int N, int K)
{
    constexpr int B_CHUNKS = BN * 8;
    constexpr int STAGE_CHUNKS = A_CHUNKS + B_CHUNKS;
    constexpr int WN = BN / 4;       // warp tile N (64 or 32)
    constexpr int NT = WN / 8;       // n8 tiles per warp (8 or 4)
    constexpr int NB = WN / 16;      // 16-col ldsm groups (4 or 2)

    extern __shared__ uint4 smem4[];
    const uint32_t smem_base = (uint32_t)__cvta_generic_to_shared(smem4);

    const int t    = threadIdx.x;
    const int lane = t & 31;
    const int wid  = t >> 5;
    const int wm   = wid & 1;     // 0..1 (64-row slab)
    const int wn   = wid >> 1;    // 0..3 (WN-col slab)
    const int rowC = blockIdx.y * BMg;
    const int colC = blockIdx.x * BN;

    float acc[4][NT][4];
#pragma unroll
    for (int i = 0; i < 4; i++)
#pragma unroll
        for (int j = 0; j < NT; j++)
#pragma unroll
            for (int r = 0; r < 4; r++) acc[i][j][r] = 0.f;

    const int ntiles = K / BKg;

    auto load_tile = [&](int stage, int kt) {
        const uint32_t sa = smem_base + stage * (STAGE_CHUNKS * 16);
#pragma unroll
        for (int i = 0; i < 4; i++) {
            int lin = i * 256 + t;
            int m = lin >> 3, c = lin & 7;
            uint32_t dst = sa + (uint32_t)(m * 8 + (c ^ (m & 7))) * 16;
            cp_async16(dst, A + (size_t)(rowC + m) * K + kt * BKg + c * 8);
        }
#pragma unroll
        for (int i = 0; i < B_CHUNKS / 256; i++) {
            int lin = i * 256 + t;
            int n = lin >> 3, c = lin & 7;
            uint32_t dst = sa + (uint32_t)(A_CHUNKS + n * 8 + (c ^ (n & 7))) * 16;
            cp_async16(dst, Bt + (size_t)(colC + n) * K + kt * BKg + c * 8);
        }
        CP_COMMIT();
    };

    load_tile(0, 0);
    load_tile(1, 1);

    const int lr = lane & 15;
    const int hi = lane >> 4;
    const int x7 = lane & 7;
    uint32_t aRowOff[4], bRowOff[NB];
#pragma unroll
    for (int mt = 0; mt < 4; mt++)
        aRowOff[mt] = (uint32_t)(wm * 64 + mt * 16 + lr) * 128;
#pragma unroll
    for (int nb = 0; nb < NB; nb++)
        bRowOff[nb] = (uint32_t)(A_CHUNKS * 16) + (uint32_t)(wn * WN + nb * 16 + lr) * 128;

    for (int kt = 0; kt < ntiles; kt++) {
        CP_WAIT1();
        __syncthreads();

        const int nxt = kt + STAGES - 1;
        if (nxt < ntiles) load_tile(nxt % STAGES, nxt);
        else              CP_COMMIT();

        const uint32_t sa = smem_base + (kt % STAGES) * (STAGE_CHUNKS * 16);
#pragma unroll
        for (int kk = 0; kk < 4; kk++) {
            const uint32_t cx = (uint32_t)(((2 * kk + hi) ^ x7) * 16);
            uint32_t a[4][4], bfr[NB][4];
#pragma unroll
            for (int mt = 0; mt < 4; mt++)
                ldsm4(a[mt], sa + aRowOff[mt] + cx);
#pragma unroll
            for (int nb = 0; nb < NB; nb++)
                ldsm4(bfr[nb], sa + bRowOff[nb] + cx);
#pragma unroll
            for (int mt = 0; mt < 4; mt++)
#pragma unroll
                for (int nt = 0; nt < NT; nt++) {
                    uint32_t bb[2];
                    bb[0] = bfr[nt >> 1][(nt & 1)];
                    bb[1] = bfr[nt >> 1][2 + (nt & 1)];
                    mma_f16(acc[mt][nt], a[mt], bb);
                }
        }
    }

    // epilogue
    const int g2 = lane >> 2, q2 = lane & 3;
#pragma unroll
    for (int mt = 0; mt < 4; mt++) {
        const int r0 = rowC + wm * 64 + mt * 16 + g2;
#pragma unroll
        for (int nt = 0; nt < NT; nt++) {
            const int c = colC + wn * WN + nt * 8 + 2 * q2;
            const float b0v = bias[c], b1v = bias[c + 1];
            float o00 = acc[mt][nt][0] + b0v, o01 = acc[mt][nt][1] + b1v;
            float o10 = acc[mt][nt][2] + b0v, o11 = acc[mt][nt][3] + b1v;
            if (RELU) {
                o00 = fmaxf(o00, 0.f); o01 = fmaxf(o01, 0.f);
                o10 = fmaxf(o10, 0.f); o11 = fmaxf(o11, 0.f);
            }
            if (OUTH) {
                __half* Ch = (__half*)Cv;
                *(uint32_t*)(Ch + (size_t)r0 * N + c)       = h2u(__floats2half2_rn(o00, o01));
                *(uint32_t*)(Ch + (size_t)(r0 + 8) * N + c) = h2u(__floats2half2_rn(o10, o11));
            } else {
                float* Cf = (float*)Cv;
                *(float2*)(Cf + (size_t)r0 * N + c)       = make_float2(o00, o01);
                *(float2*)(Cf + (size_t)(r0 + 8) * N + c) = make_float2(o10, o11);
            }
        }
    }
}

// ---------------- FP16 mma flash attention (register-P, cp.async double buffer) ----------------
#define AT_BQ 128
#define AT_BK 64
#define ATQ_BYTES (AT_BQ * 64 * 2)          // 16384
#define ATKV_STAGE (AT_BK * 64 * 2 * 2)     // 16384 (K+V)
#define ATT_SMEM (ATQ_BYTES + 2 * ATKV_STAGE)

__global__ __launch_bounds__(256) void attn_f16_kernel(
    const __half* __restrict__ qkv, __half* __restrict__ out)
{
    extern __shared__ uint4 smemA[];
    const uint32_t sb = (uint32_t)__cvta_generic_to_shared(smemA);

    const int t    = threadIdx.x;
    const int w    = t >> 5;
    const int lane = t & 31;
    const int g    = lane >> 2;
    const int q    = lane & 3;
    const int lr   = lane & 15;
    const int hi   = lane >> 4;
    const int x7   = lane & 7;
    const int qb = blockIdx.x, h = blockIdx.y, b = blockIdx.z;

    const __half* qg = qkv + (size_t)(b * S_ + qb * AT_BQ) * NQKV_ + h * DK_;

#pragma unroll
    for (int i = 0; i < 4; i++) {
        int lin = i * 256 + t;
        int row = lin >> 3, c = lin & 7;
        uint32_t dst = sb + (uint32_t)(row * 8 + (c ^ (row & 7))) * 16;
        cp_async16(dst, qg + (size_t)row * NQKV_ + c * 8);
    }
    CP_COMMIT();
    CP_WAIT0();
    __syncthreads();

    uint32_t qa[4][4];
    {
        const uint32_t qRowOff = (uint32_t)(w * 16 + lr) * 128;
        const __half2 sc = __float2half2_rn(0.125f);
#pragma unroll
        for (int kb2 = 0; kb2 < 4; kb2++) {
            ldsm4(qa[kb2], sb + qRowOff + (uint32_t)(((2 * kb2 + hi) ^ x7) * 16));
#pragma unroll
            for (int i = 0; i < 4; i++) {
                __half2 v = *reinterpret_cast<__half2*>(&qa[kb2][i]);
                v = __hmul2(v, sc);
                qa[kb2][i] = h2u(v);
            }
        }
    }

    float m0 = -3.0e38f, m1 = -3.0e38f, l0 = 0.f, l1 = 0.f;
    float o[8][4];
#pragma unroll
    for (int nt = 0; nt < 8; nt++)
#pragma unroll
        for (int r = 0; r < 4; r++) o[nt][r] = 0.f;

    const __half* kg = qkv + (size_t)b * S_ * NQKV_ + D_ + h * DK_;

    auto loadKV = [&](int stage, int kb) {
        const uint32_t sbase = sb + ATQ_BYTES + stage * ATKV_STAGE;
        const __half* kr = kg + (size_t)(kb * AT_BK) * NQKV_;
#pragma unroll
        for (int i = 0; i < 2; i++) {
            int lin = i * 256 + t;
            int row = lin >> 3, c = lin & 7;
            uint32_t sw = (uint32_t)(row * 8 + (c ^ (row & 7))) * 16;
            const __half* kp = kr + (size_t)row * NQKV_ + c * 8;
            cp_async16(sbase + sw, kp);
            cp_async16(sbase + (AT_BK * 64 * 2) + sw, kp + D_);
        }
        CP_COMMIT();
    };

    const int NTILES = S_ / AT_BK;   // 32
    int buf = 0;
    loadKV(0, 0);

    for (int kb = 0; kb < NTILES; kb++) {
        const bool more = (kb + 1) < NTILES;
        if (more) loadKV(buf ^ 1, kb + 1);
        if (more) { CP_WAIT1(); } else { CP_WAIT0(); }
        __syncthreads();

        const uint32_t kbase = sb + ATQ_BYTES + buf * ATKV_STAGE;
        const uint32_t vbase = kbase + AT_BK * 64 * 2;

        float s[8][4];
#pragma unroll
        for (int nt = 0; nt < 8; nt++)
#pragma unroll
            for (int r = 0; r < 4; r++) s[nt][r] = 0.f;

#pragma unroll
        for (int nb = 0; nb < 4; nb++) {
            uint32_t kf[4][4];
            const uint32_t kro = (uint32_t)(nb * 16 + lr) * 128;
#pragma unroll
            for (int kb2 = 0; kb2 < 4; kb2++)
                ldsm4(kf[kb2], kbase + kro + (uint32_t)(((2 * kb2 + hi) ^ x7) * 16));
#pragma unroll
            for (int kb2 = 0; kb2 < 4; kb2++) {
                uint32_t b0[2] = { kf[kb2][0], kf[kb2][2] };
                uint32_t b1[2] = { kf[kb2][1], kf[kb2][3] };
                mma_f16(s[2 * nb],     qa[kb2], b0);
                mma_f16(s[2 * nb + 1], qa[kb2], b1);
            }
        }

        float mx0 = -3.0e38f, mx1 = -3.0e38f;
#pragma unroll
        for (int nt = 0; nt < 8; nt++) {
            mx0 = fmaxf(mx0, fmaxf(s[nt][0], s[nt][1]));
            mx1 = fmaxf(mx1, fmaxf(s[nt][2], s[nt][3]));
        }
        mx0 = fmaxf(mx0, __shfl_xor_sync(0xffffffffu, mx0, 1));
        mx0 = fmaxf(mx0, __shfl_xor_sync(0xffffffffu, mx0, 2));
        mx1 = fmaxf(mx1, __shfl_xor_sync(0xffffffffu, mx1, 1));
        mx1 = fmaxf(mx1, __shfl_xor_sync(0xffffffffu, mx1, 2));

        const float mn0 = fmaxf(m0, mx0), mn1 = fmaxf(m1, mx1);
        const float f0 = __expf(m0 - mn0), f1 = __expf(m1 - mn1);
        m0 = mn0; m1 = mn1;

        float ls0 = 0.f, ls1 = 0.f;
#pragma unroll
        for (int nt = 0; nt < 8; nt++) {
            s[nt][0] = __expf(s[nt][0] - mn0);
            s[nt][1] = __expf(s[nt][1] - mn0);
            s[nt][2] = __expf(s[nt][2] - mn1);
            s[nt][3] = __expf(s[nt][3] - mn1);
            ls0 += s[nt][0] + s[nt][1];
            ls1 += s[nt][2] + s[nt][3];
        }
        ls0 += __shfl_xor_sync(0xffffffffu, ls0, 1);
        ls0 += __shfl_xor_sync(0xffffffffu, ls0, 2);
        ls1 += __shfl_xor_sync(0xffffffffu, ls1, 1);
        ls1 += __shfl_xor_sync(0xffffffffu, ls1, 2);
        l0 = l0 * f0 + ls0;
        l1 = l1 * f1 + ls1;

        uint32_t pa[4][4];
#pragma unroll
        for (int kb2 = 0; kb2 < 4; kb2++) {
            pa[kb2][0] = h2u(__floats2half2_rn(s[2 * kb2][0],     s[2 * kb2][1]));
            pa[kb2][1] = h2u(__floats2half2_rn(s[2 * kb2][2],     s[2 * kb2][3]));
            pa[kb2][2] = h2u(__floats2half2_rn(s[2 * kb2 + 1][0], s[2 * kb2 + 1][1]));
            pa[kb2][3] = h2u(__floats2half2_rn(s[2 * kb2 + 1][2], s[2 * kb2 + 1][3]));
        }

#pragma unroll
        for (int nt = 0; nt < 8; nt++) {
            o[nt][0] *= f0; o[nt][1] *= f0;
            o[nt][2] *= f1; o[nt][3] *= f1;
        }

#pragma unroll
        for (int nb2 = 0; nb2 < 4; nb2++) {
            const uint32_t cxv = (uint32_t)(((2 * nb2 + hi) ^ x7) * 16);
#pragma unroll
            for (int kb2 = 0; kb2 < 4; kb2++) {
                uint32_t vf[4];
                ldsm4t(vf, vbase + (uint32_t)(kb2 * 16 + lr) * 128 + cxv);
                uint32_t b0[2] = { vf[0], vf[1] };
                uint32_t b1[2] = { vf[2], vf[3] };
                mma_f16(o[2 * nb2],     pa[kb2], b0);
                mma_f16(o[2 * nb2 + 1], pa[kb2], b1);
            }
        }

        __syncthreads();
        buf ^= 1;
    }

    const float i0 = 1.0f / l0, i1 = 1.0f / l1;
    __half* op = out + (size_t)(b * S_ + qb * AT_BQ + w * 16) * D_ + h * DK_;
#pragma unroll
    for (int nt = 0; nt < 8; nt++) {
        const int c = nt * 8 + 2 * q;
        *(uint32_t*)(op + (size_t)g * D_ + c) =
            h2u(__floats2half2_rn(o[nt][0] * i0, o[nt][1] * i0));
        *(uint32_t*)(op + (size_t)(g + 8) * D_ + c) =
            h2u(__floats2half2_rn(o[nt][2] * i1, o[nt][3] * i1));
    }
}

// ---------------- fused residual-add + LayerNorm: warp-per-row, float4, shuffle-only ----------------
// A is fp32 (residual), Bv is fp16 (GEMM output).
template<int DUAL>
__global__ __launch_bounds__(256) void add_ln_kernel(
    const float* __restrict__ A, const __half* __restrict__ Bv,
    const float* __restrict__ gamma, const float* __restrict__ beta,
    float* __restrict__ out, __half* __restrict__ outh)
{
    const int w    = threadIdx.x >> 5;
    const int lane = threadIdx.x & 31;
    const int row  = blockIdx.x * 8 + w;

    const float*  pa = A  + (size_t)row * D_;
    const __half* pb = Bv + (size_t)row * D_;

    float4 v[6];
    float s = 0.f;
#pragma unroll
    for (int i = 0; i < 6; i++) {
        const int off = (i * 32 + lane) * 4;
        float4 a4 = *(const float4*)(pa + off);
        uint2 bh = *(const uint2*)(pb + off);
        float2 b0 = __half22float2(*reinterpret_cast<__half2*>(&bh.x));
        float2 b1 = __half22float2(*reinterpret_cast<__half2*>(&bh.y));
        v[i].x = a4.x + b0.x; v[i].y = a4.y + b0.y;
        v[i].z = a4.z + b1.x; v[i].w = a4.w + b1.y;
        s += v[i].x + v[i].y + v[i].z + v[i].w;
    }
#pragma unroll
    for (int mk = 16; mk; mk >>= 1) s += __shfl_xor_sync(0xffffffffu, s, mk);
    const float mean = s * (1.0f / D_);

    float qv = 0.f;
#pragma unroll
    for (int i = 0; i < 6; i++) {
        v[i].x -= mean; v[i].y -= mean; v[i].z -= mean; v[i].w -= mean;
        qv += v[i].x * v[i].x + v[i].y * v[i].y + v[i].z * v[i].z + v[i].w * v[i].w;
    }
#pragma unroll
    for (int mk = 16; mk; mk >>= 1) qv += __shfl_xor_sync(0xffffffffu, qv, mk);
    const float rstd = rsqrtf(qv * (1.0f / D_) + 1e-5f);

    float* po = out + (size_t)row * D_;
    __half* ph = DUAL ? (outh + (size_t)row * D_) : nullptr;
#pragma unroll
    for (int i = 0; i < 6; i++) {
        const int off = (i * 32 + lane) * 4;
        float4 g4 = *(const float4*)(gamma + off);
        float4 e4 = *(const float4*)(beta + off);
        float4 r;
        r.x = v[i].x * rstd * g4.x + e4.x;
        r.y = v[i].y * rstd * g4.y + e4.y;
        r.z = v[i].z * rstd * g4.z + e4.z;
        r.w = v[i].w * rstd * g4.w + e4.w;
        *(float4*)(po + off) = r;
        if (DUAL) {
            uint2 hh;
            hh.x = h2u(__floats2half2_rn(r.x, r.y));
            hh.y = h2u(__floats2half2_rn(r.z, r.w));
            *(uint2*)(ph + off) = hh;
        }
    }
}

// ---------------- launch ----------------
extern "C" void kernel_launch(void* const* d_in, const int* in_sizes, int n_in,
                              void* d_out, int out_size)
{
    const float* src = (const float*)d_in[0];
    const float* Wq  = (const float*)d_in[1];
    const float* bq  = (const float*)d_in[2];
    const float* Wk  = (const float*)d_in[3];
    const float* bk  = (const float*)d_in[4];
    const float* Wv  = (const float*)d_in[5];
    const float* bv  = (const float*)d_in[6];
    const float* Wo  = (const float*)d_in[7];
    const float* bo  = (const float*)d_in[8];
    const float* g1  = (const float*)d_in[9];
    const float* be1 = (const float*)d_in[10];
    const float* W1  = (const float*)d_in[11];
    const float* bf1 = (const float*)d_in[12];
    const float* W2  = (const float*)d_in[13];
    const float* bf2 = (const float*)d_in[14];
    const float* g2  = (const float*)d_in[15];
    const float* be2 = (const float*)d_in[16];
    float* out = (float*)d_out;

    __half *wqkvT, *woT, *w1T, *w2T, *srch, *x1h, *qkvh, *attnh, *ffn1h, *mhah, *ffn2h;
    float *bqkv, *x1;
    cudaGetSymbolAddress((void**)&wqkvT, g_wqkvT);
    cudaGetSymbolAddress((void**)&bqkv,  g_bqkv);
    cudaGetSymbolAddress((void**)&woT,   g_woT);
    cudaGetSymbolAddress((void**)&w1T,   g_w1T);
    cudaGetSymbolAddress((void**)&w2T,   g_w2T);
    cudaGetSymbolAddress((void**)&srch,  g_srch);
    cudaGetSymbolAddress((void**)&x1h,   g_x1h);
    cudaGetSymbolAddress((void**)&qkvh,  g_qkvh);
    cudaGetSymbolAddress((void**)&attnh, g_attnh);
    cudaGetSymbolAddress((void**)&ffn1h, g_ffn1h);
    cudaGetSymbolAddress((void**)&mhah,  g_mhah);
    cudaGetSymbolAddress((void**)&ffn2h, g_ffn2h);
    cudaGetSymbolAddress((void**)&x1,    g_x1);

    const int smem256 = gemm_smem_bytes(256);   // 147456
    const int smem128 = gemm_smem_bytes(128);   // 98304
    cudaFuncSetAttribute(gemm_f16<0,1,256>, cudaFuncAttributeMaxDynamicSharedMemorySize, smem256);
    cudaFuncSetAttribute(gemm_f16<1,1,256>, cudaFuncAttributeMaxDynamicSharedMemorySize, smem256);
    cudaFuncSetAttribute(gemm_f16<0,1,128>, cudaFuncAttributeMaxDynamicSharedMemorySize, smem128);
    cudaFuncSetAttribute(attn_f16_kernel, cudaFuncAttributeMaxDynamicSharedMemorySize, ATT_SMEM);

    // 0) fused operand prep (src cvt + bias pack + all weight transposes)
    prep_all<<<PB_TOTAL, 256>>>(src, Wq, Wk, Wv, bq, bk, bv, Wo, W1, W2);

    // 1) QKV projection -> fp16 qkv   (grid 9x64 = 576)
    gemm_f16<0,1,256><<<dim3(NQKV_ / 256, M_ / BMg), 256, smem256>>>(srch, wqkvT, bqkv, qkvh, M_, NQKV_, D_);

    // 2) fused attention -> fp16 attn
    attn_f16_kernel<<<dim3(S_ / AT_BQ, H_, B_), 256, ATT_SMEM>>>(qkvh, attnh);

    // 3) output projection -> fp16 mha  (BN=128: grid 6x64 = 384, 2 CTAs/SM)
    gemm_f16<0,1,128><<<dim3(D_ / 128, M_ / BMg), 256, smem128>>>(attnh, woT, bo, mhah, M_, D_, D_);

    // 4) x1 = LN(src + mha), dual fp32 + fp16
    add_ln_kernel<1><<<M_ / 8, 256>>>(src, mhah, g1, be1, x1, x1h);

    // 5) FFN1 (+ReLU) -> fp16 ffn1  (grid 12x64 = 768)
    gemm_f16<1,1,256><<<dim3(F_ / 256, M_ / BMg), 256, smem256>>>(x1h, w1T, bf1, ffn1h, M_, F_, D_);

    // 6) FFN2 -> fp16 ffn2  (BN=128: grid 6x64 = 384, 2 CTAs/SM)
    gemm_f16<0,1,128><<<dim3(D_ / 128, M_ / BMg), 256, smem128>>>(ffn1h, w2T, bf2, ffn2h, M_, D_, F_);

    // 7) out = LN(x1 + ffn2)
    add_ln_kernel<0><<<M_ / 8, 256>>>(x1, ffn2h, g2, be2, out, nullptr);
}

// round 13
// speedup vs baseline: 8.2663x; 1.0188x over previous
#include <cuda_runtime.h>
#include <cuda_fp16.h>
#include <math.h>
#include <stdint.h>

// Problem constants
#define B_    4
#define S_    2048
#define D_    768
#define H_    12
#define DK_   64
#define F_    3072
#define M_    (B_*S_)        // 8192 rows
#define NQKV_ (3*D_)         // 2304

// ---------------- scratch (static device globals; no allocation) ----------------
__device__ __half g_wqkvT[NQKV_*D_];   // packed+transposed QKV weights [3*H*DK][D] (Wq pre-scaled by 0.125)
__device__ float  g_bqkv[NQKV_];       // packed QKV bias (fp32; bq pre-scaled by 0.125)
__device__ __half g_woT [D_*D_];       // Wo^T  [D][D]
__device__ __half g_w1T [F_*D_];       // W1^T  [F][D]
__device__ __half g_w2T [D_*F_];       // W2^T  [D][F]
__device__ __half g_srch[M_*D_];       // fp16 source
__device__ __half g_x1h [M_*D_];       // fp16 x1
__device__ __half g_qkvh[M_*NQKV_];    // fp16 qkv (q|k|v), q pre-scaled
__device__ __half g_attnh[M_*D_];      // fp16 concat-head attention out
__device__ __half g_ffn1h[M_*F_];      // fp16 relu(ffn1)
__device__ __half g_mhah [M_*D_];      // fp16 out-proj result
__device__ __half g_ffn2h[M_*D_];      // fp16 ffn2 result
__device__ float  g_x1  [M_*D_];

// ---------------- helpers ----------------
__device__ __forceinline__ void mma_f16(float* d, const uint32_t* a, const uint32_t* b) {
    asm volatile(
        "mma.sync.aligned.m16n8k16.row.col.f32.f16.f16.f32 "
        "{%0,%1,%2,%3}, {%4,%5,%6,%7}, {%8,%9}, {%0,%1,%2,%3};"
        : "+f"(d[0]), "+f"(d[1]), "+f"(d[2]), "+f"(d[3])
        : "r"(a[0]), "r"(a[1]), "r"(a[2]), "r"(a[3]), "r"(b[0]), "r"(b[1]));
}

__device__ __forceinline__ void ldsm4(uint32_t* r, uint32_t addr) {
    asm volatile("ldmatrix.sync.aligned.m8n8.x4.shared.b16 {%0,%1,%2,%3}, [%4];"
                 : "=r"(r[0]), "=r"(r[1]), "=r"(r[2]), "=r"(r[3]) : "r"(addr));
}

__device__ __forceinline__ void ldsm4t(uint32_t* r, uint32_t addr) {
    asm volatile("ldmatrix.sync.aligned.m8n8.x4.trans.shared.b16 {%0,%1,%2,%3}, [%4];"
                 : "=r"(r[0]), "=r"(r[1]), "=r"(r[2]), "=r"(r[3]) : "r"(addr));
}

__device__ __forceinline__ void cp_async16(uint32_t smem_dst, const void* gmem_src) {
    asm volatile("cp.async.cg.shared.global [%0], [%1], 16;" :: "r"(smem_dst), "l"(gmem_src));
}
#define CP_COMMIT() asm volatile("cp.async.commit_group;")
#define CP_WAIT0()  asm volatile("cp.async.wait_group 0;")
#define CP_WAIT1()  asm volatile("cp.async.wait_group 1;")

__device__ __forceinline__ uint32_t h2u(__half2 h) { return *reinterpret_cast<uint32_t*>(&h); }

__device__ __forceinline__ uint32_t ex2_f16x2(uint32_t x) {
    uint32_t r;
    asm("ex2.approx.f16x2 %0, %1;" : "=r"(r) : "r"(x));
    return r;
}

// ---------------- fused prep kernel: src cvt + bias pack + all weight transposes ----------------
// block-job dispatch; 256 threads/block.
#define PB_CVT   6144                       // M_*D_/4/256
#define PB_BIAS  9                          // ceil(2304/256)
#define PB_WO    576                        // (768/32)*(768/32)
#define PB_W1    2304                       // (3072/32)*(768/32)
#define PB_W2    2304                       // (768/32)*(3072/32)
#define PB_QKV   1728                       // 36 * (64/32)*(768/32)
#define PB_TOTAL (PB_CVT + PB_BIAS + PB_WO + PB_W1 + PB_W2 + PB_QKV)

__global__ __launch_bounds__(256) void prep_all(
    const float* __restrict__ src,
    const float* __restrict__ Wq, const float* __restrict__ Wk, const float* __restrict__ Wv,
    const float* __restrict__ bq, const float* __restrict__ bk, const float* __restrict__ bv,
    const float* __restrict__ Wo, const float* __restrict__ W1, const float* __restrict__ W2)
{
    int bid = blockIdx.x;
    const int t = threadIdx.x;

    if (bid < PB_CVT) {                     // src fp32 -> fp16
        int i = bid * 256 + t;              // float4 index
        float4 v = *(const float4*)(src + (size_t)i * 4);
        uint2 o;
        o.x = h2u(__floats2half2_rn(v.x, v.y));
        o.y = h2u(__floats2half2_rn(v.z, v.w));
        *(uint2*)(g_srch + (size_t)i * 4) = o;
        return;
    }
    bid -= PB_CVT;
    if (bid < PB_BIAS) {                    // qkv bias pack (bq scaled by 0.125)
        int idx = bid * 256 + t;
        if (idx < NQKV_) {
            int wh = idx / D_, jj = idx % D_;
            const float* bsrc = (wh == 0) ? bq : (wh == 1) ? bk : bv;
            float sc = (wh == 0) ? 0.125f : 1.0f;
            g_bqkv[idx] = bsrc[jj] * sc;
        }
        return;
    }
    bid -= PB_BIAS;

    // ---- transpose jobs: 32x32 tile, (32,8) thread view ----
    __shared__ float tile[32][33];
    const int tx = t & 31, ty = t >> 5;

    const float* in; __half* out;
    int C, r0, c0, obase, outLD;
    float wscale = 1.0f;
    if (bid < PB_WO) {                      // Wo [768,768] -> woT
        in = Wo; out = g_woT; C = D_; outLD = D_; obase = 0;
        c0 = (bid % 24) * 32; r0 = (bid / 24) * 32;
    } else if (bid < PB_WO + PB_W1) {       // W1 [768,3072] -> w1T
        bid -= PB_WO;
        in = W1; out = g_w1T; C = F_; outLD = D_; obase = 0;
        c0 = (bid % 96) * 32; r0 = (bid / 96) * 32;
    } else if (bid < PB_WO + PB_W1 + PB_W2) {  // W2 [3072,768] -> w2T
        bid -= PB_WO + PB_W1;
        in = W2; out = g_w2T; C = D_; outLD = F_; obase = 0;
        c0 = (bid % 24) * 32; r0 = (bid / 24) * 32;
    } else {                                // QKV weights [H,D,DK]x3 -> wqkvT (Wq x0.125)
        bid -= PB_WO + PB_W1 + PB_W2;
        const int z = bid / 48;             // 0..35
        const int j = bid % 48;             // 2 x 24 tiles
        const int wh = z / H_, h = z % H_;
        in = ((wh == 0) ? Wq : (wh == 1) ? Wk : Wv) + (size_t)h * D_ * DK_;
        out = g_wqkvT; C = DK_; outLD = D_;
        obase = wh * D_ + h * DK_;
        if (wh == 0) wscale = 0.125f;
        c0 = (j % 2) * 32; r0 = (j / 2) * 32;
    }

#pragma unroll
    for (int i = 0; i < 32; i += 8)
        tile[ty + i][tx] = in[(size_t)(r0 + ty + i) * C + c0 + tx];
    __syncthreads();
#pragma unroll
    for (int i = 0; i < 32; i += 8)
        out[(size_t)(obase + c0 + ty + i) * outLD + r0 + tx] =
            __float2half_rn(tile[tx][ty + i] * wscale);
}

// ---------------- FP16 tensor-core GEMM: ldmatrix + cp.async, 3 stages ----------------
// C[M,N] = A[M,K] @ Bt[N,K]^T + bias. CTA 128xBN, BK=64 halves, 8 warps (2 x 4),
// warp tile 64x(BN/4), mma.m16n8k16. BN=256 (1 CTA/SM) or BN=128 (2 CTAs/SM).
#define BMg 128
#define BKg 64
#define STAGES 3
#define A_CHUNKS (BMg*8)                   // 16B chunks per stage

constexpr int gemm_smem_bytes(int BN) { return STAGES * (A_CHUNKS + BN * 8) * 16; }

template<int RELU, int OUTH, int BN>
__global__ __launch_bounds__(256, (BN == 128) ? 2 : 1) void gemm_f16(
    const __half* __restrict__ A, const __half* __restrict__ Bt,
    const float* __restrict__ bias, void* __restrict__ Cv,
    int M, int N, int K)
{
    constexpr int B_CHUNKS = BN * 8;
    constexpr int STAGE_CHUNKS = A_CHUNKS + B_CHUNKS;
    constexpr int WN = BN / 4;       // warp tile N (64 or 32)
    constexpr int NT = WN / 8;       // n8 tiles per warp (8 or 4)
    constexpr int NB = WN / 16;      // 16-col ldsm groups (4 or 2)

    extern __shared__ uint4 smem4[];
    const uint32_t smem_base = (uint32_t)__cvta_generic_to_shared(smem4);

    const int t    = threadIdx.x;
    const int lane = t & 31;
    const int wid  = t >> 5;
    const int wm   = wid & 1;     // 0..1 (64-row slab)
    const int wn   = wid >> 1;    // 0..3 (WN-col slab)
    const int rowC = blockIdx.y * BMg;
    const int colC = blockIdx.x * BN;

    float acc[4][NT][4];
#pragma unroll
    for (int i = 0; i < 4; i++)
#pragma unroll
        for (int j = 0; j < NT; j++)
#pragma unroll
            for (int r = 0; r < 4; r++) acc[i][j][r] = 0.f;

    const int ntiles = K / BKg;

    auto load_tile = [&](int stage, int kt) {
        const uint32_t sa = smem_base + stage * (STAGE_CHUNKS * 16);
#pragma unroll
        for (int i = 0; i < 4; i++) {
            int lin = i * 256 + t;
            int m = lin >> 3, c = lin & 7;
            uint32_t dst = sa + (uint32_t)(m * 8 + (c ^ (m & 7))) * 16;
            cp_async16(dst, A + (size_t)(rowC + m) * K + kt * BKg + c * 8);
        }
#pragma unroll
        for (int i = 0; i < B_CHUNKS / 256; i++) {
            int lin = i * 256 + t;
            int n = lin >> 3, c = lin & 7;
            uint32_t dst = sa + (uint32_t)(A_CHUNKS + n * 8 + (c ^ (n & 7))) * 16;
            cp_async16(dst, Bt + (size_t)(colC + n) * K + kt * BKg + c * 8);
        }
        CP_COMMIT();
    };

    load_tile(0, 0);
    load_tile(1, 1);

    const int lr = lane & 15;
    const int hi = lane >> 4;
    const int x7 = lane & 7;
    uint32_t aRowOff[4], bRowOff[NB];
#pragma unroll
    for (int mt = 0; mt < 4; mt++)
        aRowOff[mt] = (uint32_t)(wm * 64 + mt * 16 + lr) * 128;
#pragma unroll
    for (int nb = 0; nb < NB; nb++)
        bRowOff[nb] = (uint32_t)(A_CHUNKS * 16) + (uint32_t)(wn * WN + nb * 16 + lr) * 128;

    for (int kt = 0; kt < ntiles; kt++) {
        CP_WAIT1();
        __syncthreads();

        const int nxt = kt + STAGES - 1;
        if (nxt < ntiles) load_tile(nxt % STAGES, nxt);
        else              CP_COMMIT();

        const uint32_t sa = smem_base + (kt % STAGES) * (STAGE_CHUNKS * 16);
#pragma unroll
        for (int kk = 0; kk < 4; kk++) {
            const uint32_t cx = (uint32_t)(((2 * kk + hi) ^ x7) * 16);
            uint32_t a[4][4], bfr[NB][4];
#pragma unroll
            for (int mt = 0; mt < 4; mt++)
                ldsm4(a[mt], sa + aRowOff[mt] + cx);
#pragma unroll
            for (int nb = 0; nb < NB; nb++)
                ldsm4(bfr[nb], sa + bRowOff[nb] + cx);
#pragma unroll
            for (int mt = 0; mt < 4; mt++)
#pragma unroll
                for (int nt = 0; nt < NT; nt++) {
                    uint32_t bb[2];
                    bb[0] = bfr[nt >> 1][(nt & 1)];
                    bb[1] = bfr[nt >> 1][2 + (nt & 1)];
                    mma_f16(acc[mt][nt], a[mt], bb);
                }
        }
    }

    // epilogue
    const int g2 = lane >> 2, q2 = lane & 3;
#pragma unroll
    for (int mt = 0; mt < 4; mt++) {
        const int r0 = rowC + wm * 64 + mt * 16 + g2;
#pragma unroll
        for (int nt = 0; nt < NT; nt++) {
            const int c = colC + wn * WN + nt * 8 + 2 * q2;
            const float b0v = bias[c], b1v = bias[c + 1];
            float o00 = acc[mt][nt][0] + b0v, o01 = acc[mt][nt][1] + b1v;
            float o10 = acc[mt][nt][2] + b0v, o11 = acc[mt][nt][3] + b1v;
            if (RELU) {
                o00 = fmaxf(o00, 0.f); o01 = fmaxf(o01, 0.f);
                o10 = fmaxf(o10, 0.f); o11 = fmaxf(o11, 0.f);
            }
            if (OUTH) {
                __half* Ch = (__half*)Cv;
                *(uint32_t*)(Ch + (size_t)r0 * N + c)       = h2u(__floats2half2_rn(o00, o01));
                *(uint32_t*)(Ch + (size_t)(r0 + 8) * N + c) = h2u(__floats2half2_rn(o10, o11));
            } else {
                float* Cf = (float*)Cv;
                *(float2*)(Cf + (size_t)r0 * N + c)       = make_float2(o00, o01);
                *(float2*)(Cf + (size_t)(r0 + 8) * N + c) = make_float2(o10, o11);
            }
        }
    }
}

// ---------------- FP16 mma flash attention (register-P, f16x2 ex2 softmax) ----------------
#define AT_BQ 128
#define AT_BK 64
#define ATQ_BYTES (AT_BQ * 64 * 2)          // 16384
#define ATKV_STAGE (AT_BK * 64 * 2 * 2)     // 16384 (K+V)
#define ATT_SMEM (ATQ_BYTES + 2 * ATKV_STAGE)

__global__ __launch_bounds__(256) void attn_f16_kernel(
    const __half* __restrict__ qkv, __half* __restrict__ out)
{
    extern __shared__ uint4 smemA[];
    const uint32_t sb = (uint32_t)__cvta_generic_to_shared(smemA);

    const int t    = threadIdx.x;
    const int w    = t >> 5;
    const int lane = t & 31;
    const int g    = lane >> 2;
    const int q    = lane & 3;
    const int lr   = lane & 15;
    const int hi   = lane >> 4;
    const int x7   = lane & 7;
    const int qb = blockIdx.x, h = blockIdx.y, b = blockIdx.z;

    const __half* qg = qkv + (size_t)(b * S_ + qb * AT_BQ) * NQKV_ + h * DK_;

#pragma unroll
    for (int i = 0; i < 4; i++) {
        int lin = i * 256 + t;
        int row = lin >> 3, c = lin & 7;
        uint32_t dst = sb + (uint32_t)(row * 8 + (c ^ (row & 7))) * 16;
        cp_async16(dst, qg + (size_t)row * NQKV_ + c * 8);
    }
    CP_COMMIT();
    CP_WAIT0();
    __syncthreads();

    // Q fragments (already pre-scaled by 1/8 at the weight level)
    uint32_t qa[4][4];
    {
        const uint32_t qRowOff = (uint32_t)(w * 16 + lr) * 128;
#pragma unroll
        for (int kb2 = 0; kb2 < 4; kb2++)
            ldsm4(qa[kb2], sb + qRowOff + (uint32_t)(((2 * kb2 + hi) ^ x7) * 16));
    }

    float m0 = -3.0e38f, m1 = -3.0e38f, l0 = 0.f, l1 = 0.f;
    float o[8][4];
#pragma unroll
    for (int nt = 0; nt < 8; nt++)
#pragma unroll
        for (int r = 0; r < 4; r++) o[nt][r] = 0.f;

    const __half* kg = qkv + (size_t)b * S_ * NQKV_ + D_ + h * DK_;

    auto loadKV = [&](int stage, int kb) {
        const uint32_t sbase = sb + ATQ_BYTES + stage * ATKV_STAGE;
        const __half* kr = kg + (size_t)(kb * AT_BK) * NQKV_;
#pragma unroll
        for (int i = 0; i < 2; i++) {
            int lin = i * 256 + t;
            int row = lin >> 3, c = lin & 7;
            uint32_t sw = (uint32_t)(row * 8 + (c ^ (row & 7))) * 16;
            const __half* kp = kr + (size_t)row * NQKV_ + c * 8;
            cp_async16(sbase + sw, kp);
            cp_async16(sbase + (AT_BK * 64 * 2) + sw, kp + D_);
        }
        CP_COMMIT();
    };

    const int NTILES = S_ / AT_BK;   // 32
    int buf = 0;
    loadKV(0, 0);

    const float L2E = 1.4426950408889634f;

    for (int kb = 0; kb < NTILES; kb++) {
        const bool more = (kb + 1) < NTILES;
        if (more) loadKV(buf ^ 1, kb + 1);
        if (more) { CP_WAIT1(); } else { CP_WAIT0(); }
        __syncthreads();

        const uint32_t kbase = sb + ATQ_BYTES + buf * ATKV_STAGE;
        const uint32_t vbase = kbase + AT_BK * 64 * 2;

        float s[8][4];
#pragma unroll
        for (int nt = 0; nt < 8; nt++)
#pragma unroll
            for (int r = 0; r < 4; r++) s[nt][r] = 0.f;

#pragma unroll
        for (int nb = 0; nb < 4; nb++) {
            uint32_t kf[4][4];
            const uint32_t kro = (uint32_t)(nb * 16 + lr) * 128;
#pragma unroll
            for (int kb2 = 0; kb2 < 4; kb2++)
                ldsm4(kf[kb2], kbase + kro + (uint32_t)(((2 * kb2 + hi) ^ x7) * 16));
#pragma unroll
            for (int kb2 = 0; kb2 < 4; kb2++) {
                uint32_t b0[2] = { kf[kb2][0], kf[kb2][2] };
                uint32_t b1[2] = { kf[kb2][1], kf[kb2][3] };
                mma_f16(s[2 * nb],     qa[kb2], b0);
                mma_f16(s[2 * nb + 1], qa[kb2], b1);
            }
        }

        // online softmax
        float mx0 = -3.0e38f, mx1 = -3.0e38f;
#pragma unroll
        for (int nt = 0; nt < 8; nt++) {
            mx0 = fmaxf(mx0, fmaxf(s[nt][0], s[nt][1]));
            mx1 = fmaxf(mx1, fmaxf(s[nt][2], s[nt][3]));
        }
        mx0 = fmaxf(mx0, __shfl_xor_sync(0xffffffffu, mx0, 1));
        mx0 = fmaxf(mx0, __shfl_xor_sync(0xffffffffu, mx0, 2));
        mx1 = fmaxf(mx1, __shfl_xor_sync(0xffffffffu, mx1, 1));
        mx1 = fmaxf(mx1, __shfl_xor_sync(0xffffffffu, mx1, 2));

        const float mn0 = fmaxf(m0, mx0), mn1 = fmaxf(m1, mx1);
        const float f0 = __expf(m0 - mn0), f1 = __expf(m1 - mn1);
        m0 = mn0; m1 = mn1;

        // p = exp2((s - mn) * log2e) computed in f16x2 (P lands in fp16 anyway)
        const float a0 = mn0 * L2E, a1 = mn1 * L2E;
        uint32_t pa[4][4];
        float ls0 = 0.f, ls1 = 0.f;
#pragma unroll
        for (int nt = 0; nt < 8; nt++) {
            float t00 = fmaf(s[nt][0], L2E, -a0);
            float t01 = fmaf(s[nt][1], L2E, -a0);
            float t10 = fmaf(s[nt][2], L2E, -a1);
            float t11 = fmaf(s[nt][3], L2E, -a1);
            uint32_t p0 = ex2_f16x2(h2u(__floats2half2_rn(t00, t01)));
            uint32_t p1 = ex2_f16x2(h2u(__floats2half2_rn(t10, t11)));
            if (nt & 1) { pa[nt >> 1][2] = p0; pa[nt >> 1][3] = p1; }
            else        { pa[nt >> 1][0] = p0; pa[nt >> 1][1] = p1; }
            float2 q0 = __half22float2(*reinterpret_cast<__half2*>(&p0));
            float2 q1 = __half22float2(*reinterpret_cast<__half2*>(&p1));
            ls0 += q0.x + q0.y;
            ls1 += q1.x + q1.y;
        }
        ls0 += __shfl_xor_sync(0xffffffffu, ls0, 1);
        ls0 += __shfl_xor_sync(0xffffffffu, ls0, 2);
        ls1 += __shfl_xor_sync(0xffffffffu, ls1, 1);
        ls1 += __shfl_xor_sync(0xffffffffu, ls1, 2);
        l0 = l0 * f0 + ls0;
        l1 = l1 * f1 + ls1;

#pragma unroll
        for (int nt = 0; nt < 8; nt++) {
            o[nt][0] *= f0; o[nt][1] *= f0;
            o[nt][2] *= f1; o[nt][3] *= f1;
        }

        // O += P @ V  (V via ldmatrix.trans)
#pragma unroll
        for (int nb2 = 0; nb2 < 4; nb2++) {
            const uint32_t cxv = (uint32_t)(((2 * nb2 + hi) ^ x7) * 16);
#pragma unroll
            for (int kb2 = 0; kb2 < 4; kb2++) {
                uint32_t vf[4];
                ldsm4t(vf, vbase + (uint32_t)(kb2 * 16 + lr) * 128 + cxv);
                uint32_t b0[2] = { vf[0], vf[1] };
                uint32_t b1[2] = { vf[2], vf[3] };
                mma_f16(o[2 * nb2],     pa[kb2], b0);
                mma_f16(o[2 * nb2 + 1], pa[kb2], b1);
            }
        }

        __syncthreads();
        buf ^= 1;
    }

    const float i0 = 1.0f / l0, i1 = 1.0f / l1;
    __half* op = out + (size_t)(b * S_ + qb * AT_BQ + w * 16) * D_ + h * DK_;
#pragma unroll
    for (int nt = 0; nt < 8; nt++) {
        const int c = nt * 8 + 2 * q;
        *(uint32_t*)(op + (size_t)g * D_ + c) =
            h2u(__floats2half2_rn(o[nt][0] * i0, o[nt][1] * i0));
        *(uint32_t*)(op + (size_t)(g + 8) * D_ + c) =
            h2u(__floats2half2_rn(o[nt][2] * i1, o[nt][3] * i1));
    }
}

// ---------------- fused residual-add + LayerNorm: warp-per-row, float4, shuffle-only ----------------
// A is fp32 (residual), Bv is fp16 (GEMM output).
template<int DUAL>
__global__ __launch_bounds__(256) void add_ln_kernel(
    const float* __restrict__ A, const __half* __restrict__ Bv,
    const float* __restrict__ gamma, const float* __restrict__ beta,
    float* __restrict__ out, __half* __restrict__ outh)
{
    const int w    = threadIdx.x >> 5;
    const int lane = threadIdx.x & 31;
    const int row  = blockIdx.x * 8 + w;

    const float*  pa = A  + (size_t)row * D_;
    const __half* pb = Bv + (size_t)row * D_;

    float4 v[6];
    float s = 0.f;
#pragma unroll
    for (int i = 0; i < 6; i++) {
        const int off = (i * 32 + lane) * 4;
        float4 a4 = *(const float4*)(pa + off);
        uint2 bh = *(const uint2*)(pb + off);
        float2 b0 = __half22float2(*reinterpret_cast<__half2*>(&bh.x));
        float2 b1 = __half22float2(*reinterpret_cast<__half2*>(&bh.y));
        v[i].x = a4.x + b0.x; v[i].y = a4.y + b0.y;
        v[i].z = a4.z + b1.x; v[i].w = a4.w + b1.y;
        s += v[i].x + v[i].y + v[i].z + v[i].w;
    }
#pragma unroll
    for (int mk = 16; mk; mk >>= 1) s += __shfl_xor_sync(0xffffffffu, s, mk);
    const float mean = s * (1.0f / D_);

    float qv = 0.f;
#pragma unroll
    for (int i = 0; i < 6; i++) {
        v[i].x -= mean; v[i].y -= mean; v[i].z -= mean; v[i].w -= mean;
        qv += v[i].x * v[i].x + v[i].y * v[i].y + v[i].z * v[i].z + v[i].w * v[i].w;
    }
#pragma unroll
    for (int mk = 16; mk; mk >>= 1) qv += __shfl_xor_sync(0xffffffffu, qv, mk);
    const float rstd = rsqrtf(qv * (1.0f / D_) + 1e-5f);

    float* po = out + (size_t)row * D_;
    __half* ph = DUAL ? (outh + (size_t)row * D_) : nullptr;
#pragma unroll
    for (int i = 0; i < 6; i++) {
        const int off = (i * 32 + lane) * 4;
        float4 g4 = *(const float4*)(gamma + off);
        float4 e4 = *(const float4*)(beta + off);
        float4 r;
        r.x = v[i].x * rstd * g4.x + e4.x;
        r.y = v[i].y * rstd * g4.y + e4.y;
        r.z = v[i].z * rstd * g4.z + e4.z;
        r.w = v[i].w * rstd * g4.w + e4.w;
        *(float4*)(po + off) = r;
        if (DUAL) {
            uint2 hh;
            hh.x = h2u(__floats2half2_rn(r.x, r.y));
            hh.y = h2u(__floats2half2_rn(r.z, r.w));
            *(uint2*)(ph + off) = hh;
        }
    }
}

// ---------------- launch ----------------
extern "C" void kernel_launch(void* const* d_in, const int* in_sizes, int n_in,
                              void* d_out, int out_size)
{
    const float* src = (const float*)d_in[0];
    const float* Wq  = (const float*)d_in[1];
    const float* bq  = (const float*)d_in[2];
    const float* Wk  = (const float*)d_in[3];
    const float* bk  = (const float*)d_in[4];
    const float* Wv  = (const float*)d_in[5];
    const float* bv  = (const float*)d_in[6];
    const float* Wo  = (const float*)d_in[7];
    const float* bo  = (const float*)d_in[8];
    const float* g1  = (const float*)d_in[9];
    const float* be1 = (const float*)d_in[10];
    const float* W1  = (const float*)d_in[11];
    const float* bf1 = (const float*)d_in[12];
    const float* W2  = (const float*)d_in[13];
    const float* bf2 = (const float*)d_in[14];
    const float* g2  = (const float*)d_in[15];
    const float* be2 = (const float*)d_in[16];
    float* out = (float*)d_out;

    __half *wqkvT, *woT, *w1T, *w2T, *srch, *x1h, *qkvh, *attnh, *ffn1h, *mhah, *ffn2h;
    float *bqkv, *x1;
    cudaGetSymbolAddress((void**)&wqkvT, g_wqkvT);
    cudaGetSymbolAddress((void**)&bqkv,  g_bqkv);
    cudaGetSymbolAddress((void**)&woT,   g_woT);
    cudaGetSymbolAddress((void**)&w1T,   g_w1T);
    cudaGetSymbolAddress((void**)&w2T,   g_w2T);
    cudaGetSymbolAddress((void**)&srch,  g_srch);
    cudaGetSymbolAddress((void**)&x1h,   g_x1h);
    cudaGetSymbolAddress((void**)&qkvh,  g_qkvh);
    cudaGetSymbolAddress((void**)&attnh, g_attnh);
    cudaGetSymbolAddress((void**)&ffn1h, g_ffn1h);
    cudaGetSymbolAddress((void**)&mhah,  g_mhah);
    cudaGetSymbolAddress((void**)&ffn2h, g_ffn2h);
    cudaGetSymbolAddress((void**)&x1,    g_x1);

    const int smem256 = gemm_smem_bytes(256);   // 147456
    const int smem128 = gemm_smem_bytes(128);   // 98304
    cudaFuncSetAttribute(gemm_f16<0,1,256>, cudaFuncAttributeMaxDynamicSharedMemorySize, smem256);
    cudaFuncSetAttribute(gemm_f16<1,1,256>, cudaFuncAttributeMaxDynamicSharedMemorySize, smem256);
    cudaFuncSetAttribute(gemm_f16<0,1,128>, cudaFuncAttributeMaxDynamicSharedMemorySize, smem128);
    cudaFuncSetAttribute(attn_f16_kernel, cudaFuncAttributeMaxDynamicSharedMemorySize, ATT_SMEM);

    // 0) fused operand prep (src cvt + bias pack + all weight transposes; Wq/bq pre-scaled 1/8)
    prep_all<<<PB_TOTAL, 256>>>(src, Wq, Wk, Wv, bq, bk, bv, Wo, W1, W2);

    // 1) QKV projection -> fp16 qkv   (grid 9x64 = 576)
    gemm_f16<0,1,256><<<dim3(NQKV_ / 256, M_ / BMg), 256, smem256>>>(srch, wqkvT, bqkv, qkvh, M_, NQKV_, D_);

    // 2) fused attention -> fp16 attn
    attn_f16_kernel<<<dim3(S_ / AT_BQ, H_, B_), 256, ATT_SMEM>>>(qkvh, attnh);

    // 3) output projection -> fp16 mha  (BN=128: grid 6x64 = 384, 2 CTAs/SM)
    gemm_f16<0,1,128><<<dim3(D_ / 128, M_ / BMg), 256, smem128>>>(attnh, woT, bo, mhah, M_, D_, D_);

    // 4) x1 = LN(src + mha), dual fp32 + fp16
    add_ln_kernel<1><<<M_ / 8, 256>>>(src, mhah, g1, be1, x1, x1h);

    // 5) FFN1 (+ReLU) -> fp16 ffn1  (grid 12x64 = 768)
    gemm_f16<1,1,256><<<dim3(F_ / 256, M_ / BMg), 256, smem256>>>(x1h, w1T, bf1, ffn1h, M_, F_, D_);

    // 6) FFN2 -> fp16 ffn2  (BN=128: grid 6x64 = 384, 2 CTAs/SM)
    gemm_f16<0,1,128><<<dim3(D_ / 128, M_ / BMg), 256, smem128>>>(ffn1h, w2T, bf2, ffn2h, M_, D_, F_);

    // 7) out = LN(x1 + ffn2)
    add_ln_kernel<0><<<M_ / 8, 256>>>(x1, ffn2h, g2, be2, out, nullptr);
}

// round 14
// speedup vs baseline: 8.4160x; 1.0181x over previous
#include <cuda_runtime.h>
#include <cuda_fp16.h>
#include <math.h>
#include <stdint.h>

// Problem constants
#define B_    4
#define S_    2048
#define D_    768
#define H_    12
#define DK_   64
#define F_    3072
#define M_    (B_*S_)        // 8192 rows
#define NQKV_ (3*D_)         // 2304

// ---------------- scratch (static device globals; no allocation) ----------------
__device__ __half g_wqkvT[NQKV_*D_];   // packed+transposed QKV weights [3*H*DK][D] (Wq pre-scaled by 0.125)
__device__ float  g_bqkv[NQKV_];       // packed QKV bias (fp32; bq pre-scaled by 0.125)
__device__ __half g_woT [D_*D_];       // Wo^T  [D][D]
__device__ __half g_w1T [F_*D_];       // W1^T  [F][D]
__device__ __half g_w2T [D_*F_];       // W2^T  [D][F]
__device__ __half g_srch[M_*D_];       // fp16 source
__device__ __half g_x1h [M_*D_];       // fp16 x1
__device__ __half g_qkvh[M_*NQKV_];    // fp16 qkv (q|k|v), q pre-scaled
__device__ __half g_attnh[M_*D_];      // fp16 concat-head attention out
__device__ __half g_ffn1h[M_*F_];      // fp16 relu(ffn1)
__device__ __half g_mhah [M_*D_];      // fp16 out-proj result
__device__ __half g_ffn2h[M_*D_];      // fp16 ffn2 result
__device__ float  g_x1  [M_*D_];

// ---------------- helpers ----------------
__device__ __forceinline__ void mma_f16(float* d, const uint32_t* a, const uint32_t* b) {
    asm volatile(
        "mma.sync.aligned.m16n8k16.row.col.f32.f16.f16.f32 "
        "{%0,%1,%2,%3}, {%4,%5,%6,%7}, {%8,%9}, {%0,%1,%2,%3};"
        : "+f"(d[0]), "+f"(d[1]), "+f"(d[2]), "+f"(d[3])
        : "r"(a[0]), "r"(a[1]), "r"(a[2]), "r"(a[3]), "r"(b[0]), "r"(b[1]));
}

__device__ __forceinline__ void ldsm4(uint32_t* r, uint32_t addr) {
    asm volatile("ldmatrix.sync.aligned.m8n8.x4.shared.b16 {%0,%1,%2,%3}, [%4];"
                 : "=r"(r[0]), "=r"(r[1]), "=r"(r[2]), "=r"(r[3]) : "r"(addr));
}

__device__ __forceinline__ void ldsm4t(uint32_t* r, uint32_t addr) {
    asm volatile("ldmatrix.sync.aligned.m8n8.x4.trans.shared.b16 {%0,%1,%2,%3}, [%4];"
                 : "=r"(r[0]), "=r"(r[1]), "=r"(r[2]), "=r"(r[3]) : "r"(addr));
}

__device__ __forceinline__ void cp_async16(uint32_t smem_dst, const void* gmem_src) {
    asm volatile("cp.async.cg.shared.global [%0], [%1], 16;" :: "r"(smem_dst), "l"(gmem_src));
}
#define CP_COMMIT() asm volatile("cp.async.commit_group;")
#define CP_WAIT0()  asm volatile("cp.async.wait_group 0;")
#define CP_WAIT1()  asm volatile("cp.async.wait_group 1;")

__device__ __forceinline__ uint32_t h2u(__half2 h) { return *reinterpret_cast<uint32_t*>(&h); }

__device__ __forceinline__ uint32_t ex2_f16x2(uint32_t x) {
    uint32_t r;
    asm("ex2.approx.f16x2 %0, %1;" : "=r"(r) : "r"(x));
    return r;
}

// ---------------- fused prep kernel: src cvt + bias pack + all weight transposes ----------------
// block-job dispatch; 256 threads/block.
#define PB_CVT   6144                       // M_*D_/4/256
#define PB_BIAS  9                          // ceil(2304/256)
#define PB_WO    576                        // (768/32)*(768/32)
#define PB_W1    2304                       // (3072/32)*(768/32)
#define PB_W2    2304                       // (768/32)*(3072/32)
#define PB_QKV   1728                       // 36 * (64/32)*(768/32)
#define PB_TOTAL (PB_CVT + PB_BIAS + PB_WO + PB_W1 + PB_W2 + PB_QKV)

__global__ __launch_bounds__(256) void prep_all(
    const float* __restrict__ src,
    const float* __restrict__ Wq, const float* __restrict__ Wk, const float* __restrict__ Wv,
    const float* __restrict__ bq, const float* __restrict__ bk, const float* __restrict__ bv,
    const float* __restrict__ Wo, const float* __restrict__ W1, const float* __restrict__ W2)
{
    int bid = blockIdx.x;
    const int t = threadIdx.x;

    if (bid < PB_CVT) {                     // src fp32 -> fp16
        int i = bid * 256 + t;              // float4 index
        float4 v = *(const float4*)(src + (size_t)i * 4);
        uint2 o;
        o.x = h2u(__floats2half2_rn(v.x, v.y));
        o.y = h2u(__floats2half2_rn(v.z, v.w));
        *(uint2*)(g_srch + (size_t)i * 4) = o;
        return;
    }
    bid -= PB_CVT;
    if (bid < PB_BIAS) {                    // qkv bias pack (bq scaled by 0.125)
        int idx = bid * 256 + t;
        if (idx < NQKV_) {
            int wh = idx / D_, jj = idx % D_;
            const float* bsrc = (wh == 0) ? bq : (wh == 1) ? bk : bv;
            float sc = (wh == 0) ? 0.125f : 1.0f;
            g_bqkv[idx] = bsrc[jj] * sc;
        }
        return;
    }
    bid -= PB_BIAS;

    // ---- transpose jobs: 32x32 tile, (32,8) thread view ----
    __shared__ float tile[32][33];
    const int tx = t & 31, ty = t >> 5;

    const float* in; __half* out;
    int C, r0, c0, obase, outLD;
    float wscale = 1.0f;
    if (bid < PB_WO) {                      // Wo [768,768] -> woT
        in = Wo; out = g_woT; C = D_; outLD = D_; obase = 0;
        c0 = (bid % 24) * 32; r0 = (bid / 24) * 32;
    } else if (bid < PB_WO + PB_W1) {       // W1 [768,3072] -> w1T
        bid -= PB_WO;
        in = W1; out = g_w1T; C = F_; outLD = D_; obase = 0;
        c0 = (bid % 96) * 32; r0 = (bid / 96) * 32;
    } else if (bid < PB_WO + PB_W1 + PB_W2) {  // W2 [3072,768] -> w2T
        bid -= PB_WO + PB_W1;
        in = W2; out = g_w2T; C = D_; outLD = F_; obase = 0;
        c0 = (bid % 24) * 32; r0 = (bid / 24) * 32;
    } else {                                // QKV weights [H,D,DK]x3 -> wqkvT (Wq x0.125)
        bid -= PB_WO + PB_W1 + PB_W2;
        const int z = bid / 48;             // 0..35
        const int j = bid % 48;             // 2 x 24 tiles
        const int wh = z / H_, h = z % H_;
        in = ((wh == 0) ? Wq : (wh == 1) ? Wk : Wv) + (size_t)h * D_ * DK_;
        out = g_wqkvT; C = DK_; outLD = D_;
        obase = wh * D_ + h * DK_;
        if (wh == 0) wscale = 0.125f;
        c0 = (j % 2) * 32; r0 = (j / 2) * 32;
    }

#pragma unroll
    for (int i = 0; i < 32; i += 8)
        tile[ty + i][tx] = in[(size_t)(r0 + ty + i) * C + c0 + tx];
    __syncthreads();
#pragma unroll
    for (int i = 0; i < 32; i += 8)
        out[(size_t)(obase + c0 + ty + i) * outLD + r0 + tx] =
            __float2half_rn(tile[tx][ty + i] * wscale);
}

// ---------------- FP16 tensor-core GEMM: ldmatrix + cp.async, 3 stages ----------------
// C[M,N] = A[M,K] @ Bt[N,K]^T + bias. CTA 128xBN, BK=64 halves, 8 warps (2 x 4),
// warp tile 64x(BN/4), mma.m16n8k16. BN=256 (1 CTA/SM) or BN=128 (2 CTAs/SM).
#define BMg 128
#define BKg 64
#define STAGES 3
#define A_CHUNKS (BMg*8)                   // 16B chunks per stage

constexpr int gemm_smem_bytes(int BN) { return STAGES * (A_CHUNKS + BN * 8) * 16; }

template<int RELU, int OUTH, int BN>
__global__ __launch_bounds__(256, (BN == 128) ? 2 : 1) void gemm_f16(
    const __half* __restrict__ A, const __half* __restrict__ Bt,
    const float* __restrict__ bias, void* __restrict__ Cv,
    int M, int N, int K)
{
    constexpr int B_CHUNKS = BN * 8;
    constexpr int STAGE_CHUNKS = A_CHUNKS + B_CHUNKS;
    constexpr int WN = BN / 4;       // warp tile N (64 or 32)
    constexpr int NT = WN / 8;       // n8 tiles per warp (8 or 4)
    constexpr int NB = WN / 16;      // 16-col ldsm groups (4 or 2)

    extern __shared__ uint4 smem4[];
    const uint32_t smem_base = (uint32_t)__cvta_generic_to_shared(smem4);

    const int t    = threadIdx.x;
    const int lane = t & 31;
    const int wid  = t >> 5;
    const int wm   = wid & 1;     // 0..1 (64-row slab)
    const int wn   = wid >> 1;    // 0..3 (WN-col slab)
    const int rowC = blockIdx.y * BMg;
    const int colC = blockIdx.x * BN;

    float acc[4][NT][4];
#pragma unroll
    for (int i = 0; i < 4; i++)
#pragma unroll
        for (int j = 0; j < NT; j++)
#pragma unroll
            for (int r = 0; r < 4; r++) acc[i][j][r] = 0.f;

    const int ntiles = K / BKg;

    auto load_tile = [&](int stage, int kt) {
        const uint32_t sa = smem_base + stage * (STAGE_CHUNKS * 16);
#pragma unroll
        for (int i = 0; i < 4; i++) {
            int lin = i * 256 + t;
            int m = lin >> 3, c = lin & 7;
            uint32_t dst = sa + (uint32_t)(m * 8 + (c ^ (m & 7))) * 16;
            cp_async16(dst, A + (size_t)(rowC + m) * K + kt * BKg + c * 8);
        }
#pragma unroll
        for (int i = 0; i < B_CHUNKS / 256; i++) {
            int lin = i * 256 + t;
            int n = lin >> 3, c = lin & 7;
            uint32_t dst = sa + (uint32_t)(A_CHUNKS + n * 8 + (c ^ (n & 7))) * 16;
            cp_async16(dst, Bt + (size_t)(colC + n) * K + kt * BKg + c * 8);
        }
        CP_COMMIT();
    };

    load_tile(0, 0);
    load_tile(1, 1);

    const int lr = lane & 15;
    const int hi = lane >> 4;
    const int x7 = lane & 7;
    uint32_t aRowOff[4], bRowOff[NB];
#pragma unroll
    for (int mt = 0; mt < 4; mt++)
        aRowOff[mt] = (uint32_t)(wm * 64 + mt * 16 + lr) * 128;
#pragma unroll
    for (int nb = 0; nb < NB; nb++)
        bRowOff[nb] = (uint32_t)(A_CHUNKS * 16) + (uint32_t)(wn * WN + nb * 16 + lr) * 128;

    for (int kt = 0; kt < ntiles; kt++) {
        CP_WAIT1();
        __syncthreads();

        const int nxt = kt + STAGES - 1;
        if (nxt < ntiles) load_tile(nxt % STAGES, nxt);
        else              CP_COMMIT();

        const uint32_t sa = smem_base + (kt % STAGES) * (STAGE_CHUNKS * 16);
#pragma unroll
        for (int kk = 0; kk < 4; kk++) {
            const uint32_t cx = (uint32_t)(((2 * kk + hi) ^ x7) * 16);
            uint32_t a[4][4], bfr[NB][4];
#pragma unroll
            for (int mt = 0; mt < 4; mt++)
                ldsm4(a[mt], sa + aRowOff[mt] + cx);
#pragma unroll
            for (int nb = 0; nb < NB; nb++)
                ldsm4(bfr[nb], sa + bRowOff[nb] + cx);
#pragma unroll
            for (int mt = 0; mt < 4; mt++)
#pragma unroll
                for (int nt = 0; nt < NT; nt++) {
                    uint32_t bb[2];
                    bb[0] = bfr[nt >> 1][(nt & 1)];
                    bb[1] = bfr[nt >> 1][2 + (nt & 1)];
                    mma_f16(acc[mt][nt], a[mt], bb);
                }
        }
    }

    // epilogue
    const int g2 = lane >> 2, q2 = lane & 3;
#pragma unroll
    for (int mt = 0; mt < 4; mt++) {
        const int r0 = rowC + wm * 64 + mt * 16 + g2;
#pragma unroll
        for (int nt = 0; nt < NT; nt++) {
            const int c = colC + wn * WN + nt * 8 + 2 * q2;
            const float b0v = bias[c], b1v = bias[c + 1];
            float o00 = acc[mt][nt][0] + b0v, o01 = acc[mt][nt][1] + b1v;
            float o10 = acc[mt][nt][2] + b0v, o11 = acc[mt][nt][3] + b1v;
            if (RELU) {
                o00 = fmaxf(o00, 0.f); o01 = fmaxf(o01, 0.f);
                o10 = fmaxf(o10, 0.f); o11 = fmaxf(o11, 0.f);
            }
            if (OUTH) {
                __half* Ch = (__half*)Cv;
                *(uint32_t*)(Ch + (size_t)r0 * N + c)       = h2u(__floats2half2_rn(o00, o01));
                *(uint32_t*)(Ch + (size_t)(r0 + 8) * N + c) = h2u(__floats2half2_rn(o10, o11));
            } else {
                float* Cf = (float*)Cv;
                *(float2*)(Cf + (size_t)r0 * N + c)       = make_float2(o00, o01);
                *(float2*)(Cf + (size_t)(r0 + 8) * N + c) = make_float2(o10, o11);
            }
        }
    }
}

// ---------------- FP16 mma flash attention (register-P, f16x2 ex2 softmax, 2 CTAs/SM) ----------------
#define AT_BQ 128
#define AT_BK 64
#define ATQ_BYTES (AT_BQ * 64 * 2)          // 16384
#define ATKV_STAGE (AT_BK * 64 * 2 * 2)     // 16384 (K+V)
#define ATT_SMEM (ATQ_BYTES + 2 * ATKV_STAGE)

__global__ __launch_bounds__(256, 2) void attn_f16_kernel(
    const __half* __restrict__ qkv, __half* __restrict__ out)
{
    extern __shared__ uint4 smemA[];
    const uint32_t sb = (uint32_t)__cvta_generic_to_shared(smemA);

    const int t    = threadIdx.x;
    const int w    = t >> 5;
    const int lane = t & 31;
    const int g    = lane >> 2;
    const int q    = lane & 3;
    const int lr   = lane & 15;
    const int hi   = lane >> 4;
    const int x7   = lane & 7;
    const int qb = blockIdx.x, h = blockIdx.y, b = blockIdx.z;

    const __half* qg = qkv + (size_t)(b * S_ + qb * AT_BQ) * NQKV_ + h * DK_;

#pragma unroll
    for (int i = 0; i < 4; i++) {
        int lin = i * 256 + t;
        int row = lin >> 3, c = lin & 7;
        uint32_t dst = sb + (uint32_t)(row * 8 + (c ^ (row & 7))) * 16;
        cp_async16(dst, qg + (size_t)row * NQKV_ + c * 8);
    }
    CP_COMMIT();
    CP_WAIT0();
    __syncthreads();

    // Q fragments (already pre-scaled by 1/8 at the weight level)
    uint32_t qa[4][4];
    {
        const uint32_t qRowOff = (uint32_t)(w * 16 + lr) * 128;
#pragma unroll
        for (int kb2 = 0; kb2 < 4; kb2++)
            ldsm4(qa[kb2], sb + qRowOff + (uint32_t)(((2 * kb2 + hi) ^ x7) * 16));
    }

    float m0 = -3.0e38f, m1 = -3.0e38f, l0 = 0.f, l1 = 0.f;
    float o[8][4];
#pragma unroll
    for (int nt = 0; nt < 8; nt++)
#pragma unroll
        for (int r = 0; r < 4; r++) o[nt][r] = 0.f;

    const __half* kg = qkv + (size_t)b * S_ * NQKV_ + D_ + h * DK_;

    auto loadKV = [&](int stage, int kb) {
        const uint32_t sbase = sb + ATQ_BYTES + stage * ATKV_STAGE;
        const __half* kr = kg + (size_t)(kb * AT_BK) * NQKV_;
#pragma unroll
        for (int i = 0; i < 2; i++) {
            int lin = i * 256 + t;
            int row = lin >> 3, c = lin & 7;
            uint32_t sw = (uint32_t)(row * 8 + (c ^ (row & 7))) * 16;
            const __half* kp = kr + (size_t)row * NQKV_ + c * 8;
            cp_async16(sbase + sw, kp);
            cp_async16(sbase + (AT_BK * 64 * 2) + sw, kp + D_);
        }
        CP_COMMIT();
    };

    const int NTILES = S_ / AT_BK;   // 32
    int buf = 0;
    loadKV(0, 0);

    const float L2E = 1.4426950408889634f;

    for (int kb = 0; kb < NTILES; kb++) {
        const bool more = (kb + 1) < NTILES;
        if (more) loadKV(buf ^ 1, kb + 1);
        if (more) { CP_WAIT1(); } else { CP_WAIT0(); }
        __syncthreads();

        const uint32_t kbase = sb + ATQ_BYTES + buf * ATKV_STAGE;
        const uint32_t vbase = kbase + AT_BK * 64 * 2;

        float s[8][4];
#pragma unroll
        for (int nt = 0; nt < 8; nt++)
#pragma unroll
            for (int r = 0; r < 4; r++) s[nt][r] = 0.f;

#pragma unroll
        for (int nb = 0; nb < 4; nb++) {
            uint32_t kf[4][4];
            const uint32_t kro = (uint32_t)(nb * 16 + lr) * 128;
#pragma unroll
            for (int kb2 = 0; kb2 < 4; kb2++)
                ldsm4(kf[kb2], kbase + kro + (uint32_t)(((2 * kb2 + hi) ^ x7) * 16));
#pragma unroll
            for (int kb2 = 0; kb2 < 4; kb2++) {
                uint32_t b0[2] = { kf[kb2][0], kf[kb2][2] };
                uint32_t b1[2] = { kf[kb2][1], kf[kb2][3] };
                mma_f16(s[2 * nb],     qa[kb2], b0);
                mma_f16(s[2 * nb + 1], qa[kb2], b1);
            }
        }

        // online softmax
        float mx0 = -3.0e38f, mx1 = -3.0e38f;
#pragma unroll
        for (int nt = 0; nt < 8; nt++) {
            mx0 = fmaxf(mx0, fmaxf(s[nt][0], s[nt][1]));
            mx1 = fmaxf(mx1, fmaxf(s[nt][2], s[nt][3]));
        }
        mx0 = fmaxf(mx0, __shfl_xor_sync(0xffffffffu, mx0, 1));
        mx0 = fmaxf(mx0, __shfl_xor_sync(0xffffffffu, mx0, 2));
        mx1 = fmaxf(mx1, __shfl_xor_sync(0xffffffffu, mx1, 1));
        mx1 = fmaxf(mx1, __shfl_xor_sync(0xffffffffu, mx1, 2));

        const float mn0 = fmaxf(m0, mx0), mn1 = fmaxf(m1, mx1);
        const float f0 = __expf(m0 - mn0), f1 = __expf(m1 - mn1);
        m0 = mn0; m1 = mn1;

        // p = exp2((s - mn) * log2e) computed in f16x2 (P lands in fp16 anyway)
        const float a0 = mn0 * L2E, a1 = mn1 * L2E;
        uint32_t pa[4][4];
        float ls0 = 0.f, ls1 = 0.f;
#pragma unroll
        for (int nt = 0; nt < 8; nt++) {
            float t00 = fmaf(s[nt][0], L2E, -a0);
            float t01 = fmaf(s[nt][1], L2E, -a0);
            float t10 = fmaf(s[nt][2], L2E, -a1);
            float t11 = fmaf(s[nt][3], L2E, -a1);
            uint32_t p0 = ex2_f16x2(h2u(__floats2half2_rn(t00, t01)));
            uint32_t p1 = ex2_f16x2(h2u(__floats2half2_rn(t10, t11)));
            if (nt & 1) { pa[nt >> 1][2] = p0; pa[nt >> 1][3] = p1; }
            else        { pa[nt >> 1][0] = p0; pa[nt >> 1][1] = p1; }
            float2 q0 = __half22float2(*reinterpret_cast<__half2*>(&p0));
            float2 q1 = __half22float2(*reinterpret_cast<__half2*>(&p1));
            ls0 += q0.x + q0.y;
            ls1 += q1.x + q1.y;
        }
        ls0 += __shfl_xor_sync(0xffffffffu, ls0, 1);
        ls0 += __shfl_xor_sync(0xffffffffu, ls0, 2);
        ls1 += __shfl_xor_sync(0xffffffffu, ls1, 1);
        ls1 += __shfl_xor_sync(0xffffffffu, ls1, 2);
        l0 = l0 * f0 + ls0;
        l1 = l1 * f1 + ls1;

#pragma unroll
        for (int nt = 0; nt < 8; nt++) {
            o[nt][0] *= f0; o[nt][1] *= f0;
            o[nt][2] *= f1; o[nt][3] *= f1;
        }

        // O += P @ V  (V via ldmatrix.trans)
#pragma unroll
        for (int nb2 = 0; nb2 < 4; nb2++) {
            const uint32_t cxv = (uint32_t)(((2 * nb2 + hi) ^ x7) * 16);
#pragma unroll
            for (int kb2 = 0; kb2 < 4; kb2++) {
                uint32_t vf[4];
                ldsm4t(vf, vbase + (uint32_t)(kb2 * 16 + lr) * 128 + cxv);
                uint32_t b0[2] = { vf[0], vf[1] };
                uint32_t b1[2] = { vf[2], vf[3] };
                mma_f16(o[2 * nb2],     pa[kb2], b0);
                mma_f16(o[2 * nb2 + 1], pa[kb2], b1);
            }
        }

        __syncthreads();
        buf ^= 1;
    }

    const float i0 = 1.0f / l0, i1 = 1.0f / l1;
    __half* op = out + (size_t)(b * S_ + qb * AT_BQ + w * 16) * D_ + h * DK_;
#pragma unroll
    for (int nt = 0; nt < 8; nt++) {
        const int c = nt * 8 + 2 * q;
        *(uint32_t*)(op + (size_t)g * D_ + c) =
            h2u(__floats2half2_rn(o[nt][0] * i0, o[nt][1] * i0));
        *(uint32_t*)(op + (size_t)(g + 8) * D_ + c) =
            h2u(__floats2half2_rn(o[nt][2] * i1, o[nt][3] * i1));
    }
}

// ---------------- fused residual-add + LayerNorm: warp-per-row, float4, shuffle-only ----------------
// A is fp32 (residual), Bv is fp16 (GEMM output).
template<int DUAL>
__global__ __launch_bounds__(256) void add_ln_kernel(
    const float* __restrict__ A, const __half* __restrict__ Bv,
    const float* __restrict__ gamma, const float* __restrict__ beta,
    float* __restrict__ out, __half* __restrict__ outh)
{
    const int w    = threadIdx.x >> 5;
    const int lane = threadIdx.x & 31;
    const int row  = blockIdx.x * 8 + w;

    const float*  pa = A  + (size_t)row * D_;
    const __half* pb = Bv + (size_t)row * D_;

    float4 v[6];
    float s = 0.f;
#pragma unroll
    for (int i = 0; i < 6; i++) {
        const int off = (i * 32 + lane) * 4;
        float4 a4 = *(const float4*)(pa + off);
        uint2 bh = *(const uint2*)(pb + off);
        float2 b0 = __half22float2(*reinterpret_cast<__half2*>(&bh.x));
        float2 b1 = __half22float2(*reinterpret_cast<__half2*>(&bh.y));
        v[i].x = a4.x + b0.x; v[i].y = a4.y + b0.y;
        v[i].z = a4.z + b1.x; v[i].w = a4.w + b1.y;
        s += v[i].x + v[i].y + v[i].z + v[i].w;
    }
#pragma unroll
    for (int mk = 16; mk; mk >>= 1) s += __shfl_xor_sync(0xffffffffu, s, mk);
    const float mean = s * (1.0f / D_);

    float qv = 0.f;
#pragma unroll
    for (int i = 0; i < 6; i++) {
        v[i].x -= mean; v[i].y -= mean; v[i].z -= mean; v[i].w -= mean;
        qv += v[i].x * v[i].x + v[i].y * v[i].y + v[i].z * v[i].z + v[i].w * v[i].w;
    }
#pragma unroll
    for (int mk = 16; mk; mk >>= 1) qv += __shfl_xor_sync(0xffffffffu, qv, mk);
    const float rstd = rsqrtf(qv * (1.0f / D_) + 1e-5f);

    float* po = out + (size_t)row * D_;
    __half* ph = DUAL ? (outh + (size_t)row * D_) : nullptr;
#pragma unroll
    for (int i = 0; i < 6; i++) {
        const int off = (i * 32 + lane) * 4;
        float4 g4 = *(const float4*)(gamma + off);
        float4 e4 = *(const float4*)(beta + off);
        float4 r;
        r.x = v[i].x * rstd * g4.x + e4.x;
        r.y = v[i].y * rstd * g4.y + e4.y;
        r.z = v[i].z * rstd * g4.z + e4.z;
        r.w = v[i].w * rstd * g4.w + e4.w;
        *(float4*)(po + off) = r;
        if (DUAL) {
            uint2 hh;
            hh.x = h2u(__floats2half2_rn(r.x, r.y));
            hh.y = h2u(__floats2half2_rn(r.z, r.w));
            *(uint2*)(ph + off) = hh;
        }
    }
}

// ---------------- launch ----------------
extern "C" void kernel_launch(void* const* d_in, const int* in_sizes, int n_in,
                              void* d_out, int out_size)
{
    const float* src = (const float*)d_in[0];
    const float* Wq  = (const float*)d_in[1];
    const float* bq  = (const float*)d_in[2];
    const float* Wk  = (const float*)d_in[3];
    const float* bk  = (const float*)d_in[4];
    const float* Wv  = (const float*)d_in[5];
    const float* bv  = (const float*)d_in[6];
    const float* Wo  = (const float*)d_in[7];
    const float* bo  = (const float*)d_in[8];
    const float* g1  = (const float*)d_in[9];
    const float* be1 = (const float*)d_in[10];
    const float* W1  = (const float*)d_in[11];
    const float* bf1 = (const float*)d_in[12];
    const float* W2  = (const float*)d_in[13];
    const float* bf2 = (const float*)d_in[14];
    const float* g2  = (const float*)d_in[15];
    const float* be2 = (const float*)d_in[16];
    float* out = (float*)d_out;

    __half *wqkvT, *woT, *w1T, *w2T, *srch, *x1h, *qkvh, *attnh, *ffn1h, *mhah, *ffn2h;
    float *bqkv, *x1;
    cudaGetSymbolAddress((void**)&wqkvT, g_wqkvT);
    cudaGetSymbolAddress((void**)&bqkv,  g_bqkv);
    cudaGetSymbolAddress((void**)&woT,   g_woT);
    cudaGetSymbolAddress((void**)&w1T,   g_w1T);
    cudaGetSymbolAddress((void**)&w2T,   g_w2T);
    cudaGetSymbolAddress((void**)&srch,  g_srch);
    cudaGetSymbolAddress((void**)&x1h,   g_x1h);
    cudaGetSymbolAddress((void**)&qkvh,  g_qkvh);
    cudaGetSymbolAddress((void**)&attnh, g_attnh);
    cudaGetSymbolAddress((void**)&ffn1h, g_ffn1h);
    cudaGetSymbolAddress((void**)&mhah,  g_mhah);
    cudaGetSymbolAddress((void**)&ffn2h, g_ffn2h);
    cudaGetSymbolAddress((void**)&x1,    g_x1);

    const int smem256 = gemm_smem_bytes(256);   // 147456
    const int smem128 = gemm_smem_bytes(128);   // 98304
    cudaFuncSetAttribute(gemm_f16<0,1,256>, cudaFuncAttributeMaxDynamicSharedMemorySize, smem256);
    cudaFuncSetAttribute(gemm_f16<1,1,256>, cudaFuncAttributeMaxDynamicSharedMemorySize, smem256);
    cudaFuncSetAttribute(gemm_f16<0,1,128>, cudaFuncAttributeMaxDynamicSharedMemorySize, smem128);
    cudaFuncSetAttribute(attn_f16_kernel, cudaFuncAttributeMaxDynamicSharedMemorySize, ATT_SMEM);

    // 0) fused operand prep (src cvt + bias pack + all weight transposes; Wq/bq pre-scaled 1/8)
    prep_all<<<PB_TOTAL, 256>>>(src, Wq, Wk, Wv, bq, bk, bv, Wo, W1, W2);

    // 1) QKV projection -> fp16 qkv   (grid 9x64 = 576)
    gemm_f16<0,1,256><<<dim3(NQKV_ / 256, M_ / BMg), 256, smem256>>>(srch, wqkvT, bqkv, qkvh, M_, NQKV_, D_);

    // 2) fused attention -> fp16 attn  (2 CTAs/SM)
    attn_f16_kernel<<<dim3(S_ / AT_BQ, H_, B_), 256, ATT_SMEM>>>(qkvh, attnh);

    // 3) output projection -> fp16 mha  (BN=128: grid 6x64 = 384, 2 CTAs/SM)
    gemm_f16<0,1,128><<<dim3(D_ / 128, M_ / BMg), 256, smem128>>>(attnh, woT, bo, mhah, M_, D_, D_);

    // 4) x1 = LN(src + mha), dual fp32 + fp16
    add_ln_kernel<1><<<M_ / 8, 256>>>(src, mhah, g1, be1, x1, x1h);

    // 5) FFN1 (+ReLU) -> fp16 ffn1  (grid 12x64 = 768)
    gemm_f16<1,1,256><<<dim3(F_ / 256, M_ / BMg), 256, smem256>>>(x1h, w1T, bf1, ffn1h, M_, F_, D_);

    // 6) FFN2 -> fp16 ffn2  (BN=128: grid 6x64 = 384, 2 CTAs/SM)
    gemm_f16<0,1,128><<<dim3(D_ / 128, M_ / BMg), 256, smem128>>>(ffn1h, w2T, bf2, ffn2h, M_, D_, F_);

    // 7) out = LN(x1 + ffn2)
    add_ln_kernel<0><<<M_ / 8, 256>>>(x1, ffn2h, g2, be2, out, nullptr);
}